// round 7
// baseline (speedup 1.0000x reference)
#include <cuda_runtime.h>
#include <math.h>
#include <stdint.h>

// ---------------- problem constants ----------------
constexpr int CB   = 8;      // batch
constexpr int CN   = 1024;   // nodes
constexpr int CM   = 8;      // speakers
constexpr int CDIN = 1024;
constexpr int CHID = 256;
constexpr int CL   = 2;
constexpr int CNC  = 7;
constexpr int CNH  = 4;
constexpr int CDH  = 64;
#define NEGF  (-9e15f)
#define ALPHAF 0.1f

// ---------------- scratch ----------------
__device__ float g_H   [CB*CN*CHID];
__device__ float g_Hn  [CB*CN*CHID];
__device__ float g_P   [CB*CM*CHID];
__device__ float g_Pagg[CB*CM*CHID];
__device__ float g_Pl1 [CB*CN*CHID];
__device__ float g_h   [CB*CN*CHID];
__device__ float g_Agg [CB*CN*CHID];
__device__ float g_Q   [CB*CN*CHID];
__device__ float g_K   [CB*CN*CHID];
__device__ float g_V   [CB*CN*CHID];
__device__ float g_ctx [CB*CN*CHID];
__device__ float g_T   [CB*CN*CHID];
__device__ float g_att [(long)CB*CN*CN];
__device__ float g_e1  [CB*CN];
__device__ float g_e2  [CB*CN];
__device__ float g_rsc [2];

// ---------------- tf32 / async helpers ----------------
__device__ __forceinline__ uint32_t f2tf(float f) {
    uint32_t u;
    asm("cvt.rna.tf32.f32 %0, %1;" : "=r"(u) : "f"(f));
    return u;
}
__device__ __forceinline__ void mma_tf32(float c[4], const uint32_t a[4], const uint32_t b[2]) {
    asm volatile(
        "mma.sync.aligned.m16n8k8.row.col.f32.tf32.tf32.f32 "
        "{%0,%1,%2,%3}, {%4,%5,%6,%7}, {%8,%9}, {%0,%1,%2,%3};\n"
        : "+f"(c[0]), "+f"(c[1]), "+f"(c[2]), "+f"(c[3])
        : "r"(a[0]), "r"(a[1]), "r"(a[2]), "r"(a[3]), "r"(b[0]), "r"(b[1]));
}
__device__ __forceinline__ void cpasync16(uint32_t saddr, const void* gptr) {
    asm volatile("cp.async.cg.shared.global [%0], [%1], 16;\n" :: "r"(saddr), "l"(gptr));
}
__device__ __forceinline__ void cpcommit() { asm volatile("cp.async.commit_group;\n"); }
__device__ __forceinline__ void cpwait0()  { asm volatile("cp.async.wait_group 0;\n"); }
__device__ __forceinline__ void cpwait1()  { asm volatile("cp.async.wait_group 1;\n"); }

// ================= core GEMM tile (128x128, KS=32, 2-stage, 2 CTAs/SM) =================
struct TileCtx {
    float *As, *Bs;
    uint32_t As_b, Bs_b;
    const float *Ag, *Bg;
    int K, N;
    int tid;
};
constexpr int T_strA = 36, T_strB = 132;
constexpr int T_AW = 128 * T_strA, T_BW = 32 * T_strB;
constexpr int SM_TG = (2 * (T_AW + T_BW)) * 4;   // 70656 bytes

__device__ __forceinline__ void tg_load_stage(TileCtx& c, int kt, int s) {
    int k0 = kt * 32;
    #pragma unroll
    for (int i = 0; i < 4; i++) {
        int f = c.tid + i * 256;
        int m = f >> 3, k4 = (f & 7) * 4;
        cpasync16(c.As_b + (uint32_t)(((s * 128 + m) * T_strA + k4) * 4),
                  c.Ag + (long)m * c.K + k0 + k4);
    }
    #pragma unroll
    for (int i = 0; i < 4; i++) {
        int f = c.tid + i * 256;
        int k = f >> 5, n4 = (f & 31) * 4;
        cpasync16(c.Bs_b + (uint32_t)(((s * 32 + k) * T_strB + n4) * 4),
                  c.Bg + (long)(k0 + k) * c.N + n4);
    }
    cpcommit();
}

// act: 0 none, 1 relu, 2 elu, 3 store-tf32-bits
__device__ __forceinline__ void tg_body(
    TileCtx& c, const float* bias, float* C, int M, int N, int K,
    int row0, int col0, float scale, int act)
{
    int tid  = c.tid;
    int warp = tid >> 5, lane = tid & 31;
    int g = lane >> 2, tg = lane & 3;
    int mw = warp >> 2, nw = warp & 3;

    float acc[4][4][4];
    #pragma unroll
    for (int mi = 0; mi < 4; mi++)
        #pragma unroll
        for (int ni = 0; ni < 4; ni++)
            #pragma unroll
            for (int q = 0; q < 4; q++) acc[mi][ni][q] = 0.f;

    int nk = K / 32;
    tg_load_stage(c, 0, 0);

    for (int kt = 0; kt < nk; kt++) {
        cpwait0();
        __syncthreads();          // loads for stage s visible; all warps past previous compute
        int s = kt & 1;
        if (kt + 1 < nk) tg_load_stage(c, kt + 1, s ^ 1);

        // ---- convert stage s fp32 -> tf32 in place (once, shared) ----
        #pragma unroll
        for (int i = 0; i < 4; i++) {
            int f = tid + i * 256;
            int m = f >> 3, k4 = (f & 7) * 4;
            float4* p = (float4*)&c.As[(s * 128 + m) * T_strA + k4];
            float4 v = *p;
            *(uint4*)p = make_uint4(f2tf(v.x), f2tf(v.y), f2tf(v.z), f2tf(v.w));
        }
        #pragma unroll
        for (int i = 0; i < 4; i++) {
            int f = tid + i * 256;
            int k = f >> 5, n4 = (f & 31) * 4;
            float4* p = (float4*)&c.Bs[s * T_BW + k * T_strB + n4];
            float4 v = *p;
            *(uint4*)p = make_uint4(f2tf(v.x), f2tf(v.y), f2tf(v.z), f2tf(v.w));
        }
        __syncthreads();

        const uint32_t* Asb = (const uint32_t*)(c.As + s * T_AW);
        const uint32_t* Bsb = (const uint32_t*)(c.Bs + s * T_BW);
        #pragma unroll
        for (int ks = 0; ks < 32; ks += 8) {
            uint32_t a[4][4], b[4][2];
            #pragma unroll
            for (int mi = 0; mi < 4; mi++) {
                int mr = mw * 64 + mi * 16;
                a[mi][0] = Asb[(mr + g)     * T_strA + ks + tg];
                a[mi][1] = Asb[(mr + g + 8) * T_strA + ks + tg];
                a[mi][2] = Asb[(mr + g)     * T_strA + ks + tg + 4];
                a[mi][3] = Asb[(mr + g + 8) * T_strA + ks + tg + 4];
            }
            #pragma unroll
            for (int ni = 0; ni < 4; ni++) {
                int nc = nw * 32 + ni * 8;
                b[ni][0] = Bsb[(ks + tg)     * T_strB + nc + g];
                b[ni][1] = Bsb[(ks + tg + 4) * T_strB + nc + g];
            }
            #pragma unroll
            for (int mi = 0; mi < 4; mi++)
                #pragma unroll
                for (int ni = 0; ni < 4; ni++)
                    mma_tf32(acc[mi][ni], a[mi], b[ni]);
        }
        // no bottom sync: next iter's top sync protects the buffers
    }

    #pragma unroll
    for (int mi = 0; mi < 4; mi++) {
        #pragma unroll
        for (int ni = 0; ni < 4; ni++) {
            int r = row0 + mw * 64 + mi * 16 + g;
            int cc0 = col0 + nw * 32 + ni * 8 + tg * 2;
            float b0 = bias ? bias[cc0] : 0.f;
            float b1 = bias ? bias[cc0 + 1] : 0.f;
            #pragma unroll
            for (int rr = 0; rr < 2; rr++) {
                float v0 = acc[mi][ni][rr * 2 + 0] * scale + b0;
                float v1 = acc[mi][ni][rr * 2 + 1] * scale + b1;
                if (act == 1) { v0 = fmaxf(v0, 0.f); v1 = fmaxf(v1, 0.f); }
                else if (act == 2) {
                    v0 = v0 > 0.f ? v0 : expm1f(v0);
                    v1 = v1 > 0.f ? v1 : expm1f(v1);
                } else if (act == 3) {
                    v0 = __uint_as_float(f2tf(v0));
                    v1 = __uint_as_float(f2tf(v1));
                }
                *(float2*)(C + (long)(r + rr * 8) * N + cc0) = make_float2(v0, v1);
            }
        }
    }
}

// ---------------- single GEMM (batched via strides) ----------------
template<int ACT>
__global__ void __launch_bounds__(256, 2) tgemm(
    const float* __restrict__ A, const float* __restrict__ Bm,
    const float* __restrict__ bias, float* __restrict__ C,
    int M, int N, int K, long sA, long sB, long sC, float scale)
{
    extern __shared__ float smem[];
    int bz = blockIdx.z;
    TileCtx c;
    c.As = smem; c.Bs = smem + 2 * T_AW;
    c.As_b = (uint32_t)__cvta_generic_to_shared(c.As);
    c.Bs_b = (uint32_t)__cvta_generic_to_shared(c.Bs);
    c.K = K; c.N = N; c.tid = threadIdx.x;
    int row0 = blockIdx.y * 128, col0 = blockIdx.x * 128;
    const float* Ab = A + (long)bz * sA;
    const float* Bb = Bm + (long)bz * sB;
    c.Ag = Ab + (long)row0 * K;
    c.Bg = Bb + col0;
    tg_body(c, bias, C + (long)bz * sC, M, N, K, row0, col0, scale, ACT);
}

// ---------------- paired GEMM: z selects {A,B,bias,C,act} ----------------
struct G2 { const float* A[2]; const float* B[2]; const float* bias[2]; float* C[2]; int act[2]; };
__global__ void __launch_bounds__(256, 2) tgemm_pair(G2 args, int M, int N, int K)
{
    extern __shared__ float smem[];
    int z = blockIdx.z;
    TileCtx c;
    c.As = smem; c.Bs = smem + 2 * T_AW;
    c.As_b = (uint32_t)__cvta_generic_to_shared(c.As);
    c.Bs_b = (uint32_t)__cvta_generic_to_shared(c.Bs);
    c.K = K; c.N = N; c.tid = threadIdx.x;
    int row0 = blockIdx.y * 128, col0 = blockIdx.x * 128;
    c.Ag = args.A[z] + (long)row0 * K;
    c.Bg = args.B[z] + col0;
    tg_body(c, args.bias[z], args.C[z], M, N, K, row0, col0, 1.f, args.act[z]);
}

// ---------------- fused flash attention, 64-row KV tiles ----------------
// Q, K, V already hold tf32-rounded bit patterns (stored as float).
__global__ void __launch_bounds__(256, 2) flash_kernel(
    const float* __restrict__ Q, const float* __restrict__ Kg_,
    const float* __restrict__ Vg_, float* __restrict__ O)
{
    constexpr int SK = 68, SV = 72, KT = 64;
    extern __shared__ float sm[];
    float* Qs = sm;                          // 128*68
    float* Ks = sm + 128 * SK;               // 2 * 64*68
    float* Vs = Ks + 2 * KT * SK;            // 2 * 64*72
    uint32_t Qs_b = (uint32_t)__cvta_generic_to_shared(Qs);
    uint32_t Ks_b = (uint32_t)__cvta_generic_to_shared(Ks);
    uint32_t Vs_b = (uint32_t)__cvta_generic_to_shared(Vs);
    const uint32_t* Ku = (const uint32_t*)Ks;
    const uint32_t* Vu = (const uint32_t*)Vs;

    long base = (long)blockIdx.y * CN * CDH;
    const float* Qg = Q + base + (long)blockIdx.x * 128 * CDH;
    const float* Kg = Kg_ + base;
    const float* Vg = Vg_ + base;
    float* Og = O + base + (long)blockIdx.x * 128 * CDH;

    int tid = threadIdx.x, warp = tid >> 5, lane = tid & 31;
    int g = lane >> 2, tg = lane & 3;
    int r0 = warp * 16;

    #pragma unroll
    for (int i = 0; i < 8; i++) {
        int f = tid + i * 256;
        int r = f >> 4, c4 = (f & 15) * 4;
        cpasync16(Qs_b + (uint32_t)((r * SK + c4) * 4), Qg + r * CDH + c4);
    }
    cpcommit();

    auto load_kv = [&](int t, int s) {
        const float* Kt = Kg + t * KT * CDH;
        const float* Vt = Vg + t * KT * CDH;
        #pragma unroll
        for (int i = 0; i < 4; i++) {
            int f = tid + i * 256;
            int r = f >> 4, c4 = (f & 15) * 4;
            cpasync16(Ks_b + (uint32_t)(((s * KT + r) * SK + c4) * 4), Kt + r * CDH + c4);
            cpasync16(Vs_b + (uint32_t)(((s * KT + r) * SV + c4) * 4), Vt + r * CDH + c4);
        }
        cpcommit();
    };
    load_kv(0, 0);

    cpwait1();            // Q done
    __syncthreads();

    // Q fragments (already tf32 bits)
    uint32_t aq[8][4];
    #pragma unroll
    for (int kf = 0; kf < 8; kf++) {
        aq[kf][0] = __float_as_uint(Qs[(r0 + g)     * SK + kf * 8 + tg]);
        aq[kf][1] = __float_as_uint(Qs[(r0 + g + 8) * SK + kf * 8 + tg]);
        aq[kf][2] = __float_as_uint(Qs[(r0 + g)     * SK + kf * 8 + tg + 4]);
        aq[kf][3] = __float_as_uint(Qs[(r0 + g + 8) * SK + kf * 8 + tg + 4]);
    }

    float m0 = -3.4e38f, m1 = -3.4e38f, l0 = 0.f, l1 = 0.f;
    float o[8][4];
    #pragma unroll
    for (int nf = 0; nf < 8; nf++)
        #pragma unroll
        for (int q = 0; q < 4; q++) o[nf][q] = 0.f;

    for (int t = 0; t < 16; t++) {
        int s = t & 1;
        if (t < 15) load_kv(t + 1, s ^ 1);
        if (t < 15) cpwait1(); else cpwait0();
        __syncthreads();

        // S = Q @ K^T  (per-warp [16,64])
        float sc[8][4];
        #pragma unroll
        for (int nf = 0; nf < 8; nf++)
            #pragma unroll
            for (int q = 0; q < 4; q++) sc[nf][q] = 0.f;
        #pragma unroll
        for (int kf = 0; kf < 8; kf++) {
            #pragma unroll
            for (int nf = 0; nf < 8; nf++) {
                uint32_t b[2];
                b[0] = Ku[(s * KT + nf * 8 + g) * SK + kf * 8 + tg];
                b[1] = Ku[(s * KT + nf * 8 + g) * SK + kf * 8 + tg + 4];
                mma_tf32(sc[nf], aq[kf], b);
            }
        }

        // online softmax (scale 1/8)
        float mx0 = -3.4e38f, mx1 = -3.4e38f;
        #pragma unroll
        for (int nf = 0; nf < 8; nf++) {
            mx0 = fmaxf(mx0, fmaxf(sc[nf][0], sc[nf][1]));
            mx1 = fmaxf(mx1, fmaxf(sc[nf][2], sc[nf][3]));
        }
        #pragma unroll
        for (int off = 1; off <= 2; off <<= 1) {
            mx0 = fmaxf(mx0, __shfl_xor_sync(0xffffffffu, mx0, off));
            mx1 = fmaxf(mx1, __shfl_xor_sync(0xffffffffu, mx1, off));
        }
        float mn0 = fmaxf(m0, mx0 * 0.125f);
        float mn1 = fmaxf(m1, mx1 * 0.125f);
        float cr0 = __expf(m0 - mn0);
        float cr1 = __expf(m1 - mn1);
        l0 *= cr0; l1 *= cr1;
        #pragma unroll
        for (int nf = 0; nf < 8; nf++) {
            o[nf][0] *= cr0; o[nf][1] *= cr0;
            o[nf][2] *= cr1; o[nf][3] *= cr1;
        }
        float rs0 = 0.f, rs1 = 0.f;
        #pragma unroll
        for (int nf = 0; nf < 8; nf++) {
            float p0 = __expf(sc[nf][0] * 0.125f - mn0);
            float p1 = __expf(sc[nf][1] * 0.125f - mn0);
            float p2 = __expf(sc[nf][2] * 0.125f - mn1);
            float p3 = __expf(sc[nf][3] * 0.125f - mn1);
            rs0 += p0 + p1;  rs1 += p2 + p3;
            sc[nf][0] = __uint_as_float(f2tf(p0));
            sc[nf][1] = __uint_as_float(f2tf(p1));
            sc[nf][2] = __uint_as_float(f2tf(p2));
            sc[nf][3] = __uint_as_float(f2tf(p3));
        }
        #pragma unroll
        for (int off = 1; off <= 2; off <<= 1) {
            rs0 += __shfl_xor_sync(0xffffffffu, rs0, off);
            rs1 += __shfl_xor_sync(0xffffffffu, rs1, off);
        }
        l0 += rs0; l1 += rs1; m0 = mn0; m1 = mn1;

        // O += P @ V : gather A-frags of P via intra-quad shuffles
        int srcA = (g << 2) + (tg >> 1);
        int srcB = srcA + 2;
        bool odd = tg & 1;
        #pragma unroll
        for (int kf = 0; kf < 8; kf++) {
            float u0 = __shfl_sync(0xffffffffu, sc[kf][0], srcA);
            float u1 = __shfl_sync(0xffffffffu, sc[kf][1], srcA);
            float u2 = __shfl_sync(0xffffffffu, sc[kf][2], srcA);
            float u3 = __shfl_sync(0xffffffffu, sc[kf][3], srcA);
            float w0 = __shfl_sync(0xffffffffu, sc[kf][0], srcB);
            float w1 = __shfl_sync(0xffffffffu, sc[kf][1], srcB);
            float w2 = __shfl_sync(0xffffffffu, sc[kf][2], srcB);
            float w3 = __shfl_sync(0xffffffffu, sc[kf][3], srcB);
            uint32_t a[4];
            a[0] = __float_as_uint(odd ? u1 : u0);
            a[1] = __float_as_uint(odd ? u3 : u2);
            a[2] = __float_as_uint(odd ? w1 : w0);
            a[3] = __float_as_uint(odd ? w3 : w2);
            #pragma unroll
            for (int nf = 0; nf < 8; nf++) {
                uint32_t b[2];
                b[0] = Vu[(s * KT + kf * 8 + tg)     * SV + nf * 8 + g];
                b[1] = Vu[(s * KT + kf * 8 + tg + 4) * SV + nf * 8 + g];
                mma_tf32(o[nf], a, b);
            }
        }
        __syncthreads();   // protect stage s before next iter's prefetch overwrites it
    }

    float inv0 = 1.f / l0, inv1 = 1.f / l1;
    #pragma unroll
    for (int nf = 0; nf < 8; nf++) {
        int c = nf * 8 + tg * 2;
        *(float2*)(Og + (long)(r0 + g)     * CDH + c) = make_float2(o[nf][0] * inv0, o[nf][1] * inv0);
        *(float2*)(Og + (long)(r0 + g + 8) * CDH + c) = make_float2(o[nf][2] * inv1, o[nf][3] * inv1);
    }
}
constexpr int SM_FLASH = (128 * 68 + 2 * 64 * 68 + 2 * 64 * 72) * 4;  // 106496

// ---------------- fp32 tiled SGEMM (fc2 only) ----------------
template<int ACT>
__global__ void sgemm(const float* __restrict__ A, const float* __restrict__ Bm,
                      const float* __restrict__ bias, float* __restrict__ C,
                      int M, int N, int K)
{
    __shared__ float As[16][68];
    __shared__ float Bs[16][68];
    int tx = threadIdx.x;
    int tr = tx >> 4, tc = tx & 15;
    int row0 = blockIdx.y * 64, col0 = blockIdx.x * 64;

    float acc[4][4] = {};
    for (int k0 = 0; k0 < K; k0 += 16) {
        #pragma unroll
        for (int i = 0; i < 4; i++) {
            int idx = tx * 4 + i;
            int m = idx >> 4, k = idx & 15;
            int gr = row0 + m;
            As[k][m] = (gr < M) ? A[(long)gr * K + k0 + k] : 0.f;
        }
        #pragma unroll
        for (int i = 0; i < 4; i++) {
            int idx = tx * 4 + i;
            int k = idx >> 6, n = idx & 63;
            int gn = col0 + n;
            Bs[k][n] = (gn < N) ? Bm[(long)(k0 + k) * N + gn] : 0.f;
        }
        __syncthreads();
        #pragma unroll
        for (int k = 0; k < 16; k++) {
            float a[4], b[4];
            #pragma unroll
            for (int i = 0; i < 4; i++) a[i] = As[k][tr * 4 + i];
            #pragma unroll
            for (int j = 0; j < 4; j++) b[j] = Bs[k][tc * 4 + j];
            #pragma unroll
            for (int i = 0; i < 4; i++)
                #pragma unroll
                for (int j = 0; j < 4; j++)
                    acc[i][j] = fmaf(a[i], b[j], acc[i][j]);
        }
        __syncthreads();
    }
    #pragma unroll
    for (int i = 0; i < 4; i++) {
        int gr = row0 + tr * 4 + i;
        if (gr >= M) continue;
        #pragma unroll
        for (int j = 0; j < 4; j++) {
            int gn = col0 + tc * 4 + j;
            if (gn >= N) continue;
            float v = acc[i][j];
            if (bias) v += bias[gn];
            if (ACT == 1) v = v > 0.f ? v : 0.f;
            C[(long)gr * N + gn] = v;
        }
    }
}

// ---------------- logits: warp per row, N=7 ----------------
__global__ void logits_kernel(const float* __restrict__ H, const float* __restrict__ W,
                              const float* __restrict__ bb, float* __restrict__ out)
{
    int warp = threadIdx.x >> 5, lane = threadIdx.x & 31;
    int row = blockIdx.x * 8 + warp;
    float hv[8];
    #pragma unroll
    for (int j = 0; j < 8; j++) hv[j] = H[(long)row * CHID + j * 32 + lane];
    float acc[CNC];
    #pragma unroll
    for (int c = 0; c < CNC; c++) {
        float a = 0.f;
        #pragma unroll
        for (int j = 0; j < 8; j++) a = fmaf(hv[j], W[(j * 32 + lane) * CNC + c], a);
        acc[c] = a;
    }
    #pragma unroll
    for (int c = 0; c < CNC; c++)
        #pragma unroll
        for (int off = 16; off > 0; off >>= 1)
            acc[c] += __shfl_xor_sync(0xffffffffu, acc[c], off);
    if (lane < CNC) out[(long)row * CNC + lane] = acc[lane] + bb[lane];
}

// ---------------- P_l_1 ----------------
__global__ void pl1_kernel(const float* __restrict__ sadj, const float* __restrict__ P,
                           float* __restrict__ out)
{
    long idx = (long)blockIdx.x * 256 + threadIdx.x;
    int d = idx & (CHID - 1);
    int n = (idx >> 8) & (CN - 1);
    int b = (int)(idx >> 18);
    const float* sa = sadj + (long)b * CM * CN + n;
    const float* Pb = P + (long)b * CM * CHID + d;
    float acc = 0.f;
    #pragma unroll
    for (int m = 0; m < CM; m++) acc = fmaf(sa[m * CN], Pb[m * CHID], acc);
    out[idx] = acc;
}

// ---------------- P_agg ----------------
__global__ void pagg_kernel(const float* __restrict__ sadj, const float* __restrict__ H,
                            float* __restrict__ out)
{
    int bm = blockIdx.x;
    int b = bm >> 3;
    int d = threadIdx.x;
    const float* sa = sadj + (long)bm * CN;
    const float* Hb = H + (long)b * CN * CHID + d;
    float acc = 0.f;
    #pragma unroll 4
    for (int n = 0; n < CN; n++) acc = fmaf(sa[n], Hb[(long)n * CHID], acc);
    out[(long)bm * CHID + d] = acc;
}

// ---------------- e1/e2 dots: warp per row ----------------
__global__ void dots_kernel(const float* __restrict__ h, const float* __restrict__ a1,
                            const float* __restrict__ a2,
                            float* __restrict__ e1, float* __restrict__ e2)
{
    int warp = threadIdx.x >> 5, lane = threadIdx.x & 31;
    int row = blockIdx.x * 8 + warp;
    float s1 = 0.f, s2 = 0.f;
    #pragma unroll
    for (int j = 0; j < 8; j++) {
        int c = j * 32 + lane;
        float v = h[(long)row * CHID + c];
        s1 = fmaf(v, a1[c], s1);
        s2 = fmaf(v, a2[c], s2);
    }
    #pragma unroll
    for (int off = 16; off > 0; off >>= 1) {
        s1 += __shfl_xor_sync(0xffffffffu, s1, off);
        s2 += __shfl_xor_sync(0xffffffffu, s2, off);
    }
    if (lane == 0) { e1[row] = s1; e2[row] = s2; }
}

// ---------------- rel_sc ----------------
__global__ void relsc_kernel(const float* __restrict__ rel, const float* __restrict__ a3,
                             float* __restrict__ out)
{
    __shared__ float s[256];
    int r = blockIdx.x, t = threadIdx.x;
    s[t] = rel[r * CHID + t] * a3[t];
    __syncthreads();
    for (int o = 128; o > 0; o >>= 1) {
        if (t < o) s[t] += s[t + o];
        __syncthreads();
    }
    if (t == 0) out[r] = s[0];
}

// ---------------- GAT edge scores + masked softmax (vectorized) ----------------
__global__ void gat_att_kernel(const float* __restrict__ e1, const float* __restrict__ e2,
                               const float* __restrict__ rsc,
                               const int* __restrict__ adj, const int* __restrict__ smask,
                               float* __restrict__ att)
{
    __shared__ float red[256];
    int bi = blockIdx.x;
    int b = bi >> 10;
    long base = (long)bi * CN;
    int t = threadIdx.x;
    float E1 = e1[bi];
    float r0 = rsc[0], r1 = rsc[1];

    int4   ad = ((const int4*)(adj + base))[t];
    int4   sk = ((const int4*)(smask + base))[t];
    float4 ev = ((const float4*)(e2 + (long)b * CN))[t];

    float vals[4];
    {
        float e;
        e = E1 + ev.x + (sk.x ? r1 : r0); e = e >= 0.f ? e : ALPHAF * e; vals[0] = ad.x ? e : NEGF;
        e = E1 + ev.y + (sk.y ? r1 : r0); e = e >= 0.f ? e : ALPHAF * e; vals[1] = ad.y ? e : NEGF;
        e = E1 + ev.z + (sk.z ? r1 : r0); e = e >= 0.f ? e : ALPHAF * e; vals[2] = ad.z ? e : NEGF;
        e = E1 + ev.w + (sk.w ? r1 : r0); e = e >= 0.f ? e : ALPHAF * e; vals[3] = ad.w ? e : NEGF;
    }
    float mx = fmaxf(fmaxf(vals[0], vals[1]), fmaxf(vals[2], vals[3]));
    red[t] = mx; __syncthreads();
    for (int o = 128; o > 0; o >>= 1) {
        if (t < o) red[t] = fmaxf(red[t], red[t + o]);
        __syncthreads();
    }
    mx = red[0]; __syncthreads();
    float s = 0.f;
    #pragma unroll
    for (int q = 0; q < 4; q++) { vals[q] = __expf(vals[q] - mx); s += vals[q]; }
    red[t] = s; __syncthreads();
    for (int o = 128; o > 0; o >>= 1) {
        if (t < o) red[t] += red[t + o];
        __syncthreads();
    }
    float inv = 1.f / red[0];
    ((float4*)(att + base))[t] =
        make_float4(vals[0] * inv, vals[1] * inv, vals[2] * inv, vals[3] * inv);
}

// ---------------- LayerNorm: warp per row ----------------
__global__ void ln_kernel(const float* __restrict__ T, const float* __restrict__ Hold,
                          const float* __restrict__ g, const float* __restrict__ bb,
                          float* __restrict__ out)
{
    int warp = threadIdx.x >> 5, lane = threadIdx.x & 31;
    int row = blockIdx.x * 8 + warp;
    long base = (long)row * CHID;
    float v[8];
    float s = 0.f;
    #pragma unroll
    for (int j = 0; j < 8; j++) {
        int c = j * 32 + lane;
        v[j] = T[base + c] + Hold[base + c];
        s += v[j];
    }
    #pragma unroll
    for (int off = 16; off > 0; off >>= 1) s += __shfl_xor_sync(0xffffffffu, s, off);
    float mu = s * (1.f / CHID);
    float q = 0.f;
    #pragma unroll
    for (int j = 0; j < 8; j++) { v[j] -= mu; q = fmaf(v[j], v[j], q); }
    #pragma unroll
    for (int off = 16; off > 0; off >>= 1) q += __shfl_xor_sync(0xffffffffu, q, off);
    float rstd = rsqrtf(q * (1.f / CHID) + 1e-5f);
    #pragma unroll
    for (int j = 0; j < 8; j++) {
        int c = j * 32 + lane;
        out[base + c] = v[j] * rstd * g[c] + bb[c];
    }
}

// ---------------- GRU3d ----------------
__global__ void gru_kernel(float* __restrict__ P, const float* __restrict__ Pagg,
                           const float* __restrict__ wz, const float* __restrict__ uz,
                           const float* __restrict__ wr, const float* __restrict__ ur,
                           const float* __restrict__ w,  const float* __restrict__ u)
{
    __shared__ float sp[CHID], sq[CHID];
    int r = blockIdx.x;
    int c = threadIdx.x;
    sp[c] = P[(long)r * CHID + c];
    sq[c] = Pagg[(long)r * CHID + c];
    __syncthreads();
    float az = 0, bz = 0, ar = 0, br = 0, aw = 0, bw = 0;
    #pragma unroll 4
    for (int k = 0; k < CHID; k++) {
        float pk = sp[k], qk = sq[k];
        az = fmaf(pk, wz[k * CHID + c], az); bz = fmaf(qk, uz[k * CHID + c], bz);
        ar = fmaf(pk, wr[k * CHID + c], ar); br = fmaf(qk, ur[k * CHID + c], br);
        aw = fmaf(pk, w [k * CHID + c], aw); bw = fmaf(qk, u [k * CHID + c], bw);
    }
    float z  = 1.f / (1.f + expf(-(az + bz)));
    float rr = 1.f / (1.f + expf(-(ar + br)));
    float hh = tanhf(aw + rr * bw);
    P[(long)r * CHID + c] = (1.f - z) * sp[c] + z * hh;
}

// ---------------- p_sim ----------------
__global__ void psim_kernel(const float* __restrict__ P, float* __restrict__ outp, int tail)
{
    __shared__ float red[64];
    int t = threadIdx.x;
    int b = t >> 3, m = t & 7;
    const float* Pb = P + (long)b * CM * CHID;
    float s = 0.f;
    for (int k2 = 0; k2 < CM; k2++) {
        if (k2 == m) continue;
        float d = 0.f;
        for (int dd = 0; dd < CHID; dd++)
            d = fmaf(Pb[m * CHID + dd], Pb[k2 * CHID + dd], d);
        s += d;
    }
    red[t] = s; __syncthreads();
    if ((t & 7) < 4) red[t] += red[t + 4]; __syncthreads();
    if ((t & 7) < 2) red[t] += red[t + 2]; __syncthreads();
    if ((t & 7) < 1) red[t] += red[t + 1]; __syncthreads();
    if (tail >= CB) {
        if (t < CB) outp[t] = red[t * 8] / (float)(CM * CM);
    } else {
        if (t == 0) {
            float tot = 0.f;
            for (int b2 = 0; b2 < CB; b2++) tot += red[b2 * 8];
            outp[0] = tot / (float)(CB * CM * CM);
        }
    }
}

// ---------------- host orchestration ----------------
extern "C" void kernel_launch(void* const* d_in, const int* in_sizes, int n_in,
                              void* d_out, int out_size)
{
    const float* x     = (const float*)d_in[0];
    const int*   adj   = (const int*)  d_in[1];
    const int*   smask = (const int*)  d_in[2];
    const float* sf    = (const float*)d_in[3];
    const float* sadj  = (const float*)d_in[4];
    const float* fc1w  = (const float*)d_in[6];
    const float* fc1b  = (const float*)d_in[7];
    const float* fc2w  = (const float*)d_in[8];
    const float* fc2b  = (const float*)d_in[9];
    const float* gatW  = (const float*)d_in[10];
    const float* gata  = (const float*)d_in[11];
    const float* rel   = (const float*)d_in[12];
    const float* gwz   = (const float*)d_in[13];
    const float* guz   = (const float*)d_in[14];
    const float* gwr   = (const float*)d_in[15];
    const float* gur   = (const float*)d_in[16];
    const float* gw    = (const float*)d_in[17];
    const float* gu    = (const float*)d_in[18];
    const float* wv    = (const float*)d_in[19];
    const float* bv    = (const float*)d_in[20];
    const float* wk    = (const float*)d_in[21];
    const float* bk    = (const float*)d_in[22];
    const float* wq    = (const float*)d_in[23];
    const float* bq    = (const float*)d_in[24];
    const float* wo    = (const float*)d_in[25];
    const float* bo    = (const float*)d_in[26];
    const float* lng   = (const float*)d_in[27];
    const float* lnb   = (const float*)d_in[28];
    const float* outw  = (const float*)d_in[29];
    const float* outb  = (const float*)d_in[30];
    float* out = (float*)d_out;

    float *H, *Hn, *P, *Pagg, *Pl1, *hb, *Agg, *Qb, *Kb, *Vb, *ctx, *Tb, *att, *e1, *e2, *rsc;
    cudaGetSymbolAddress((void**)&H,    g_H);
    cudaGetSymbolAddress((void**)&Hn,   g_Hn);
    cudaGetSymbolAddress((void**)&P,    g_P);
    cudaGetSymbolAddress((void**)&Pagg, g_Pagg);
    cudaGetSymbolAddress((void**)&Pl1,  g_Pl1);
    cudaGetSymbolAddress((void**)&hb,   g_h);
    cudaGetSymbolAddress((void**)&Agg,  g_Agg);
    cudaGetSymbolAddress((void**)&Qb,   g_Q);
    cudaGetSymbolAddress((void**)&Kb,   g_K);
    cudaGetSymbolAddress((void**)&Vb,   g_V);
    cudaGetSymbolAddress((void**)&ctx,  g_ctx);
    cudaGetSymbolAddress((void**)&Tb,   g_T);
    cudaGetSymbolAddress((void**)&att,  g_att);
    cudaGetSymbolAddress((void**)&e1,   g_e1);
    cudaGetSymbolAddress((void**)&e2,   g_e2);
    cudaGetSymbolAddress((void**)&rsc,  g_rsc);

    cudaFuncSetAttribute(tgemm<0>, cudaFuncAttributeMaxDynamicSharedMemorySize, SM_TG);
    cudaFuncSetAttribute(tgemm<1>, cudaFuncAttributeMaxDynamicSharedMemorySize, SM_TG);
    cudaFuncSetAttribute(tgemm<2>, cudaFuncAttributeMaxDynamicSharedMemorySize, SM_TG);
    cudaFuncSetAttribute(tgemm_pair, cudaFuncAttributeMaxDynamicSharedMemorySize, SM_TG);
    cudaFuncSetAttribute(flash_kernel, cudaFuncAttributeMaxDynamicSharedMemorySize, SM_FLASH);

    dim3 blk(256);
    const int BN = CB * CN;                          // 8192
    const long HH = (long)CHID * CHID;               // 65536

    // H = relu(x @ fc1_w + b)
    tgemm<1><<<dim3(2, 64, 1), blk, SM_TG>>>(x, fc1w, fc1b, H, BN, CHID, CDIN, 0, 0, 0, 1.f);
    // P = relu(s_feature @ fc2_w + b)
    sgemm<1><<<dim3(4, 1, 1), blk>>>(sf, fc2w, fc2b, P, CB * CM, CHID, CDIN);

    for (int l = 0; l < CL; l++) {
        float* cur = l ? Hn : H;
        float* nxt = l ? H : Hn;

        // P_l_1 = s_adj^T @ P
        pl1_kernel<<<BN * CHID / 256, blk>>>(sadj, P, Pl1);

        // paired: h = cur @ gat_W[l] (fp32) ; V = cur @ wv + bv (tf32 bits)
        {
            G2 a;
            a.A[0] = cur;           a.A[1] = cur;
            a.B[0] = gatW + l * HH; a.B[1] = wv + l * HH;
            a.bias[0] = nullptr;    a.bias[1] = bv + l * CHID;
            a.C[0] = hb;            a.C[1] = Vb;
            a.act[0] = 0;           a.act[1] = 3;
            tgemm_pair<<<dim3(2, 64, 2), blk, SM_TG>>>(a, BN, CHID, CHID);
        }
        // edge-score ingredients
        dots_kernel<<<BN / 8, blk>>>(hb, gata + l * 3 * CHID, gata + l * 3 * CHID + CHID, e1, e2);
        relsc_kernel<<<2, blk>>>(rel + l * 2 * CHID, gata + l * 3 * CHID + 2 * CHID, rsc);
        gat_att_kernel<<<BN, blk>>>(e1, e2, rsc, adj, smask, att);
        // Agg = elu(att @ h)
        tgemm<2><<<dim3(2, 8, CB), blk, SM_TG>>>(att, hb, nullptr, Agg,
                                                 CN, CHID, CN,
                                                 (long)CN * CN, (long)CN * CHID, (long)CN * CHID, 1.f);
        // paired: K = Pl1 @ wk + bk ; Q = Agg @ wq + bq   (both tf32 bits)
        {
            G2 a;
            a.A[0] = Pl1;           a.A[1] = Agg;
            a.B[0] = wk + l * HH;   a.B[1] = wq + l * HH;
            a.bias[0] = bk + l * CHID; a.bias[1] = bq + l * CHID;
            a.C[0] = Kb;            a.C[1] = Qb;
            a.act[0] = 3;           a.act[1] = 3;
            tgemm_pair<<<dim3(2, 64, 2), blk, SM_TG>>>(a, BN, CHID, CHID);
        }
        // fused MHA
        flash_kernel<<<dim3(8, 32), blk, SM_FLASH>>>(Qb, Kb, Vb, ctx);
        // T = ctx @ wo + bo ;  H_new = LN(T + H)
        tgemm<0><<<dim3(2, 64, 1), blk, SM_TG>>>(ctx, wo + l * HH, bo + l * CHID, Tb,
                                                 BN, CHID, CHID, 0, 0, 0, 1.f);
        ln_kernel<<<BN / 8, blk>>>(Tb, cur, lng + l * CHID, lnb + l * CHID, nxt);

        // GRU speaker update (uses pre-update H)
        pagg_kernel<<<CB * CM, blk>>>(sadj, cur, Pagg);
        gru_kernel<<<CB * CM, blk>>>(P, Pagg,
                                     gwz + l * HH, guz + l * HH,
                                     gwr + l * HH, gur + l * HH,
                                     gw + l * HH,  gu + l * HH);
    }

    // logits
    logits_kernel<<<BN / 8, blk>>>(H, outw, outb, out);
    // p_sim
    psim_kernel<<<1, 64>>>(P, out + (long)BN * CNC, out_size - BN * CNC);
}

// round 8
// speedup vs baseline: 1.0426x; 1.0426x over previous
#include <cuda_runtime.h>
#include <math.h>
#include <stdint.h>

// ---------------- problem constants ----------------
constexpr int CB   = 8;      // batch
constexpr int CN   = 1024;   // nodes
constexpr int CM   = 8;      // speakers
constexpr int CDIN = 1024;
constexpr int CHID = 256;
constexpr int CL   = 2;
constexpr int CNC  = 7;
constexpr int CNH  = 4;
constexpr int CDH  = 64;
#define NEGF  (-9e15f)
#define ALPHAF 0.1f

// ---------------- scratch ----------------
__device__ float g_H   [CB*CN*CHID];
__device__ float g_Hn  [CB*CN*CHID];
__device__ float g_P   [CB*CM*CHID];
__device__ float g_Pagg[CB*CM*CHID];
__device__ float g_Pl1 [CB*CN*CHID];
__device__ float g_h   [CB*CN*CHID];
__device__ float g_Agg [CB*CN*CHID];
__device__ float g_Q   [CB*CN*CHID];
__device__ float g_K   [CB*CN*CHID];
__device__ float g_V   [CB*CN*CHID];
__device__ float g_ctx [CB*CN*CHID];
__device__ float g_T   [CB*CN*CHID];
__device__ float g_att [(long)CB*CN*CN];
__device__ float g_e1  [CB*CN];
__device__ float g_e2  [CB*CN];
__device__ float g_rsc [2];

// ---------------- tf32 / async helpers ----------------
__device__ __forceinline__ uint32_t f2tf(float f) {
    uint32_t u;
    asm("cvt.rna.tf32.f32 %0, %1;" : "=r"(u) : "f"(f));
    return u;
}
__device__ __forceinline__ void mma_tf32(float c[4], const uint32_t a[4], const uint32_t b[2]) {
    asm volatile(
        "mma.sync.aligned.m16n8k8.row.col.f32.tf32.tf32.f32 "
        "{%0,%1,%2,%3}, {%4,%5,%6,%7}, {%8,%9}, {%0,%1,%2,%3};\n"
        : "+f"(c[0]), "+f"(c[1]), "+f"(c[2]), "+f"(c[3])
        : "r"(a[0]), "r"(a[1]), "r"(a[2]), "r"(a[3]), "r"(b[0]), "r"(b[1]));
}
__device__ __forceinline__ void cpasync16(uint32_t saddr, const void* gptr) {
    asm volatile("cp.async.cg.shared.global [%0], [%1], 16;\n" :: "r"(saddr), "l"(gptr));
}
__device__ __forceinline__ void cpcommit() { asm volatile("cp.async.commit_group;\n"); }
__device__ __forceinline__ void cpwait0()  { asm volatile("cp.async.wait_group 0;\n"); }
__device__ __forceinline__ void cpwait1()  { asm volatile("cp.async.wait_group 1;\n"); }

// ================= core GEMM tile (128x128, KS=32, 2-stage, 2 CTAs/SM) =================
struct TileCtx {
    float *As, *Bs;
    uint32_t As_b, Bs_b;
    const float *Ag, *Bg;
    int K, N;
    int tid;
};
constexpr int T_strA = 36, T_strB = 132;
constexpr int T_AW = 128 * T_strA, T_BW = 32 * T_strB;
constexpr int SM_TG = (2 * (T_AW + T_BW)) * 4;   // 70656 bytes

__device__ __forceinline__ void tg_load_stage(TileCtx& c, int kt, int s) {
    int k0 = kt * 32;
    #pragma unroll
    for (int i = 0; i < 4; i++) {
        int f = c.tid + i * 256;
        int m = f >> 3, k4 = (f & 7) * 4;
        cpasync16(c.As_b + (uint32_t)(((s * 128 + m) * T_strA + k4) * 4),
                  c.Ag + (long)m * c.K + k0 + k4);
    }
    #pragma unroll
    for (int i = 0; i < 4; i++) {
        int f = c.tid + i * 256;
        int k = f >> 5, n4 = (f & 31) * 4;
        cpasync16(c.Bs_b + (uint32_t)(((s * 32 + k) * T_strB + n4) * 4),
                  c.Bg + (long)(k0 + k) * c.N + n4);
    }
    cpcommit();
}

// act: 0 none, 1 relu, 2 elu, 3 store-tf32-bits
__device__ __forceinline__ void tg_body(
    TileCtx& c, const float* bias, float* C, int M, int N, int K,
    int row0, int col0, float scale, int act)
{
    int tid  = c.tid;
    int warp = tid >> 5, lane = tid & 31;
    int g = lane >> 2, tg = lane & 3;
    int mw = warp >> 2, nw = warp & 3;

    float acc[4][4][4];
    #pragma unroll
    for (int mi = 0; mi < 4; mi++)
        #pragma unroll
        for (int ni = 0; ni < 4; ni++)
            #pragma unroll
            for (int q = 0; q < 4; q++) acc[mi][ni][q] = 0.f;

    int nk = K / 32;
    tg_load_stage(c, 0, 0);

    for (int kt = 0; kt < nk; kt++) {
        cpwait0();
        __syncthreads();          // loads visible AND all warps done reading other stage
        int s = kt & 1;
        if (kt + 1 < nk) tg_load_stage(c, kt + 1, s ^ 1);

        const float* Asb = c.As + s * T_AW;
        const float* Bsb = c.Bs + s * T_BW;
        #pragma unroll
        for (int ks = 0; ks < 32; ks += 8) {
            uint32_t a[4][4], b[4][2];
            #pragma unroll
            for (int mi = 0; mi < 4; mi++) {
                int mr = mw * 64 + mi * 16;
                a[mi][0] = f2tf(Asb[(mr + g)     * T_strA + ks + tg]);
                a[mi][1] = f2tf(Asb[(mr + g + 8) * T_strA + ks + tg]);
                a[mi][2] = f2tf(Asb[(mr + g)     * T_strA + ks + tg + 4]);
                a[mi][3] = f2tf(Asb[(mr + g + 8) * T_strA + ks + tg + 4]);
            }
            #pragma unroll
            for (int ni = 0; ni < 4; ni++) {
                int nc = nw * 32 + ni * 8;
                b[ni][0] = f2tf(Bsb[(ks + tg)     * T_strB + nc + g]);
                b[ni][1] = f2tf(Bsb[(ks + tg + 4) * T_strB + nc + g]);
            }
            #pragma unroll
            for (int mi = 0; mi < 4; mi++)
                #pragma unroll
                for (int ni = 0; ni < 4; ni++)
                    mma_tf32(acc[mi][ni], a[mi], b[ni]);
        }
        // no bottom sync: loads for the other stage are issued only after the
        // NEXT iteration's top __syncthreads, which orders them after this compute.
    }

    #pragma unroll
    for (int mi = 0; mi < 4; mi++) {
        #pragma unroll
        for (int ni = 0; ni < 4; ni++) {
            int r = row0 + mw * 64 + mi * 16 + g;
            int cc0 = col0 + nw * 32 + ni * 8 + tg * 2;
            float b0 = bias ? bias[cc0] : 0.f;
            float b1 = bias ? bias[cc0 + 1] : 0.f;
            #pragma unroll
            for (int rr = 0; rr < 2; rr++) {
                float v0 = acc[mi][ni][rr * 2 + 0] * scale + b0;
                float v1 = acc[mi][ni][rr * 2 + 1] * scale + b1;
                if (act == 1) { v0 = fmaxf(v0, 0.f); v1 = fmaxf(v1, 0.f); }
                else if (act == 2) {
                    v0 = v0 > 0.f ? v0 : expm1f(v0);
                    v1 = v1 > 0.f ? v1 : expm1f(v1);
                } else if (act == 3) {
                    v0 = __uint_as_float(f2tf(v0));
                    v1 = __uint_as_float(f2tf(v1));
                }
                *(float2*)(C + (long)(r + rr * 8) * N + cc0) = make_float2(v0, v1);
            }
        }
    }
}

// ---------------- single GEMM (batched via strides) ----------------
template<int ACT>
__global__ void __launch_bounds__(256, 2) tgemm(
    const float* __restrict__ A, const float* __restrict__ Bm,
    const float* __restrict__ bias, float* __restrict__ C,
    int M, int N, int K, long sA, long sB, long sC, float scale)
{
    extern __shared__ float smem[];
    int bz = blockIdx.z;
    TileCtx c;
    c.As = smem; c.Bs = smem + 2 * T_AW;
    c.As_b = (uint32_t)__cvta_generic_to_shared(c.As);
    c.Bs_b = (uint32_t)__cvta_generic_to_shared(c.Bs);
    c.K = K; c.N = N; c.tid = threadIdx.x;
    int row0 = blockIdx.y * 128, col0 = blockIdx.x * 128;
    const float* Ab = A + (long)bz * sA;
    const float* Bb = Bm + (long)bz * sB;
    c.Ag = Ab + (long)row0 * K;
    c.Bg = Bb + col0;
    tg_body(c, bias, C + (long)bz * sC, M, N, K, row0, col0, scale, ACT);
}

// ---------------- paired GEMM: z selects {A,B,bias,C,act} ----------------
struct G2 { const float* A[2]; const float* B[2]; const float* bias[2]; float* C[2]; int act[2]; };
__global__ void __launch_bounds__(256, 2) tgemm_pair(G2 args, int M, int N, int K)
{
    extern __shared__ float smem[];
    int z = blockIdx.z;
    TileCtx c;
    c.As = smem; c.Bs = smem + 2 * T_AW;
    c.As_b = (uint32_t)__cvta_generic_to_shared(c.As);
    c.Bs_b = (uint32_t)__cvta_generic_to_shared(c.Bs);
    c.K = K; c.N = N; c.tid = threadIdx.x;
    int row0 = blockIdx.y * 128, col0 = blockIdx.x * 128;
    c.Ag = args.A[z] + (long)row0 * K;
    c.Bg = args.B[z] + col0;
    tg_body(c, args.bias[z], args.C[z], M, N, K, row0, col0, 1.f, args.act[z]);
}

// ---------------- fused flash attention, 64-row KV tiles ----------------
// Q, K, V already hold tf32-rounded bit patterns (stored as float).
__global__ void __launch_bounds__(256, 2) flash_kernel(
    const float* __restrict__ Q, const float* __restrict__ Kg_,
    const float* __restrict__ Vg_, float* __restrict__ O)
{
    constexpr int SK = 68, SV = 72, KT = 64;
    extern __shared__ float sm[];
    float* Qs = sm;                          // 128*68
    float* Ks = sm + 128 * SK;               // 2 * 64*68
    float* Vs = Ks + 2 * KT * SK;            // 2 * 64*72
    uint32_t Qs_b = (uint32_t)__cvta_generic_to_shared(Qs);
    uint32_t Ks_b = (uint32_t)__cvta_generic_to_shared(Ks);
    uint32_t Vs_b = (uint32_t)__cvta_generic_to_shared(Vs);
    const uint32_t* Ku = (const uint32_t*)Ks;
    const uint32_t* Vu = (const uint32_t*)Vs;

    long base = (long)blockIdx.y * CN * CDH;
    const float* Qg = Q + base + (long)blockIdx.x * 128 * CDH;
    const float* Kg = Kg_ + base;
    const float* Vg = Vg_ + base;
    float* Og = O + base + (long)blockIdx.x * 128 * CDH;

    int tid = threadIdx.x, warp = tid >> 5, lane = tid & 31;
    int g = lane >> 2, tg = lane & 3;
    int r0 = warp * 16;

    #pragma unroll
    for (int i = 0; i < 8; i++) {
        int f = tid + i * 256;
        int r = f >> 4, c4 = (f & 15) * 4;
        cpasync16(Qs_b + (uint32_t)((r * SK + c4) * 4), Qg + r * CDH + c4);
    }
    cpcommit();

    auto load_kv = [&](int t, int s) {
        const float* Kt = Kg + t * KT * CDH;
        const float* Vt = Vg + t * KT * CDH;
        #pragma unroll
        for (int i = 0; i < 4; i++) {
            int f = tid + i * 256;
            int r = f >> 4, c4 = (f & 15) * 4;
            cpasync16(Ks_b + (uint32_t)(((s * KT + r) * SK + c4) * 4), Kt + r * CDH + c4);
            cpasync16(Vs_b + (uint32_t)(((s * KT + r) * SV + c4) * 4), Vt + r * CDH + c4);
        }
        cpcommit();
    };
    load_kv(0, 0);

    cpwait1();            // Q done
    __syncthreads();

    // Q fragments (already tf32 bits)
    uint32_t aq[8][4];
    #pragma unroll
    for (int kf = 0; kf < 8; kf++) {
        aq[kf][0] = __float_as_uint(Qs[(r0 + g)     * SK + kf * 8 + tg]);
        aq[kf][1] = __float_as_uint(Qs[(r0 + g + 8) * SK + kf * 8 + tg]);
        aq[kf][2] = __float_as_uint(Qs[(r0 + g)     * SK + kf * 8 + tg + 4]);
        aq[kf][3] = __float_as_uint(Qs[(r0 + g + 8) * SK + kf * 8 + tg + 4]);
    }

    float m0 = -3.4e38f, m1 = -3.4e38f, l0 = 0.f, l1 = 0.f;
    float o[8][4];
    #pragma unroll
    for (int nf = 0; nf < 8; nf++)
        #pragma unroll
        for (int q = 0; q < 4; q++) o[nf][q] = 0.f;

    for (int t = 0; t < 16; t++) {
        int s = t & 1;
        if (t < 15) load_kv(t + 1, s ^ 1);
        if (t < 15) cpwait1(); else cpwait0();
        __syncthreads();

        // S = Q @ K^T  (per-warp [16,64])
        float sc[8][4];
        #pragma unroll
        for (int nf = 0; nf < 8; nf++)
            #pragma unroll
            for (int q = 0; q < 4; q++) sc[nf][q] = 0.f;
        #pragma unroll
        for (int kf = 0; kf < 8; kf++) {
            #pragma unroll
            for (int nf = 0; nf < 8; nf++) {
                uint32_t b[2];
                b[0] = Ku[(s * KT + nf * 8 + g) * SK + kf * 8 + tg];
                b[1] = Ku[(s * KT + nf * 8 + g) * SK + kf * 8 + tg + 4];
                mma_tf32(sc[nf], aq[kf], b);
            }
        }

        // online softmax (scale 1/8)
        float mx0 = -3.4e38f, mx1 = -3.4e38f;
        #pragma unroll
        for (int nf = 0; nf < 8; nf++) {
            mx0 = fmaxf(mx0, fmaxf(sc[nf][0], sc[nf][1]));
            mx1 = fmaxf(mx1, fmaxf(sc[nf][2], sc[nf][3]));
        }
        #pragma unroll
        for (int off = 1; off <= 2; off <<= 1) {
            mx0 = fmaxf(mx0, __shfl_xor_sync(0xffffffffu, mx0, off));
            mx1 = fmaxf(mx1, __shfl_xor_sync(0xffffffffu, mx1, off));
        }
        float mn0 = fmaxf(m0, mx0 * 0.125f);
        float mn1 = fmaxf(m1, mx1 * 0.125f);
        float cr0 = __expf(m0 - mn0);
        float cr1 = __expf(m1 - mn1);
        l0 *= cr0; l1 *= cr1;
        #pragma unroll
        for (int nf = 0; nf < 8; nf++) {
            o[nf][0] *= cr0; o[nf][1] *= cr0;
            o[nf][2] *= cr1; o[nf][3] *= cr1;
        }
        float rs0 = 0.f, rs1 = 0.f;
        #pragma unroll
        for (int nf = 0; nf < 8; nf++) {
            float p0 = __expf(sc[nf][0] * 0.125f - mn0);
            float p1 = __expf(sc[nf][1] * 0.125f - mn0);
            float p2 = __expf(sc[nf][2] * 0.125f - mn1);
            float p3 = __expf(sc[nf][3] * 0.125f - mn1);
            rs0 += p0 + p1;  rs1 += p2 + p3;
            sc[nf][0] = __uint_as_float(f2tf(p0));
            sc[nf][1] = __uint_as_float(f2tf(p1));
            sc[nf][2] = __uint_as_float(f2tf(p2));
            sc[nf][3] = __uint_as_float(f2tf(p3));
        }
        #pragma unroll
        for (int off = 1; off <= 2; off <<= 1) {
            rs0 += __shfl_xor_sync(0xffffffffu, rs0, off);
            rs1 += __shfl_xor_sync(0xffffffffu, rs1, off);
        }
        l0 += rs0; l1 += rs1; m0 = mn0; m1 = mn1;

        // O += P @ V : gather A-frags of P via intra-quad shuffles
        int srcA = (g << 2) + (tg >> 1);
        int srcB = srcA + 2;
        bool odd = tg & 1;
        #pragma unroll
        for (int kf = 0; kf < 8; kf++) {
            float u0 = __shfl_sync(0xffffffffu, sc[kf][0], srcA);
            float u1 = __shfl_sync(0xffffffffu, sc[kf][1], srcA);
            float u2 = __shfl_sync(0xffffffffu, sc[kf][2], srcA);
            float u3 = __shfl_sync(0xffffffffu, sc[kf][3], srcA);
            float w0 = __shfl_sync(0xffffffffu, sc[kf][0], srcB);
            float w1 = __shfl_sync(0xffffffffu, sc[kf][1], srcB);
            float w2 = __shfl_sync(0xffffffffu, sc[kf][2], srcB);
            float w3 = __shfl_sync(0xffffffffu, sc[kf][3], srcB);
            uint32_t a[4];
            a[0] = __float_as_uint(odd ? u1 : u0);
            a[1] = __float_as_uint(odd ? u3 : u2);
            a[2] = __float_as_uint(odd ? w1 : w0);
            a[3] = __float_as_uint(odd ? w3 : w2);
            #pragma unroll
            for (int nf = 0; nf < 8; nf++) {
                uint32_t b[2];
                b[0] = Vu[(s * KT + kf * 8 + tg)     * SV + nf * 8 + g];
                b[1] = Vu[(s * KT + kf * 8 + tg + 4) * SV + nf * 8 + g];
                mma_tf32(o[nf], a, b);
            }
        }
        __syncthreads();   // stage s must drain before next iter's prefetch overwrites it
    }

    float inv0 = 1.f / l0, inv1 = 1.f / l1;
    #pragma unroll
    for (int nf = 0; nf < 8; nf++) {
        int c = nf * 8 + tg * 2;
        *(float2*)(Og + (long)(r0 + g)     * CDH + c) = make_float2(o[nf][0] * inv0, o[nf][1] * inv0);
        *(float2*)(Og + (long)(r0 + g + 8) * CDH + c) = make_float2(o[nf][2] * inv1, o[nf][3] * inv1);
    }
}
constexpr int SM_FLASH = (128 * 68 + 2 * 64 * 68 + 2 * 64 * 72) * 4;  // 106496

// ---------------- fp32 tiled SGEMM (fc2 only) ----------------
template<int ACT>
__global__ void sgemm(const float* __restrict__ A, const float* __restrict__ Bm,
                      const float* __restrict__ bias, float* __restrict__ C,
                      int M, int N, int K)
{
    __shared__ float As[16][68];
    __shared__ float Bs[16][68];
    int tx = threadIdx.x;
    int tr = tx >> 4, tc = tx & 15;
    int row0 = blockIdx.y * 64, col0 = blockIdx.x * 64;

    float acc[4][4] = {};
    for (int k0 = 0; k0 < K; k0 += 16) {
        #pragma unroll
        for (int i = 0; i < 4; i++) {
            int idx = tx * 4 + i;
            int m = idx >> 4, k = idx & 15;
            int gr = row0 + m;
            As[k][m] = (gr < M) ? A[(long)gr * K + k0 + k] : 0.f;
        }
        #pragma unroll
        for (int i = 0; i < 4; i++) {
            int idx = tx * 4 + i;
            int k = idx >> 6, n = idx & 63;
            int gn = col0 + n;
            Bs[k][n] = (gn < N) ? Bm[(long)(k0 + k) * N + gn] : 0.f;
        }
        __syncthreads();
        #pragma unroll
        for (int k = 0; k < 16; k++) {
            float a[4], b[4];
            #pragma unroll
            for (int i = 0; i < 4; i++) a[i] = As[k][tr * 4 + i];
            #pragma unroll
            for (int j = 0; j < 4; j++) b[j] = Bs[k][tc * 4 + j];
            #pragma unroll
            for (int i = 0; i < 4; i++)
                #pragma unroll
                for (int j = 0; j < 4; j++)
                    acc[i][j] = fmaf(a[i], b[j], acc[i][j]);
        }
        __syncthreads();
    }
    #pragma unroll
    for (int i = 0; i < 4; i++) {
        int gr = row0 + tr * 4 + i;
        if (gr >= M) continue;
        #pragma unroll
        for (int j = 0; j < 4; j++) {
            int gn = col0 + tc * 4 + j;
            if (gn >= N) continue;
            float v = acc[i][j];
            if (bias) v += bias[gn];
            if (ACT == 1) v = v > 0.f ? v : 0.f;
            C[(long)gr * N + gn] = v;
        }
    }
}

// ---------------- logits: warp per row, N=7 ----------------
__global__ void logits_kernel(const float* __restrict__ H, const float* __restrict__ W,
                              const float* __restrict__ bb, float* __restrict__ out)
{
    int warp = threadIdx.x >> 5, lane = threadIdx.x & 31;
    int row = blockIdx.x * 8 + warp;
    float hv[8];
    #pragma unroll
    for (int j = 0; j < 8; j++) hv[j] = H[(long)row * CHID + j * 32 + lane];
    float acc[CNC];
    #pragma unroll
    for (int c = 0; c < CNC; c++) {
        float a = 0.f;
        #pragma unroll
        for (int j = 0; j < 8; j++) a = fmaf(hv[j], W[(j * 32 + lane) * CNC + c], a);
        acc[c] = a;
    }
    #pragma unroll
    for (int c = 0; c < CNC; c++)
        #pragma unroll
        for (int off = 16; off > 0; off >>= 1)
            acc[c] += __shfl_xor_sync(0xffffffffu, acc[c], off);
    if (lane < CNC) out[(long)row * CNC + lane] = acc[lane] + bb[lane];
}

// ---------------- P_l_1 ----------------
__global__ void pl1_kernel(const float* __restrict__ sadj, const float* __restrict__ P,
                           float* __restrict__ out)
{
    long idx = (long)blockIdx.x * 256 + threadIdx.x;
    int d = idx & (CHID - 1);
    int n = (idx >> 8) & (CN - 1);
    int b = (int)(idx >> 18);
    const float* sa = sadj + (long)b * CM * CN + n;
    const float* Pb = P + (long)b * CM * CHID + d;
    float acc = 0.f;
    #pragma unroll
    for (int m = 0; m < CM; m++) acc = fmaf(sa[m * CN], Pb[m * CHID], acc);
    out[idx] = acc;
}

// ---------------- P_agg ----------------
__global__ void pagg_kernel(const float* __restrict__ sadj, const float* __restrict__ H,
                            float* __restrict__ out)
{
    int bm = blockIdx.x;
    int b = bm >> 3;
    int d = threadIdx.x;
    const float* sa = sadj + (long)bm * CN;
    const float* Hb = H + (long)b * CN * CHID + d;
    float acc = 0.f;
    #pragma unroll 4
    for (int n = 0; n < CN; n++) acc = fmaf(sa[n], Hb[(long)n * CHID], acc);
    out[(long)bm * CHID + d] = acc;
}

// ---------------- e1/e2 dots: warp per row ----------------
__global__ void dots_kernel(const float* __restrict__ h, const float* __restrict__ a1,
                            const float* __restrict__ a2,
                            float* __restrict__ e1, float* __restrict__ e2)
{
    int warp = threadIdx.x >> 5, lane = threadIdx.x & 31;
    int row = blockIdx.x * 8 + warp;
    float s1 = 0.f, s2 = 0.f;
    #pragma unroll
    for (int j = 0; j < 8; j++) {
        int c = j * 32 + lane;
        float v = h[(long)row * CHID + c];
        s1 = fmaf(v, a1[c], s1);
        s2 = fmaf(v, a2[c], s2);
    }
    #pragma unroll
    for (int off = 16; off > 0; off >>= 1) {
        s1 += __shfl_xor_sync(0xffffffffu, s1, off);
        s2 += __shfl_xor_sync(0xffffffffu, s2, off);
    }
    if (lane == 0) { e1[row] = s1; e2[row] = s2; }
}

// ---------------- rel_sc ----------------
__global__ void relsc_kernel(const float* __restrict__ rel, const float* __restrict__ a3,
                             float* __restrict__ out)
{
    __shared__ float s[256];
    int r = blockIdx.x, t = threadIdx.x;
    s[t] = rel[r * CHID + t] * a3[t];
    __syncthreads();
    for (int o = 128; o > 0; o >>= 1) {
        if (t < o) s[t] += s[t + o];
        __syncthreads();
    }
    if (t == 0) out[r] = s[0];
}

// ---------------- GAT edge scores + masked softmax (vectorized) ----------------
__global__ void gat_att_kernel(const float* __restrict__ e1, const float* __restrict__ e2,
                               const float* __restrict__ rsc,
                               const int* __restrict__ adj, const int* __restrict__ smask,
                               float* __restrict__ att)
{
    __shared__ float red[256];
    int bi = blockIdx.x;
    int b = bi >> 10;
    long base = (long)bi * CN;
    int t = threadIdx.x;
    float E1 = e1[bi];
    float r0 = rsc[0], r1 = rsc[1];

    int4   ad = ((const int4*)(adj + base))[t];
    int4   sk = ((const int4*)(smask + base))[t];
    float4 ev = ((const float4*)(e2 + (long)b * CN))[t];

    float vals[4];
    {
        float e;
        e = E1 + ev.x + (sk.x ? r1 : r0); e = e >= 0.f ? e : ALPHAF * e; vals[0] = ad.x ? e : NEGF;
        e = E1 + ev.y + (sk.y ? r1 : r0); e = e >= 0.f ? e : ALPHAF * e; vals[1] = ad.y ? e : NEGF;
        e = E1 + ev.z + (sk.z ? r1 : r0); e = e >= 0.f ? e : ALPHAF * e; vals[2] = ad.z ? e : NEGF;
        e = E1 + ev.w + (sk.w ? r1 : r0); e = e >= 0.f ? e : ALPHAF * e; vals[3] = ad.w ? e : NEGF;
    }
    float mx = fmaxf(fmaxf(vals[0], vals[1]), fmaxf(vals[2], vals[3]));
    red[t] = mx; __syncthreads();
    for (int o = 128; o > 0; o >>= 1) {
        if (t < o) red[t] = fmaxf(red[t], red[t + o]);
        __syncthreads();
    }
    mx = red[0]; __syncthreads();
    float s = 0.f;
    #pragma unroll
    for (int q = 0; q < 4; q++) { vals[q] = __expf(vals[q] - mx); s += vals[q]; }
    red[t] = s; __syncthreads();
    for (int o = 128; o > 0; o >>= 1) {
        if (t < o) red[t] += red[t + o];
        __syncthreads();
    }
    float inv = 1.f / red[0];
    ((float4*)(att + base))[t] =
        make_float4(vals[0] * inv, vals[1] * inv, vals[2] * inv, vals[3] * inv);
}

// ---------------- LayerNorm: warp per row ----------------
__global__ void ln_kernel(const float* __restrict__ T, const float* __restrict__ Hold,
                          const float* __restrict__ g, const float* __restrict__ bb,
                          float* __restrict__ out)
{
    int warp = threadIdx.x >> 5, lane = threadIdx.x & 31;
    int row = blockIdx.x * 8 + warp;
    long base = (long)row * CHID;
    float v[8];
    float s = 0.f;
    #pragma unroll
    for (int j = 0; j < 8; j++) {
        int c = j * 32 + lane;
        v[j] = T[base + c] + Hold[base + c];
        s += v[j];
    }
    #pragma unroll
    for (int off = 16; off > 0; off >>= 1) s += __shfl_xor_sync(0xffffffffu, s, off);
    float mu = s * (1.f / CHID);
    float q = 0.f;
    #pragma unroll
    for (int j = 0; j < 8; j++) { v[j] -= mu; q = fmaf(v[j], v[j], q); }
    #pragma unroll
    for (int off = 16; off > 0; off >>= 1) q += __shfl_xor_sync(0xffffffffu, q, off);
    float rstd = rsqrtf(q * (1.f / CHID) + 1e-5f);
    #pragma unroll
    for (int j = 0; j < 8; j++) {
        int c = j * 32 + lane;
        out[base + c] = v[j] * rstd * g[c] + bb[c];
    }
}

// ---------------- GRU3d ----------------
__global__ void gru_kernel(float* __restrict__ P, const float* __restrict__ Pagg,
                           const float* __restrict__ wz, const float* __restrict__ uz,
                           const float* __restrict__ wr, const float* __restrict__ ur,
                           const float* __restrict__ w,  const float* __restrict__ u)
{
    __shared__ float sp[CHID], sq[CHID];
    int r = blockIdx.x;
    int c = threadIdx.x;
    sp[c] = P[(long)r * CHID + c];
    sq[c] = Pagg[(long)r * CHID + c];
    __syncthreads();
    float az = 0, bz = 0, ar = 0, br = 0, aw = 0, bw = 0;
    #pragma unroll 4
    for (int k = 0; k < CHID; k++) {
        float pk = sp[k], qk = sq[k];
        az = fmaf(pk, wz[k * CHID + c], az); bz = fmaf(qk, uz[k * CHID + c], bz);
        ar = fmaf(pk, wr[k * CHID + c], ar); br = fmaf(qk, ur[k * CHID + c], br);
        aw = fmaf(pk, w [k * CHID + c], aw); bw = fmaf(qk, u [k * CHID + c], bw);
    }
    float z  = 1.f / (1.f + expf(-(az + bz)));
    float rr = 1.f / (1.f + expf(-(ar + br)));
    float hh = tanhf(aw + rr * bw);
    P[(long)r * CHID + c] = (1.f - z) * sp[c] + z * hh;
}

// ---------------- p_sim ----------------
__global__ void psim_kernel(const float* __restrict__ P, float* __restrict__ outp, int tail)
{
    __shared__ float red[64];
    int t = threadIdx.x;
    int b = t >> 3, m = t & 7;
    const float* Pb = P + (long)b * CM * CHID;
    float s = 0.f;
    for (int k2 = 0; k2 < CM; k2++) {
        if (k2 == m) continue;
        float d = 0.f;
        for (int dd = 0; dd < CHID; dd++)
            d = fmaf(Pb[m * CHID + dd], Pb[k2 * CHID + dd], d);
        s += d;
    }
    red[t] = s; __syncthreads();
    if ((t & 7) < 4) red[t] += red[t + 4]; __syncthreads();
    if ((t & 7) < 2) red[t] += red[t + 2]; __syncthreads();
    if ((t & 7) < 1) red[t] += red[t + 1]; __syncthreads();
    if (tail >= CB) {
        if (t < CB) outp[t] = red[t * 8] / (float)(CM * CM);
    } else {
        if (t == 0) {
            float tot = 0.f;
            for (int b2 = 0; b2 < CB; b2++) tot += red[b2 * 8];
            outp[0] = tot / (float)(CB * CM * CM);
        }
    }
}

// ---------------- host orchestration ----------------
extern "C" void kernel_launch(void* const* d_in, const int* in_sizes, int n_in,
                              void* d_out, int out_size)
{
    const float* x     = (const float*)d_in[0];
    const int*   adj   = (const int*)  d_in[1];
    const int*   smask = (const int*)  d_in[2];
    const float* sf    = (const float*)d_in[3];
    const float* sadj  = (const float*)d_in[4];
    const float* fc1w  = (const float*)d_in[6];
    const float* fc1b  = (const float*)d_in[7];
    const float* fc2w  = (const float*)d_in[8];
    const float* fc2b  = (const float*)d_in[9];
    const float* gatW  = (const float*)d_in[10];
    const float* gata  = (const float*)d_in[11];
    const float* rel   = (const float*)d_in[12];
    const float* gwz   = (const float*)d_in[13];
    const float* guz   = (const float*)d_in[14];
    const float* gwr   = (const float*)d_in[15];
    const float* gur   = (const float*)d_in[16];
    const float* gw    = (const float*)d_in[17];
    const float* gu    = (const float*)d_in[18];
    const float* wv    = (const float*)d_in[19];
    const float* bv    = (const float*)d_in[20];
    const float* wk    = (const float*)d_in[21];
    const float* bk    = (const float*)d_in[22];
    const float* wq    = (const float*)d_in[23];
    const float* bq    = (const float*)d_in[24];
    const float* wo    = (const float*)d_in[25];
    const float* bo    = (const float*)d_in[26];
    const float* lng   = (const float*)d_in[27];
    const float* lnb   = (const float*)d_in[28];
    const float* outw  = (const float*)d_in[29];
    const float* outb  = (const float*)d_in[30];
    float* out = (float*)d_out;

    float *H, *Hn, *P, *Pagg, *Pl1, *hb, *Agg, *Qb, *Kb, *Vb, *ctx, *Tb, *att, *e1, *e2, *rsc;
    cudaGetSymbolAddress((void**)&H,    g_H);
    cudaGetSymbolAddress((void**)&Hn,   g_Hn);
    cudaGetSymbolAddress((void**)&P,    g_P);
    cudaGetSymbolAddress((void**)&Pagg, g_Pagg);
    cudaGetSymbolAddress((void**)&Pl1,  g_Pl1);
    cudaGetSymbolAddress((void**)&hb,   g_h);
    cudaGetSymbolAddress((void**)&Agg,  g_Agg);
    cudaGetSymbolAddress((void**)&Qb,   g_Q);
    cudaGetSymbolAddress((void**)&Kb,   g_K);
    cudaGetSymbolAddress((void**)&Vb,   g_V);
    cudaGetSymbolAddress((void**)&ctx,  g_ctx);
    cudaGetSymbolAddress((void**)&Tb,   g_T);
    cudaGetSymbolAddress((void**)&att,  g_att);
    cudaGetSymbolAddress((void**)&e1,   g_e1);
    cudaGetSymbolAddress((void**)&e2,   g_e2);
    cudaGetSymbolAddress((void**)&rsc,  g_rsc);

    cudaFuncSetAttribute(tgemm<0>, cudaFuncAttributeMaxDynamicSharedMemorySize, SM_TG);
    cudaFuncSetAttribute(tgemm<1>, cudaFuncAttributeMaxDynamicSharedMemorySize, SM_TG);
    cudaFuncSetAttribute(tgemm<2>, cudaFuncAttributeMaxDynamicSharedMemorySize, SM_TG);
    cudaFuncSetAttribute(tgemm_pair, cudaFuncAttributeMaxDynamicSharedMemorySize, SM_TG);
    cudaFuncSetAttribute(flash_kernel, cudaFuncAttributeMaxDynamicSharedMemorySize, SM_FLASH);

    dim3 blk(256);
    const int BN = CB * CN;                          // 8192
    const long HH = (long)CHID * CHID;               // 65536

    // H = relu(x @ fc1_w + b)
    tgemm<1><<<dim3(2, 64, 1), blk, SM_TG>>>(x, fc1w, fc1b, H, BN, CHID, CDIN, 0, 0, 0, 1.f);
    // P = relu(s_feature @ fc2_w + b)
    sgemm<1><<<dim3(4, 1, 1), blk>>>(sf, fc2w, fc2b, P, CB * CM, CHID, CDIN);

    for (int l = 0; l < CL; l++) {
        float* cur = l ? Hn : H;
        float* nxt = l ? H : Hn;

        // P_l_1 = s_adj^T @ P
        pl1_kernel<<<BN * CHID / 256, blk>>>(sadj, P, Pl1);

        // paired: h = cur @ gat_W[l] (fp32) ; V = cur @ wv + bv (tf32 bits)
        {
            G2 a;
            a.A[0] = cur;           a.A[1] = cur;
            a.B[0] = gatW + l * HH; a.B[1] = wv + l * HH;
            a.bias[0] = nullptr;    a.bias[1] = bv + l * CHID;
            a.C[0] = hb;            a.C[1] = Vb;
            a.act[0] = 0;           a.act[1] = 3;
            tgemm_pair<<<dim3(2, 64, 2), blk, SM_TG>>>(a, BN, CHID, CHID);
        }
        // edge-score ingredients
        dots_kernel<<<BN / 8, blk>>>(hb, gata + l * 3 * CHID, gata + l * 3 * CHID + CHID, e1, e2);
        relsc_kernel<<<2, blk>>>(rel + l * 2 * CHID, gata + l * 3 * CHID + 2 * CHID, rsc);
        gat_att_kernel<<<BN, blk>>>(e1, e2, rsc, adj, smask, att);
        // Agg = elu(att @ h)
        tgemm<2><<<dim3(2, 8, CB), blk, SM_TG>>>(att, hb, nullptr, Agg,
                                                 CN, CHID, CN,
                                                 (long)CN * CN, (long)CN * CHID, (long)CN * CHID, 1.f);
        // paired: K = Pl1 @ wk + bk ; Q = Agg @ wq + bq   (both tf32 bits)
        {
            G2 a;
            a.A[0] = Pl1;           a.A[1] = Agg;
            a.B[0] = wk + l * HH;   a.B[1] = wq + l * HH;
            a.bias[0] = bk + l * CHID; a.bias[1] = bq + l * CHID;
            a.C[0] = Kb;            a.C[1] = Qb;
            a.act[0] = 3;           a.act[1] = 3;
            tgemm_pair<<<dim3(2, 64, 2), blk, SM_TG>>>(a, BN, CHID, CHID);
        }
        // fused MHA
        flash_kernel<<<dim3(8, 32), blk, SM_FLASH>>>(Qb, Kb, Vb, ctx);
        // T = ctx @ wo + bo ;  H_new = LN(T + H)
        tgemm<0><<<dim3(2, 64, 1), blk, SM_TG>>>(ctx, wo + l * HH, bo + l * CHID, Tb,
                                                 BN, CHID, CHID, 0, 0, 0, 1.f);
        ln_kernel<<<BN / 8, blk>>>(Tb, cur, lng + l * CHID, lnb + l * CHID, nxt);

        // GRU speaker update (uses pre-update H)
        pagg_kernel<<<CB * CM, blk>>>(sadj, cur, Pagg);
        gru_kernel<<<CB * CM, blk>>>(P, Pagg,
                                     gwz + l * HH, guz + l * HH,
                                     gwr + l * HH, gur + l * HH,
                                     gw + l * HH,  gu + l * HH);
    }

    // logits
    logits_kernel<<<BN / 8, blk>>>(H, outw, outb, out);
    // p_sim
    psim_kernel<<<1, 64>>>(P, out + (long)BN * CNC, out_size - BN * CNC);
}

// round 9
// speedup vs baseline: 1.0571x; 1.0139x over previous
#include <cuda_runtime.h>
#include <math.h>
#include <stdint.h>

// ---------------- problem constants ----------------
constexpr int CB   = 8;      // batch
constexpr int CN   = 1024;   // nodes
constexpr int CM   = 8;      // speakers
constexpr int CDIN = 1024;
constexpr int CHID = 256;
constexpr int CL   = 2;
constexpr int CNC  = 7;
constexpr int CNH  = 4;
constexpr int CDH  = 64;
#define NEGF  (-9e15f)
#define ALPHAF 0.1f

// ---------------- scratch ----------------
__device__ float g_H   [CB*CN*CHID];
__device__ float g_Hn  [CB*CN*CHID];
__device__ float g_P   [CB*CM*CHID];
__device__ float g_Pl1 [CB*CN*CHID];
__device__ float g_h   [CB*CN*CHID];
__device__ float g_Agg [CB*CN*CHID];
__device__ float g_Q   [CB*CN*CHID];
__device__ float g_K   [CB*CN*CHID];
__device__ float g_V   [CB*CN*CHID];
__device__ float g_ctx [CB*CN*CHID];
__device__ float g_T   [CB*CN*CHID];
__device__ uint8_t g_codes[(long)CB*CN*CN];   // 2-bit masks packed (8.4 MB)
__device__ float g_e1  [CB*CN];
__device__ float g_e2  [CB*CN];
__device__ float g_rsc [2];

// ---------------- tf32 / async helpers ----------------
__device__ __forceinline__ uint32_t f2tf(float f) {
    uint32_t u;
    asm("cvt.rna.tf32.f32 %0, %1;" : "=r"(u) : "f"(f));
    return u;
}
__device__ __forceinline__ void mma_tf32(float c[4], const uint32_t a[4], const uint32_t b[2]) {
    asm volatile(
        "mma.sync.aligned.m16n8k8.row.col.f32.tf32.tf32.f32 "
        "{%0,%1,%2,%3}, {%4,%5,%6,%7}, {%8,%9}, {%0,%1,%2,%3};\n"
        : "+f"(c[0]), "+f"(c[1]), "+f"(c[2]), "+f"(c[3])
        : "r"(a[0]), "r"(a[1]), "r"(a[2]), "r"(a[3]), "r"(b[0]), "r"(b[1]));
}
__device__ __forceinline__ void cpasync16(uint32_t saddr, const void* gptr) {
    asm volatile("cp.async.cg.shared.global [%0], [%1], 16;\n" :: "r"(saddr), "l"(gptr));
}
__device__ __forceinline__ void cpcommit() { asm volatile("cp.async.commit_group;\n"); }
__device__ __forceinline__ void cpwait0()  { asm volatile("cp.async.wait_group 0;\n"); }
__device__ __forceinline__ void cpwait1()  { asm volatile("cp.async.wait_group 1;\n"); }

// ================= core GEMM tile (128x128, KS=32, 2-stage, 2 CTAs/SM) =================
struct TileCtx {
    float *As, *Bs;
    uint32_t As_b, Bs_b;
    const float *Ag, *Bg;
    int K, N;
    int tid;
};
constexpr int T_strA = 36, T_strB = 132;
constexpr int T_AW = 128 * T_strA, T_BW = 32 * T_strB;
constexpr int SM_TG = (2 * (T_AW + T_BW)) * 4;   // 70656 bytes

__device__ __forceinline__ void tg_load_stage(TileCtx& c, int kt, int s) {
    int k0 = kt * 32;
    #pragma unroll
    for (int i = 0; i < 4; i++) {
        int f = c.tid + i * 256;
        int m = f >> 3, k4 = (f & 7) * 4;
        cpasync16(c.As_b + (uint32_t)(((s * 128 + m) * T_strA + k4) * 4),
                  c.Ag + (long)m * c.K + k0 + k4);
    }
    #pragma unroll
    for (int i = 0; i < 4; i++) {
        int f = c.tid + i * 256;
        int k = f >> 5, n4 = (f & 31) * 4;
        cpasync16(c.Bs_b + (uint32_t)(((s * 32 + k) * T_strB + n4) * 4),
                  c.Bg + (long)(k0 + k) * c.N + n4);
    }
    cpcommit();
}

// act: 0 none, 1 relu, 2 elu, 3 store-tf32-bits
__device__ __forceinline__ void tg_body(
    TileCtx& c, const float* bias, float* C, int M, int N, int K,
    int row0, int col0, float scale, int act)
{
    int tid  = c.tid;
    int warp = tid >> 5, lane = tid & 31;
    int g = lane >> 2, tg = lane & 3;
    int mw = warp >> 2, nw = warp & 3;

    float acc[4][4][4];
    #pragma unroll
    for (int mi = 0; mi < 4; mi++)
        #pragma unroll
        for (int ni = 0; ni < 4; ni++)
            #pragma unroll
            for (int q = 0; q < 4; q++) acc[mi][ni][q] = 0.f;

    int nk = K / 32;
    tg_load_stage(c, 0, 0);

    for (int kt = 0; kt < nk; kt++) {
        cpwait0();
        __syncthreads();
        int s = kt & 1;
        if (kt + 1 < nk) tg_load_stage(c, kt + 1, s ^ 1);

        const float* Asb = c.As + s * T_AW;
        const float* Bsb = c.Bs + s * T_BW;
        #pragma unroll
        for (int ks = 0; ks < 32; ks += 8) {
            uint32_t a[4][4], b[4][2];
            #pragma unroll
            for (int mi = 0; mi < 4; mi++) {
                int mr = mw * 64 + mi * 16;
                a[mi][0] = f2tf(Asb[(mr + g)     * T_strA + ks + tg]);
                a[mi][1] = f2tf(Asb[(mr + g + 8) * T_strA + ks + tg]);
                a[mi][2] = f2tf(Asb[(mr + g)     * T_strA + ks + tg + 4]);
                a[mi][3] = f2tf(Asb[(mr + g + 8) * T_strA + ks + tg + 4]);
            }
            #pragma unroll
            for (int ni = 0; ni < 4; ni++) {
                int nc = nw * 32 + ni * 8;
                b[ni][0] = f2tf(Bsb[(ks + tg)     * T_strB + nc + g]);
                b[ni][1] = f2tf(Bsb[(ks + tg + 4) * T_strB + nc + g]);
            }
            #pragma unroll
            for (int mi = 0; mi < 4; mi++)
                #pragma unroll
                for (int ni = 0; ni < 4; ni++)
                    mma_tf32(acc[mi][ni], a[mi], b[ni]);
        }
    }

    #pragma unroll
    for (int mi = 0; mi < 4; mi++) {
        #pragma unroll
        for (int ni = 0; ni < 4; ni++) {
            int r = row0 + mw * 64 + mi * 16 + g;
            int cc0 = col0 + nw * 32 + ni * 8 + tg * 2;
            float b0 = bias ? bias[cc0] : 0.f;
            float b1 = bias ? bias[cc0 + 1] : 0.f;
            #pragma unroll
            for (int rr = 0; rr < 2; rr++) {
                float v0 = acc[mi][ni][rr * 2 + 0] * scale + b0;
                float v1 = acc[mi][ni][rr * 2 + 1] * scale + b1;
                if (act == 1) { v0 = fmaxf(v0, 0.f); v1 = fmaxf(v1, 0.f); }
                else if (act == 2) {
                    v0 = v0 > 0.f ? v0 : expm1f(v0);
                    v1 = v1 > 0.f ? v1 : expm1f(v1);
                } else if (act == 3) {
                    v0 = __uint_as_float(f2tf(v0));
                    v1 = __uint_as_float(f2tf(v1));
                }
                *(float2*)(C + (long)(r + rr * 8) * N + cc0) = make_float2(v0, v1);
            }
        }
    }
}

// ---------------- single GEMM (batched via strides) ----------------
template<int ACT>
__global__ void __launch_bounds__(256, 2) tgemm(
    const float* __restrict__ A, const float* __restrict__ Bm,
    const float* __restrict__ bias, float* __restrict__ C,
    int M, int N, int K, long sA, long sB, long sC, float scale)
{
    extern __shared__ float smem[];
    int bz = blockIdx.z;
    TileCtx c;
    c.As = smem; c.Bs = smem + 2 * T_AW;
    c.As_b = (uint32_t)__cvta_generic_to_shared(c.As);
    c.Bs_b = (uint32_t)__cvta_generic_to_shared(c.Bs);
    c.K = K; c.N = N; c.tid = threadIdx.x;
    int row0 = blockIdx.y * 128, col0 = blockIdx.x * 128;
    const float* Ab = A + (long)bz * sA;
    const float* Bb = Bm + (long)bz * sB;
    c.Ag = Ab + (long)row0 * K;
    c.Bg = Bb + col0;
    tg_body(c, bias, C + (long)bz * sC, M, N, K, row0, col0, scale, ACT);
}

// ---------------- paired GEMM: z selects {A,B,bias,C,act} ----------------
struct G2 { const float* A[2]; const float* B[2]; const float* bias[2]; float* C[2]; int act[2]; };
__global__ void __launch_bounds__(256, 2) tgemm_pair(G2 args, int M, int N, int K)
{
    extern __shared__ float smem[];
    int z = blockIdx.z;
    TileCtx c;
    c.As = smem; c.Bs = smem + 2 * T_AW;
    c.As_b = (uint32_t)__cvta_generic_to_shared(c.As);
    c.Bs_b = (uint32_t)__cvta_generic_to_shared(c.Bs);
    c.K = K; c.N = N; c.tid = threadIdx.x;
    int row0 = blockIdx.y * 128, col0 = blockIdx.x * 128;
    c.Ag = args.A[z] + (long)row0 * K;
    c.Bg = args.B[z] + col0;
    tg_body(c, args.bias[z], args.C[z], M, N, K, row0, col0, 1.f, args.act[z]);
}

// ---------------- fused flash attention (MHA), 64-row KV tiles ----------------
// Q, K, V already hold tf32-rounded bit patterns (stored as float).
__global__ void __launch_bounds__(256, 2) flash_kernel(
    const float* __restrict__ Q, const float* __restrict__ Kg_,
    const float* __restrict__ Vg_, float* __restrict__ O)
{
    constexpr int SK = 68, SV = 72, KT = 64;
    extern __shared__ float sm[];
    float* Qs = sm;                          // 128*68
    float* Ks = sm + 128 * SK;               // 2 * 64*68
    float* Vs = Ks + 2 * KT * SK;            // 2 * 64*72
    uint32_t Qs_b = (uint32_t)__cvta_generic_to_shared(Qs);
    uint32_t Ks_b = (uint32_t)__cvta_generic_to_shared(Ks);
    uint32_t Vs_b = (uint32_t)__cvta_generic_to_shared(Vs);
    const uint32_t* Ku = (const uint32_t*)Ks;
    const uint32_t* Vu = (const uint32_t*)Vs;

    long base = (long)blockIdx.y * CN * CDH;
    const float* Qg = Q + base + (long)blockIdx.x * 128 * CDH;
    const float* Kg = Kg_ + base;
    const float* Vg = Vg_ + base;
    float* Og = O + base + (long)blockIdx.x * 128 * CDH;

    int tid = threadIdx.x, warp = tid >> 5, lane = tid & 31;
    int g = lane >> 2, tg = lane & 3;
    int r0 = warp * 16;

    #pragma unroll
    for (int i = 0; i < 8; i++) {
        int f = tid + i * 256;
        int r = f >> 4, c4 = (f & 15) * 4;
        cpasync16(Qs_b + (uint32_t)((r * SK + c4) * 4), Qg + r * CDH + c4);
    }
    cpcommit();

    auto load_kv = [&](int t, int s) {
        const float* Kt = Kg + t * KT * CDH;
        const float* Vt = Vg + t * KT * CDH;
        #pragma unroll
        for (int i = 0; i < 4; i++) {
            int f = tid + i * 256;
            int r = f >> 4, c4 = (f & 15) * 4;
            cpasync16(Ks_b + (uint32_t)(((s * KT + r) * SK + c4) * 4), Kt + r * CDH + c4);
            cpasync16(Vs_b + (uint32_t)(((s * KT + r) * SV + c4) * 4), Vt + r * CDH + c4);
        }
        cpcommit();
    };
    load_kv(0, 0);

    cpwait1();            // Q done
    __syncthreads();

    uint32_t aq[8][4];
    #pragma unroll
    for (int kf = 0; kf < 8; kf++) {
        aq[kf][0] = __float_as_uint(Qs[(r0 + g)     * SK + kf * 8 + tg]);
        aq[kf][1] = __float_as_uint(Qs[(r0 + g + 8) * SK + kf * 8 + tg]);
        aq[kf][2] = __float_as_uint(Qs[(r0 + g)     * SK + kf * 8 + tg + 4]);
        aq[kf][3] = __float_as_uint(Qs[(r0 + g + 8) * SK + kf * 8 + tg + 4]);
    }

    float m0 = -3.4e38f, m1 = -3.4e38f, l0 = 0.f, l1 = 0.f;
    float o[8][4];
    #pragma unroll
    for (int nf = 0; nf < 8; nf++)
        #pragma unroll
        for (int q = 0; q < 4; q++) o[nf][q] = 0.f;

    for (int t = 0; t < 16; t++) {
        int s = t & 1;
        if (t < 15) load_kv(t + 1, s ^ 1);
        if (t < 15) cpwait1(); else cpwait0();
        __syncthreads();

        float sc[8][4];
        #pragma unroll
        for (int nf = 0; nf < 8; nf++)
            #pragma unroll
            for (int q = 0; q < 4; q++) sc[nf][q] = 0.f;
        #pragma unroll
        for (int kf = 0; kf < 8; kf++) {
            #pragma unroll
            for (int nf = 0; nf < 8; nf++) {
                uint32_t b[2];
                b[0] = Ku[(s * KT + nf * 8 + g) * SK + kf * 8 + tg];
                b[1] = Ku[(s * KT + nf * 8 + g) * SK + kf * 8 + tg + 4];
                mma_tf32(sc[nf], aq[kf], b);
            }
        }

        float mx0 = -3.4e38f, mx1 = -3.4e38f;
        #pragma unroll
        for (int nf = 0; nf < 8; nf++) {
            mx0 = fmaxf(mx0, fmaxf(sc[nf][0], sc[nf][1]));
            mx1 = fmaxf(mx1, fmaxf(sc[nf][2], sc[nf][3]));
        }
        #pragma unroll
        for (int off = 1; off <= 2; off <<= 1) {
            mx0 = fmaxf(mx0, __shfl_xor_sync(0xffffffffu, mx0, off));
            mx1 = fmaxf(mx1, __shfl_xor_sync(0xffffffffu, mx1, off));
        }
        float mn0 = fmaxf(m0, mx0 * 0.125f);
        float mn1 = fmaxf(m1, mx1 * 0.125f);
        float cr0 = __expf(m0 - mn0);
        float cr1 = __expf(m1 - mn1);
        l0 *= cr0; l1 *= cr1;
        #pragma unroll
        for (int nf = 0; nf < 8; nf++) {
            o[nf][0] *= cr0; o[nf][1] *= cr0;
            o[nf][2] *= cr1; o[nf][3] *= cr1;
        }
        float rs0 = 0.f, rs1 = 0.f;
        #pragma unroll
        for (int nf = 0; nf < 8; nf++) {
            float p0 = __expf(sc[nf][0] * 0.125f - mn0);
            float p1 = __expf(sc[nf][1] * 0.125f - mn0);
            float p2 = __expf(sc[nf][2] * 0.125f - mn1);
            float p3 = __expf(sc[nf][3] * 0.125f - mn1);
            rs0 += p0 + p1;  rs1 += p2 + p3;
            sc[nf][0] = __uint_as_float(f2tf(p0));
            sc[nf][1] = __uint_as_float(f2tf(p1));
            sc[nf][2] = __uint_as_float(f2tf(p2));
            sc[nf][3] = __uint_as_float(f2tf(p3));
        }
        #pragma unroll
        for (int off = 1; off <= 2; off <<= 1) {
            rs0 += __shfl_xor_sync(0xffffffffu, rs0, off);
            rs1 += __shfl_xor_sync(0xffffffffu, rs1, off);
        }
        l0 += rs0; l1 += rs1; m0 = mn0; m1 = mn1;

        int srcA = (g << 2) + (tg >> 1);
        int srcB = srcA + 2;
        bool odd = tg & 1;
        #pragma unroll
        for (int kf = 0; kf < 8; kf++) {
            float u0 = __shfl_sync(0xffffffffu, sc[kf][0], srcA);
            float u1 = __shfl_sync(0xffffffffu, sc[kf][1], srcA);
            float u2 = __shfl_sync(0xffffffffu, sc[kf][2], srcA);
            float u3 = __shfl_sync(0xffffffffu, sc[kf][3], srcA);
            float w0 = __shfl_sync(0xffffffffu, sc[kf][0], srcB);
            float w1 = __shfl_sync(0xffffffffu, sc[kf][1], srcB);
            float w2 = __shfl_sync(0xffffffffu, sc[kf][2], srcB);
            float w3 = __shfl_sync(0xffffffffu, sc[kf][3], srcB);
            uint32_t a[4];
            a[0] = __float_as_uint(odd ? u1 : u0);
            a[1] = __float_as_uint(odd ? u3 : u2);
            a[2] = __float_as_uint(odd ? w1 : w0);
            a[3] = __float_as_uint(odd ? w3 : w2);
            #pragma unroll
            for (int nf = 0; nf < 8; nf++) {
                uint32_t b[2];
                b[0] = Vu[(s * KT + kf * 8 + tg)     * SV + nf * 8 + g];
                b[1] = Vu[(s * KT + kf * 8 + tg + 4) * SV + nf * 8 + g];
                mma_tf32(o[nf], a, b);
            }
        }
        __syncthreads();
    }

    float inv0 = 1.f / l0, inv1 = 1.f / l1;
    #pragma unroll
    for (int nf = 0; nf < 8; nf++) {
        int c = nf * 8 + tg * 2;
        *(float2*)(Og + (long)(r0 + g)     * CDH + c) = make_float2(o[nf][0] * inv0, o[nf][1] * inv0);
        *(float2*)(Og + (long)(r0 + g + 8) * CDH + c) = make_float2(o[nf][2] * inv1, o[nf][3] * inv1);
    }
}
constexpr int SM_FLASH = (128 * 68 + 2 * 64 * 68 + 2 * 64 * 72) * 4;  // 106496

// ---------------- pack adj+smask into 2-bit codes ----------------
__global__ void pack_codes(const int* __restrict__ adj, const int* __restrict__ smask,
                           uint8_t* __restrict__ codes)
{
    long i = (long)blockIdx.x * 256 + threadIdx.x;    // over total/4
    int4 a = ((const int4*)adj)[i];
    int4 s = ((const int4*)smask)[i];
    uchar4 c;
    c.x = (uint8_t)(((a.x > 0) ? 2 : 0) | (s.x & 1));
    c.y = (uint8_t)(((a.y > 0) ? 2 : 0) | (s.y & 1));
    c.z = (uint8_t)(((a.z > 0) ? 2 : 0) | (s.z & 1));
    c.w = (uint8_t)(((a.w > 0) ? 2 : 0) | (s.w & 1));
    ((uchar4*)codes)[i] = c;
}

// ---------------- fused GAT attention: e-scores + masked softmax + P@h + elu ----------------
// grid (4 n-quarters, 8 i-blocks, 8 batches); 8 warps x 16 rows; j-tiles of 64.
constexpr int G_HS = 72;                      // h-tile smem stride (floats)
constexpr int G_CS = 80;                      // codes row stride (bytes)
constexpr int SM_GATT = (2 * 64 * G_HS + CN) * 4 + 2 * 128 * G_CS;  // 61440
__global__ void __launch_bounds__(256, 2) gatt_kernel(
    const float* __restrict__ e1, const float* __restrict__ e2,
    const float* __restrict__ rsc, const uint8_t* __restrict__ codes,
    const float* __restrict__ h, float* __restrict__ Agg)
{
    constexpr int JT = 64;
    extern __shared__ float sm[];
    float* Hs  = sm;                               // 2 * 64 * G_HS floats
    float* e2s = Hs + 2 * JT * G_HS;               // 1024 floats
    uint8_t* Cs = (uint8_t*)(e2s + CN);            // 2 * 128 * G_CS bytes
    uint32_t Hs_b = (uint32_t)__cvta_generic_to_shared(Hs);
    uint32_t Cs_b = (uint32_t)__cvta_generic_to_shared(Cs);

    int nq = blockIdx.x, ib = blockIdx.y, b = blockIdx.z;
    const float*   hB   = h + (long)b * CN * CHID + nq * 64;
    const uint8_t* cB   = codes + ((long)b * CN + ib * 128) * CN;
    const float*   e2B  = e2 + (long)b * CN;
    float*         AggB = Agg + ((long)b * CN + ib * 128) * CHID + nq * 64;

    int tid = threadIdx.x, warp = tid >> 5, lane = tid & 31;
    int g = lane >> 2, tg = lane & 3;
    int r0 = warp * 16;

    auto load_jt = [&](int t, int s) {
        // h tile: 64 j-rows x 64 cols
        #pragma unroll
        for (int i = 0; i < 4; i++) {
            int f = tid + i * 256;
            int r = f >> 4, c4 = (f & 15) * 4;
            cpasync16(Hs_b + (uint32_t)(((s * JT + r) * G_HS + c4) * 4),
                      hB + (long)(t * JT + r) * CHID + c4);
        }
        // codes tile: 128 i-rows x 64 bytes (row stride G_CS in smem)
        #pragma unroll
        for (int i = 0; i < 2; i++) {
            int f = tid + i * 256;
            int r = f >> 2, c16 = (f & 3) * 16;
            cpasync16(Cs_b + (uint32_t)(s * 128 * G_CS + r * G_CS + c16),
                      cB + (long)r * CN + t * JT + c16);
        }
        cpcommit();
    };
    load_jt(0, 0);

    // full e2 row -> smem (plain loads)
    #pragma unroll
    for (int i = 0; i < 1; i++) {
        ((float4*)e2s)[tid] = ((const float4*)e2B)[tid];   // 256 threads * 4 = 1024
    }
    float e1v0 = e1[(long)b * CN + ib * 128 + r0 + g];
    float e1v1 = e1[(long)b * CN + ib * 128 + r0 + g + 8];
    float rA = rsc[0], rB2 = rsc[1];

    float m0 = -3.4e38f, m1 = -3.4e38f, l0 = 0.f, l1 = 0.f;
    float o[8][4];
    #pragma unroll
    for (int nf = 0; nf < 8; nf++)
        #pragma unroll
        for (int q = 0; q < 4; q++) o[nf][q] = 0.f;

    for (int t = 0; t < 16; t++) {
        int s = t & 1;
        if (t < 15) load_jt(t + 1, s ^ 1);
        if (t < 15) cpwait1(); else cpwait0();
        __syncthreads();

        // e-scores straight into C-fragment layout
        float sc[8][4];
        #pragma unroll
        for (int nf = 0; nf < 8; nf++) {
            int lc = nf * 8 + tg * 2;
            float eA = e2s[t * JT + lc];
            float eB = e2s[t * JT + lc + 1];
            uint32_t c0 = *(const uint16_t*)&Cs[s * 128 * G_CS + (r0 + g) * G_CS + lc];
            uint32_t c1 = *(const uint16_t*)&Cs[s * 128 * G_CS + (r0 + g + 8) * G_CS + lc];
            float v;
            v = e1v0 + eA + ((c0 & 1u)   ? rB2 : rA); v = v >= 0.f ? v : ALPHAF * v; sc[nf][0] = (c0 & 2u)   ? v : NEGF;
            v = e1v0 + eB + ((c0 & 256u) ? rB2 : rA); v = v >= 0.f ? v : ALPHAF * v; sc[nf][1] = (c0 & 512u) ? v : NEGF;
            v = e1v1 + eA + ((c1 & 1u)   ? rB2 : rA); v = v >= 0.f ? v : ALPHAF * v; sc[nf][2] = (c1 & 2u)   ? v : NEGF;
            v = e1v1 + eB + ((c1 & 256u) ? rB2 : rA); v = v >= 0.f ? v : ALPHAF * v; sc[nf][3] = (c1 & 512u) ? v : NEGF;
        }

        // online softmax (no scale)
        float mx0 = -3.4e38f, mx1 = -3.4e38f;
        #pragma unroll
        for (int nf = 0; nf < 8; nf++) {
            mx0 = fmaxf(mx0, fmaxf(sc[nf][0], sc[nf][1]));
            mx1 = fmaxf(mx1, fmaxf(sc[nf][2], sc[nf][3]));
        }
        #pragma unroll
        for (int off = 1; off <= 2; off <<= 1) {
            mx0 = fmaxf(mx0, __shfl_xor_sync(0xffffffffu, mx0, off));
            mx1 = fmaxf(mx1, __shfl_xor_sync(0xffffffffu, mx1, off));
        }
        float mn0 = fmaxf(m0, mx0);
        float mn1 = fmaxf(m1, mx1);
        float cr0 = __expf(m0 - mn0);
        float cr1 = __expf(m1 - mn1);
        l0 *= cr0; l1 *= cr1;
        #pragma unroll
        for (int nf = 0; nf < 8; nf++) {
            o[nf][0] *= cr0; o[nf][1] *= cr0;
            o[nf][2] *= cr1; o[nf][3] *= cr1;
        }
        float rs0 = 0.f, rs1 = 0.f;
        #pragma unroll
        for (int nf = 0; nf < 8; nf++) {
            float p0 = __expf(sc[nf][0] - mn0);
            float p1 = __expf(sc[nf][1] - mn0);
            float p2 = __expf(sc[nf][2] - mn1);
            float p3 = __expf(sc[nf][3] - mn1);
            rs0 += p0 + p1;  rs1 += p2 + p3;
            sc[nf][0] = __uint_as_float(f2tf(p0));
            sc[nf][1] = __uint_as_float(f2tf(p1));
            sc[nf][2] = __uint_as_float(f2tf(p2));
            sc[nf][3] = __uint_as_float(f2tf(p3));
        }
        #pragma unroll
        for (int off = 1; off <= 2; off <<= 1) {
            rs0 += __shfl_xor_sync(0xffffffffu, rs0, off);
            rs1 += __shfl_xor_sync(0xffffffffu, rs1, off);
        }
        l0 += rs0; l1 += rs1; m0 = mn0; m1 = mn1;

        // O += P @ h  (P A-frags via intra-quad shuffles, h B-frags from smem)
        int srcA = (g << 2) + (tg >> 1);
        int srcB = srcA + 2;
        bool odd = tg & 1;
        #pragma unroll
        for (int kf = 0; kf < 8; kf++) {
            float u0 = __shfl_sync(0xffffffffu, sc[kf][0], srcA);
            float u1 = __shfl_sync(0xffffffffu, sc[kf][1], srcA);
            float u2 = __shfl_sync(0xffffffffu, sc[kf][2], srcA);
            float u3 = __shfl_sync(0xffffffffu, sc[kf][3], srcA);
            float w0 = __shfl_sync(0xffffffffu, sc[kf][0], srcB);
            float w1 = __shfl_sync(0xffffffffu, sc[kf][1], srcB);
            float w2 = __shfl_sync(0xffffffffu, sc[kf][2], srcB);
            float w3 = __shfl_sync(0xffffffffu, sc[kf][3], srcB);
            uint32_t a[4];
            a[0] = __float_as_uint(odd ? u1 : u0);
            a[1] = __float_as_uint(odd ? u3 : u2);
            a[2] = __float_as_uint(odd ? w1 : w0);
            a[3] = __float_as_uint(odd ? w3 : w2);
            #pragma unroll
            for (int nf = 0; nf < 8; nf++) {
                uint32_t bb[2];
                bb[0] = f2tf(Hs[(s * JT + kf * 8 + tg)     * G_HS + nf * 8 + g]);
                bb[1] = f2tf(Hs[(s * JT + kf * 8 + tg + 4) * G_HS + nf * 8 + g]);
                mma_tf32(o[nf], a, bb);
            }
        }
        __syncthreads();
    }

    float inv0 = 1.f / l0, inv1 = 1.f / l1;
    #pragma unroll
    for (int nf = 0; nf < 8; nf++) {
        int c = nf * 8 + tg * 2;
        float v0 = o[nf][0] * inv0, v1 = o[nf][1] * inv0;
        float v2 = o[nf][2] * inv1, v3 = o[nf][3] * inv1;
        v0 = v0 > 0.f ? v0 : expm1f(v0);
        v1 = v1 > 0.f ? v1 : expm1f(v1);
        v2 = v2 > 0.f ? v2 : expm1f(v2);
        v3 = v3 > 0.f ? v3 : expm1f(v3);
        *(float2*)(AggB + (long)(r0 + g)     * CHID + c) = make_float2(v0, v1);
        *(float2*)(AggB + (long)(r0 + g + 8) * CHID + c) = make_float2(v2, v3);
    }
}

// ---------------- fp32 tiled SGEMM (fc2 only) ----------------
template<int ACT>
__global__ void sgemm(const float* __restrict__ A, const float* __restrict__ Bm,
                      const float* __restrict__ bias, float* __restrict__ C,
                      int M, int N, int K)
{
    __shared__ float As[16][68];
    __shared__ float Bs[16][68];
    int tx = threadIdx.x;
    int tr = tx >> 4, tc = tx & 15;
    int row0 = blockIdx.y * 64, col0 = blockIdx.x * 64;

    float acc[4][4] = {};
    for (int k0 = 0; k0 < K; k0 += 16) {
        #pragma unroll
        for (int i = 0; i < 4; i++) {
            int idx = tx * 4 + i;
            int m = idx >> 4, k = idx & 15;
            int gr = row0 + m;
            As[k][m] = (gr < M) ? A[(long)gr * K + k0 + k] : 0.f;
        }
        #pragma unroll
        for (int i = 0; i < 4; i++) {
            int idx = tx * 4 + i;
            int k = idx >> 6, n = idx & 63;
            int gn = col0 + n;
            Bs[k][n] = (gn < N) ? Bm[(long)(k0 + k) * N + gn] : 0.f;
        }
        __syncthreads();
        #pragma unroll
        for (int k = 0; k < 16; k++) {
            float a[4], b[4];
            #pragma unroll
            for (int i = 0; i < 4; i++) a[i] = As[k][tr * 4 + i];
            #pragma unroll
            for (int j = 0; j < 4; j++) b[j] = Bs[k][tc * 4 + j];
            #pragma unroll
            for (int i = 0; i < 4; i++)
                #pragma unroll
                for (int j = 0; j < 4; j++)
                    acc[i][j] = fmaf(a[i], b[j], acc[i][j]);
        }
        __syncthreads();
    }
    #pragma unroll
    for (int i = 0; i < 4; i++) {
        int gr = row0 + tr * 4 + i;
        if (gr >= M) continue;
        #pragma unroll
        for (int j = 0; j < 4; j++) {
            int gn = col0 + tc * 4 + j;
            if (gn >= N) continue;
            float v = acc[i][j];
            if (bias) v += bias[gn];
            if (ACT == 1) v = v > 0.f ? v : 0.f;
            C[(long)gr * N + gn] = v;
        }
    }
}

// ---------------- logits: warp per row, N=7 ----------------
__global__ void logits_kernel(const float* __restrict__ H, const float* __restrict__ W,
                              const float* __restrict__ bb, float* __restrict__ out)
{
    int warp = threadIdx.x >> 5, lane = threadIdx.x & 31;
    int row = blockIdx.x * 8 + warp;
    float hv[8];
    #pragma unroll
    for (int j = 0; j < 8; j++) hv[j] = H[(long)row * CHID + j * 32 + lane];
    float acc[CNC];
    #pragma unroll
    for (int c = 0; c < CNC; c++) {
        float a = 0.f;
        #pragma unroll
        for (int j = 0; j < 8; j++) a = fmaf(hv[j], W[(j * 32 + lane) * CNC + c], a);
        acc[c] = a;
    }
    #pragma unroll
    for (int c = 0; c < CNC; c++)
        #pragma unroll
        for (int off = 16; off > 0; off >>= 1)
            acc[c] += __shfl_xor_sync(0xffffffffu, acc[c], off);
    if (lane < CNC) out[(long)row * CNC + lane] = acc[lane] + bb[lane];
}

// ---------------- P_l_1 ----------------
__global__ void pl1_kernel(const float* __restrict__ sadj, const float* __restrict__ P,
                           float* __restrict__ out)
{
    long idx = (long)blockIdx.x * 256 + threadIdx.x;
    int d = idx & (CHID - 1);
    int n = (idx >> 8) & (CN - 1);
    int b = (int)(idx >> 18);
    const float* sa = sadj + (long)b * CM * CN + n;
    const float* Pb = P + (long)b * CM * CHID + d;
    float acc = 0.f;
    #pragma unroll
    for (int m = 0; m < CM; m++) acc = fmaf(sa[m * CN], Pb[m * CHID], acc);
    out[idx] = acc;
}

// ---------------- e1/e2 dots: warp per row ----------------
__global__ void dots_kernel(const float* __restrict__ h, const float* __restrict__ a1,
                            const float* __restrict__ a2,
                            float* __restrict__ e1, float* __restrict__ e2)
{
    int warp = threadIdx.x >> 5, lane = threadIdx.x & 31;
    int row = blockIdx.x * 8 + warp;
    float s1 = 0.f, s2 = 0.f;
    #pragma unroll
    for (int j = 0; j < 8; j++) {
        int c = j * 32 + lane;
        float v = h[(long)row * CHID + c];
        s1 = fmaf(v, a1[c], s1);
        s2 = fmaf(v, a2[c], s2);
    }
    #pragma unroll
    for (int off = 16; off > 0; off >>= 1) {
        s1 += __shfl_xor_sync(0xffffffffu, s1, off);
        s2 += __shfl_xor_sync(0xffffffffu, s2, off);
    }
    if (lane == 0) { e1[row] = s1; e2[row] = s2; }
}

// ---------------- rel_sc ----------------
__global__ void relsc_kernel(const float* __restrict__ rel, const float* __restrict__ a3,
                             float* __restrict__ out)
{
    __shared__ float s[256];
    int r = blockIdx.x, t = threadIdx.x;
    s[t] = rel[r * CHID + t] * a3[t];
    __syncthreads();
    for (int o = 128; o > 0; o >>= 1) {
        if (t < o) s[t] += s[t + o];
        __syncthreads();
    }
    if (t == 0) out[r] = s[0];
}

// ---------------- LayerNorm: warp per row ----------------
__global__ void ln_kernel(const float* __restrict__ T, const float* __restrict__ Hold,
                          const float* __restrict__ g, const float* __restrict__ bb,
                          float* __restrict__ out)
{
    int warp = threadIdx.x >> 5, lane = threadIdx.x & 31;
    int row = blockIdx.x * 8 + warp;
    long base = (long)row * CHID;
    float v[8];
    float s = 0.f;
    #pragma unroll
    for (int j = 0; j < 8; j++) {
        int c = j * 32 + lane;
        v[j] = T[base + c] + Hold[base + c];
        s += v[j];
    }
    #pragma unroll
    for (int off = 16; off > 0; off >>= 1) s += __shfl_xor_sync(0xffffffffu, s, off);
    float mu = s * (1.f / CHID);
    float q = 0.f;
    #pragma unroll
    for (int j = 0; j < 8; j++) { v[j] -= mu; q = fmaf(v[j], v[j], q); }
    #pragma unroll
    for (int off = 16; off > 0; off >>= 1) q += __shfl_xor_sync(0xffffffffu, q, off);
    float rstd = rsqrtf(q * (1.f / CHID) + 1e-5f);
    #pragma unroll
    for (int j = 0; j < 8; j++) {
        int c = j * 32 + lane;
        out[base + c] = v[j] * rstd * g[c] + bb[c];
    }
}

// ---------------- fused P_agg + GRU3d ----------------
__global__ void pagggru_kernel(const float* __restrict__ sadj, const float* __restrict__ Hcur,
                               float* __restrict__ P,
                               const float* __restrict__ wz, const float* __restrict__ uz,
                               const float* __restrict__ wr, const float* __restrict__ ur,
                               const float* __restrict__ w,  const float* __restrict__ u)
{
    __shared__ float sp[CHID], sq[CHID];
    int bm = blockIdx.x;                   // 0..63
    int b = bm >> 3;
    int c = threadIdx.x;
    const float* sa = sadj + (long)bm * CN;
    const float* Hb = Hcur + (long)b * CN * CHID + c;
    float acc = 0.f;
    #pragma unroll 4
    for (int n = 0; n < CN; n++) acc = fmaf(sa[n], Hb[(long)n * CHID], acc);
    sq[c] = acc;
    sp[c] = P[(long)bm * CHID + c];
    __syncthreads();
    float az = 0, bz = 0, ar = 0, br = 0, aw = 0, bw = 0;
    #pragma unroll 4
    for (int k = 0; k < CHID; k++) {
        float pk = sp[k], qk = sq[k];
        az = fmaf(pk, wz[k * CHID + c], az); bz = fmaf(qk, uz[k * CHID + c], bz);
        ar = fmaf(pk, wr[k * CHID + c], ar); br = fmaf(qk, ur[k * CHID + c], br);
        aw = fmaf(pk, w [k * CHID + c], aw); bw = fmaf(qk, u [k * CHID + c], bw);
    }
    float z  = 1.f / (1.f + expf(-(az + bz)));
    float rr = 1.f / (1.f + expf(-(ar + br)));
    float hh = tanhf(aw + rr * bw);
    P[(long)bm * CHID + c] = (1.f - z) * sp[c] + z * hh;
}

// ---------------- p_sim ----------------
__global__ void psim_kernel(const float* __restrict__ P, float* __restrict__ outp, int tail)
{
    __shared__ float red[64];
    int t = threadIdx.x;
    int b = t >> 3, m = t & 7;
    const float* Pb = P + (long)b * CM * CHID;
    float s = 0.f;
    for (int k2 = 0; k2 < CM; k2++) {
        if (k2 == m) continue;
        float d = 0.f;
        for (int dd = 0; dd < CHID; dd++)
            d = fmaf(Pb[m * CHID + dd], Pb[k2 * CHID + dd], d);
        s += d;
    }
    red[t] = s; __syncthreads();
    if ((t & 7) < 4) red[t] += red[t + 4]; __syncthreads();
    if ((t & 7) < 2) red[t] += red[t + 2]; __syncthreads();
    if ((t & 7) < 1) red[t] += red[t + 1]; __syncthreads();
    if (tail >= CB) {
        if (t < CB) outp[t] = red[t * 8] / (float)(CM * CM);
    } else {
        if (t == 0) {
            float tot = 0.f;
            for (int b2 = 0; b2 < CB; b2++) tot += red[b2 * 8];
            outp[0] = tot / (float)(CB * CM * CM);
        }
    }
}

// ---------------- host orchestration ----------------
extern "C" void kernel_launch(void* const* d_in, const int* in_sizes, int n_in,
                              void* d_out, int out_size)
{
    const float* x     = (const float*)d_in[0];
    const int*   adj   = (const int*)  d_in[1];
    const int*   smask = (const int*)  d_in[2];
    const float* sf    = (const float*)d_in[3];
    const float* sadj  = (const float*)d_in[4];
    const float* fc1w  = (const float*)d_in[6];
    const float* fc1b  = (const float*)d_in[7];
    const float* fc2w  = (const float*)d_in[8];
    const float* fc2b  = (const float*)d_in[9];
    const float* gatW  = (const float*)d_in[10];
    const float* gata  = (const float*)d_in[11];
    const float* rel   = (const float*)d_in[12];
    const float* gwz   = (const float*)d_in[13];
    const float* guz   = (const float*)d_in[14];
    const float* gwr   = (const float*)d_in[15];
    const float* gur   = (const float*)d_in[16];
    const float* gw    = (const float*)d_in[17];
    const float* gu    = (const float*)d_in[18];
    const float* wv    = (const float*)d_in[19];
    const float* bv    = (const float*)d_in[20];
    const float* wk    = (const float*)d_in[21];
    const float* bk    = (const float*)d_in[22];
    const float* wq    = (const float*)d_in[23];
    const float* bq    = (const float*)d_in[24];
    const float* wo    = (const float*)d_in[25];
    const float* bo    = (const float*)d_in[26];
    const float* lng   = (const float*)d_in[27];
    const float* lnb   = (const float*)d_in[28];
    const float* outw  = (const float*)d_in[29];
    const float* outb  = (const float*)d_in[30];
    float* out = (float*)d_out;

    float *H, *Hn, *P, *Pl1, *hb, *Agg, *Qb, *Kb, *Vb, *ctx, *Tb, *e1, *e2, *rsc;
    uint8_t* codes;
    cudaGetSymbolAddress((void**)&H,    g_H);
    cudaGetSymbolAddress((void**)&Hn,   g_Hn);
    cudaGetSymbolAddress((void**)&P,    g_P);
    cudaGetSymbolAddress((void**)&Pl1,  g_Pl1);
    cudaGetSymbolAddress((void**)&hb,   g_h);
    cudaGetSymbolAddress((void**)&Agg,  g_Agg);
    cudaGetSymbolAddress((void**)&Qb,   g_Q);
    cudaGetSymbolAddress((void**)&Kb,   g_K);
    cudaGetSymbolAddress((void**)&Vb,   g_V);
    cudaGetSymbolAddress((void**)&ctx,  g_ctx);
    cudaGetSymbolAddress((void**)&Tb,   g_T);
    cudaGetSymbolAddress((void**)&codes, g_codes);
    cudaGetSymbolAddress((void**)&e1,   g_e1);
    cudaGetSymbolAddress((void**)&e2,   g_e2);
    cudaGetSymbolAddress((void**)&rsc,  g_rsc);

    cudaFuncSetAttribute(tgemm<0>, cudaFuncAttributeMaxDynamicSharedMemorySize, SM_TG);
    cudaFuncSetAttribute(tgemm<1>, cudaFuncAttributeMaxDynamicSharedMemorySize, SM_TG);
    cudaFuncSetAttribute(tgemm_pair, cudaFuncAttributeMaxDynamicSharedMemorySize, SM_TG);
    cudaFuncSetAttribute(flash_kernel, cudaFuncAttributeMaxDynamicSharedMemorySize, SM_FLASH);
    cudaFuncSetAttribute(gatt_kernel, cudaFuncAttributeMaxDynamicSharedMemorySize, SM_GATT);

    dim3 blk(256);
    const int BN = CB * CN;                          // 8192
    const long HH = (long)CHID * CHID;               // 65536

    // pack masks once (8.4M codes)
    pack_codes<<<(int)((long)CB * CN * CN / 4 / 256), blk>>>(adj, smask, codes);
    // H = relu(x @ fc1_w + b)
    tgemm<1><<<dim3(2, 64, 1), blk, SM_TG>>>(x, fc1w, fc1b, H, BN, CHID, CDIN, 0, 0, 0, 1.f);
    // P = relu(s_feature @ fc2_w + b)
    sgemm<1><<<dim3(4, 1, 1), blk>>>(sf, fc2w, fc2b, P, CB * CM, CHID, CDIN);

    for (int l = 0; l < CL; l++) {
        float* cur = l ? Hn : H;
        float* nxt = l ? H : Hn;

        // P_l_1 = s_adj^T @ P
        pl1_kernel<<<BN * CHID / 256, blk>>>(sadj, P, Pl1);

        // paired: h = cur @ gat_W[l] (fp32) ; V = cur @ wv + bv (tf32 bits)
        {
            G2 a;
            a.A[0] = cur;           a.A[1] = cur;
            a.B[0] = gatW + l * HH; a.B[1] = wv + l * HH;
            a.bias[0] = nullptr;    a.bias[1] = bv + l * CHID;
            a.C[0] = hb;            a.C[1] = Vb;
            a.act[0] = 0;           a.act[1] = 3;
            tgemm_pair<<<dim3(2, 64, 2), blk, SM_TG>>>(a, BN, CHID, CHID);
        }
        // edge-score ingredients
        dots_kernel<<<BN / 8, blk>>>(hb, gata + l * 3 * CHID, gata + l * 3 * CHID + CHID, e1, e2);
        relsc_kernel<<<2, blk>>>(rel + l * 2 * CHID, gata + l * 3 * CHID + 2 * CHID, rsc);
        // fused GAT attention -> Agg (elu)
        gatt_kernel<<<dim3(4, 8, CB), blk, SM_GATT>>>(e1, e2, rsc, codes, hb, Agg);
        // paired: K = Pl1 @ wk + bk ; Q = Agg @ wq + bq   (both tf32 bits)
        {
            G2 a;
            a.A[0] = Pl1;           a.A[1] = Agg;
            a.B[0] = wk + l * HH;   a.B[1] = wq + l * HH;
            a.bias[0] = bk + l * CHID; a.bias[1] = bq + l * CHID;
            a.C[0] = Kb;            a.C[1] = Qb;
            a.act[0] = 3;           a.act[1] = 3;
            tgemm_pair<<<dim3(2, 64, 2), blk, SM_TG>>>(a, BN, CHID, CHID);
        }
        // fused MHA
        flash_kernel<<<dim3(8, 32), blk, SM_FLASH>>>(Qb, Kb, Vb, ctx);
        // T = ctx @ wo + bo ;  H_new = LN(T + H)
        tgemm<0><<<dim3(2, 64, 1), blk, SM_TG>>>(ctx, wo + l * HH, bo + l * CHID, Tb,
                                                 BN, CHID, CHID, 0, 0, 0, 1.f);
        ln_kernel<<<BN / 8, blk>>>(Tb, cur, lng + l * CHID, lnb + l * CHID, nxt);

        // fused P_agg + GRU (uses pre-update H)
        pagggru_kernel<<<CB * CM, blk>>>(sadj, cur, P,
                                         gwz + l * HH, guz + l * HH,
                                         gwr + l * HH, gur + l * HH,
                                         gw + l * HH,  gu + l * HH);
    }

    // logits
    logits_kernel<<<BN / 8, blk>>>(H, outw, outb, out);
    // p_sim
    psim_kernel<<<1, 64>>>(P, out + (long)BN * CNC, out_size - BN * CNC);
}

// round 10
// speedup vs baseline: 1.1408x; 1.0791x over previous
#include <cuda_runtime.h>
#include <cuda_fp16.h>
#include <math.h>
#include <stdint.h>

// ---------------- problem constants ----------------
constexpr int CB   = 8;
constexpr int CN   = 1024;
constexpr int CM   = 8;
constexpr int CDIN = 1024;
constexpr int CHID = 256;
constexpr int CL   = 2;
constexpr int CNC  = 7;
constexpr int CDH  = 64;
#define NEGF  (-9e15f)
#define ALPHAF 0.1f

// ---------------- scratch ----------------
__device__ float  g_H   [CB*CN*CHID];
__device__ float  g_Hn  [CB*CN*CHID];
__device__ float  g_P   [CB*CM*CHID];
__device__ float  g_Pl1 [CB*CN*CHID];
__device__ float  g_Agg [CB*CN*CHID];
__device__ float  g_ctx [CB*CN*CHID];
__device__ float  g_T   [CB*CN*CHID];
__device__ __half g_Qh  [CB*CN*CHID];
__device__ __half g_Kh  [CB*CN*CHID];
__device__ __half g_VT  [CB*CN*CHID];   // [bh][d][j]
__device__ __half g_hT  [CB*CN*CHID];   // [b][c][n]
__device__ uint8_t g_codes[(long)CB*CN*CN];
__device__ float  g_e1  [CB*CN];
__device__ float  g_e2  [CB*CN];
__device__ float  g_rsc [2];

// ---------------- helpers ----------------
__device__ __forceinline__ uint32_t f2tf(float f) {
    uint32_t u;
    asm("cvt.rna.tf32.f32 %0, %1;" : "=r"(u) : "f"(f));
    return u;
}
__device__ __forceinline__ void mma_tf32(float c[4], const uint32_t a[4], const uint32_t b[2]) {
    asm volatile(
        "mma.sync.aligned.m16n8k8.row.col.f32.tf32.tf32.f32 "
        "{%0,%1,%2,%3}, {%4,%5,%6,%7}, {%8,%9}, {%0,%1,%2,%3};\n"
        : "+f"(c[0]), "+f"(c[1]), "+f"(c[2]), "+f"(c[3])
        : "r"(a[0]), "r"(a[1]), "r"(a[2]), "r"(a[3]), "r"(b[0]), "r"(b[1]));
}
__device__ __forceinline__ void mma_f16(float c[4], const uint32_t a[4], const uint32_t b[2]) {
    asm volatile(
        "mma.sync.aligned.m16n8k16.row.col.f32.f16.f16.f32 "
        "{%0,%1,%2,%3}, {%4,%5,%6,%7}, {%8,%9}, {%0,%1,%2,%3};\n"
        : "+f"(c[0]), "+f"(c[1]), "+f"(c[2]), "+f"(c[3])
        : "r"(a[0]), "r"(a[1]), "r"(a[2]), "r"(a[3]), "r"(b[0]), "r"(b[1]));
}
__device__ __forceinline__ uint32_t pkh2(float x, float y) {
    __half2 h = __floats2half2_rn(x, y);
    return *(uint32_t*)&h;
}
__device__ __forceinline__ void cpasync16(uint32_t saddr, const void* gptr) {
    asm volatile("cp.async.cg.shared.global [%0], [%1], 16;\n" :: "r"(saddr), "l"(gptr));
}
__device__ __forceinline__ void cpcommit() { asm volatile("cp.async.commit_group;\n"); }
__device__ __forceinline__ void cpwait0()  { asm volatile("cp.async.wait_group 0;\n"); }
__device__ __forceinline__ void cpwait1()  { asm volatile("cp.async.wait_group 1;\n"); }

// ================= core GEMM tile (128x128, KS=32, 2-stage, 2 CTAs/SM) =================
struct TileCtx {
    float *As, *Bs;
    uint32_t As_b, Bs_b;
    const float *Ag, *Bg;
    int K, N;
    int tid;
};
constexpr int T_strA = 36, T_strB = 132;
constexpr int T_AW = 128 * T_strA, T_BW = 32 * T_strB;
constexpr int SM_TG = (2 * (T_AW + T_BW)) * 4;   // 70656 bytes

__device__ __forceinline__ void tg_load_stage(TileCtx& c, int kt, int s) {
    int k0 = kt * 32;
    #pragma unroll
    for (int i = 0; i < 4; i++) {
        int f = c.tid + i * 256;
        int m = f >> 3, k4 = (f & 7) * 4;
        cpasync16(c.As_b + (uint32_t)(((s * 128 + m) * T_strA + k4) * 4),
                  c.Ag + (long)m * c.K + k0 + k4);
    }
    #pragma unroll
    for (int i = 0; i < 4; i++) {
        int f = c.tid + i * 256;
        int k = f >> 5, n4 = (f & 31) * 4;
        cpasync16(c.Bs_b + (uint32_t)(((s * 32 + k) * T_strB + n4) * 4),
                  c.Bg + (long)(k0 + k) * c.N + n4);
    }
    cpcommit();
}

// act: 0 none, 1 relu, 4 half row-major, 5 half batch-transpose, 6 half head-transpose
__device__ __forceinline__ void tg_body(
    TileCtx& c, const float* bias, float* C, int M, int N, int K,
    int row0, int col0, float scale, int act)
{
    int tid  = c.tid;
    int warp = tid >> 5, lane = tid & 31;
    int g = lane >> 2, tg = lane & 3;
    int mw = warp >> 2, nw = warp & 3;

    float acc[4][4][4];
    #pragma unroll
    for (int mi = 0; mi < 4; mi++)
        #pragma unroll
        for (int ni = 0; ni < 4; ni++)
            #pragma unroll
            for (int q = 0; q < 4; q++) acc[mi][ni][q] = 0.f;

    int nk = K / 32;
    tg_load_stage(c, 0, 0);

    for (int kt = 0; kt < nk; kt++) {
        cpwait0();
        __syncthreads();
        int s = kt & 1;
        if (kt + 1 < nk) tg_load_stage(c, kt + 1, s ^ 1);

        const float* Asb = c.As + s * T_AW;
        const float* Bsb = c.Bs + s * T_BW;
        #pragma unroll
        for (int ks = 0; ks < 32; ks += 8) {
            uint32_t a[4][4], b[4][2];
            #pragma unroll
            for (int mi = 0; mi < 4; mi++) {
                int mr = mw * 64 + mi * 16;
                a[mi][0] = f2tf(Asb[(mr + g)     * T_strA + ks + tg]);
                a[mi][1] = f2tf(Asb[(mr + g + 8) * T_strA + ks + tg]);
                a[mi][2] = f2tf(Asb[(mr + g)     * T_strA + ks + tg + 4]);
                a[mi][3] = f2tf(Asb[(mr + g + 8) * T_strA + ks + tg + 4]);
            }
            #pragma unroll
            for (int ni = 0; ni < 4; ni++) {
                int nc = nw * 32 + ni * 8;
                b[ni][0] = f2tf(Bsb[(ks + tg)     * T_strB + nc + g]);
                b[ni][1] = f2tf(Bsb[(ks + tg + 4) * T_strB + nc + g]);
            }
            #pragma unroll
            for (int mi = 0; mi < 4; mi++)
                #pragma unroll
                for (int ni = 0; ni < 4; ni++)
                    mma_tf32(acc[mi][ni], a[mi], b[ni]);
        }
    }

    #pragma unroll
    for (int mi = 0; mi < 4; mi++) {
        #pragma unroll
        for (int ni = 0; ni < 4; ni++) {
            int r = row0 + mw * 64 + mi * 16 + g;
            int cc0 = col0 + nw * 32 + ni * 8 + tg * 2;
            float b0 = bias ? bias[cc0] : 0.f;
            float b1 = bias ? bias[cc0 + 1] : 0.f;
            #pragma unroll
            for (int rr = 0; rr < 2; rr++) {
                int r_ = r + rr * 8;
                float v0 = acc[mi][ni][rr * 2 + 0] * scale + b0;
                float v1 = acc[mi][ni][rr * 2 + 1] * scale + b1;
                if (act == 0) {
                    *(float2*)(C + (long)r_ * N + cc0) = make_float2(v0, v1);
                } else if (act == 1) {
                    *(float2*)(C + (long)r_ * N + cc0) =
                        make_float2(fmaxf(v0, 0.f), fmaxf(v1, 0.f));
                } else if (act == 4) {
                    __half2 h = __floats2half2_rn(v0, v1);
                    *(__half2*)((__half*)C + (long)r_ * N + cc0) = h;
                } else if (act == 5) {          // hT: [b][c][n]
                    __half* CT = (__half*)C;
                    int b_ = r_ >> 10, j = r_ & 1023;
                    CT[((long)(b_ * CHID + cc0))     * CN + j] = __float2half_rn(v0);
                    CT[((long)(b_ * CHID + cc0 + 1)) * CN + j] = __float2half_rn(v1);
                } else {                        // 6: VT: [bh][d][j]
                    __half* CT = (__half*)C;
                    int bh = r_ >> 8;
                    int j = ((r_ & 255) << 2) | (cc0 >> 6);
                    int d = cc0 & 63;
                    long base = ((long)bh << 16) + ((long)d << 10) + j;
                    CT[base] = __float2half_rn(v0);
                    CT[base + 1024] = __float2half_rn(v1);   // d+1 (cc0 even, no 64-cross)
                }
            }
        }
    }
}

template<int ACT>
__global__ void __launch_bounds__(256, 2) tgemm(
    const float* __restrict__ A, const float* __restrict__ Bm,
    const float* __restrict__ bias, float* __restrict__ C,
    int M, int N, int K, long sA, long sB, long sC, float scale)
{
    extern __shared__ float smem[];
    int bz = blockIdx.z;
    TileCtx c;
    c.As = smem; c.Bs = smem + 2 * T_AW;
    c.As_b = (uint32_t)__cvta_generic_to_shared(c.As);
    c.Bs_b = (uint32_t)__cvta_generic_to_shared(c.Bs);
    c.K = K; c.N = N; c.tid = threadIdx.x;
    int row0 = blockIdx.y * 128, col0 = blockIdx.x * 128;
    c.Ag = A + (long)bz * sA + (long)row0 * K;
    c.Bg = Bm + (long)bz * sB + col0;
    tg_body(c, bias, C + (long)bz * sC, M, N, K, row0, col0, scale, ACT);
}

struct G2 { const float* A[2]; const float* B[2]; const float* bias[2]; float* C[2]; int act[2]; };
__global__ void __launch_bounds__(256, 2) tgemm_pair(G2 args, int M, int N, int K)
{
    extern __shared__ float smem[];
    int z = blockIdx.z;
    TileCtx c;
    c.As = smem; c.Bs = smem + 2 * T_AW;
    c.As_b = (uint32_t)__cvta_generic_to_shared(c.As);
    c.Bs_b = (uint32_t)__cvta_generic_to_shared(c.Bs);
    c.K = K; c.N = N; c.tid = threadIdx.x;
    int row0 = blockIdx.y * 128, col0 = blockIdx.x * 128;
    c.Ag = args.A[z] + (long)row0 * K;
    c.Bg = args.B[z] + col0;
    tg_body(c, args.bias[z], args.C[z], M, N, K, row0, col0, 1.f, args.act[z]);
}

// ---------------- fp16 flash attention, 64-row KV tiles ----------------
constexpr int F_ST = 72;   // half stride
constexpr int SM_FLASH = (128 * F_ST + 2 * 64 * F_ST + 2 * 64 * F_ST) * 2;  // 55296
__global__ void __launch_bounds__(256, 2) flash_kernel(
    const __half* __restrict__ Q, const __half* __restrict__ Kg_,
    const __half* __restrict__ Vt_, float* __restrict__ O)
{
    constexpr int KT = 64;
    extern __shared__ float smraw[];
    __half* Qs = (__half*)smraw;                 // 128*F_ST
    __half* Ks = Qs + 128 * F_ST;                // 2*64*F_ST
    __half* Vs = Ks + 2 * KT * F_ST;             // 2*64*F_ST
    uint32_t Qs_b = (uint32_t)__cvta_generic_to_shared(Qs);
    uint32_t Ks_b = (uint32_t)__cvta_generic_to_shared(Ks);
    uint32_t Vs_b = (uint32_t)__cvta_generic_to_shared(Vs);

    int bh = blockIdx.y;
    const __half* Qg = Q + (long)bh * CN * CDH + (long)blockIdx.x * 128 * CDH;
    const __half* Kg = Kg_ + (long)bh * CN * CDH;
    const __half* Vg = Vt_ + ((long)bh << 16);          // [d][j]
    float* Og = O + (long)bh * CN * CDH + (long)blockIdx.x * 128 * CDH;

    int tid = threadIdx.x, warp = tid >> 5, lane = tid & 31;
    int g = lane >> 2, tg = lane & 3;
    int r0 = warp * 16;

    // Q tile: 128 rows x 64 halves
    #pragma unroll
    for (int i = 0; i < 4; i++) {
        int f = tid + i * 256;
        int r = f >> 3, ch = f & 7;
        cpasync16(Qs_b + (uint32_t)((r * F_ST + ch * 8) * 2), Qg + r * CDH + ch * 8);
    }
    cpcommit();

    auto load_kv = [&](int t, int s) {
        const __half* Kt = Kg + t * KT * CDH;
        const __half* Vtb = Vg + t * KT;
        #pragma unroll
        for (int i = 0; i < 2; i++) {
            int f = tid + i * 256;
            int r = f >> 3, ch = f & 7;
            cpasync16(Ks_b + (uint32_t)(((s * KT + r) * F_ST + ch * 8) * 2),
                      Kt + r * CDH + ch * 8);
        }
        #pragma unroll
        for (int i = 0; i < 2; i++) {
            int f = tid + i * 256;
            int r = f >> 3, ch = f & 7;
            cpasync16(Vs_b + (uint32_t)(((s * KT + r) * F_ST + ch * 8) * 2),
                      Vtb + (long)r * CN + ch * 8);
        }
        cpcommit();
    };
    load_kv(0, 0);

    cpwait1();
    __syncthreads();

    uint32_t aq[4][4];
    #pragma unroll
    for (int kf = 0; kf < 4; kf++) {
        aq[kf][0] = *(uint32_t*)&Qs[(r0 + g)     * F_ST + kf * 16 + 2 * tg];
        aq[kf][1] = *(uint32_t*)&Qs[(r0 + g + 8) * F_ST + kf * 16 + 2 * tg];
        aq[kf][2] = *(uint32_t*)&Qs[(r0 + g)     * F_ST + kf * 16 + 2 * tg + 8];
        aq[kf][3] = *(uint32_t*)&Qs[(r0 + g + 8) * F_ST + kf * 16 + 2 * tg + 8];
    }

    float m0 = -3.4e38f, m1 = -3.4e38f, l0 = 0.f, l1 = 0.f;
    float o[8][4];
    #pragma unroll
    for (int nf = 0; nf < 8; nf++)
        #pragma unroll
        for (int q = 0; q < 4; q++) o[nf][q] = 0.f;

    for (int t = 0; t < 16; t++) {
        int s = t & 1;
        if (t < 15) load_kv(t + 1, s ^ 1);
        if (t < 15) cpwait1(); else cpwait0();
        __syncthreads();

        float sc[8][4];
        #pragma unroll
        for (int nf = 0; nf < 8; nf++)
            #pragma unroll
            for (int q = 0; q < 4; q++) sc[nf][q] = 0.f;
        #pragma unroll
        for (int kf = 0; kf < 4; kf++) {
            #pragma unroll
            for (int nf = 0; nf < 8; nf++) {
                uint32_t b[2];
                const __half* kr = &Ks[(s * KT + nf * 8 + g) * F_ST + kf * 16 + 2 * tg];
                b[0] = *(uint32_t*)kr;
                b[1] = *(uint32_t*)(kr + 8);
                mma_f16(sc[nf], aq[kf], b);
            }
        }

        float mx0 = -3.4e38f, mx1 = -3.4e38f;
        #pragma unroll
        for (int nf = 0; nf < 8; nf++) {
            mx0 = fmaxf(mx0, fmaxf(sc[nf][0], sc[nf][1]));
            mx1 = fmaxf(mx1, fmaxf(sc[nf][2], sc[nf][3]));
        }
        #pragma unroll
        for (int off = 1; off <= 2; off <<= 1) {
            mx0 = fmaxf(mx0, __shfl_xor_sync(0xffffffffu, mx0, off));
            mx1 = fmaxf(mx1, __shfl_xor_sync(0xffffffffu, mx1, off));
        }
        float mn0 = fmaxf(m0, mx0 * 0.125f);
        float mn1 = fmaxf(m1, mx1 * 0.125f);
        float cr0 = __expf(m0 - mn0);
        float cr1 = __expf(m1 - mn1);
        l0 *= cr0; l1 *= cr1;
        #pragma unroll
        for (int nf = 0; nf < 8; nf++) {
            o[nf][0] *= cr0; o[nf][1] *= cr0;
            o[nf][2] *= cr1; o[nf][3] *= cr1;
        }
        float rs0 = 0.f, rs1 = 0.f;
        #pragma unroll
        for (int nf = 0; nf < 8; nf++) {
            sc[nf][0] = __expf(sc[nf][0] * 0.125f - mn0);
            sc[nf][1] = __expf(sc[nf][1] * 0.125f - mn0);
            sc[nf][2] = __expf(sc[nf][2] * 0.125f - mn1);
            sc[nf][3] = __expf(sc[nf][3] * 0.125f - mn1);
            rs0 += sc[nf][0] + sc[nf][1];
            rs1 += sc[nf][2] + sc[nf][3];
        }
        #pragma unroll
        for (int off = 1; off <= 2; off <<= 1) {
            rs0 += __shfl_xor_sync(0xffffffffu, rs0, off);
            rs1 += __shfl_xor_sync(0xffffffffu, rs1, off);
        }
        l0 += rs0; l1 += rs1; m0 = mn0; m1 = mn1;

        // O += P @ V  (A from C-fragments, no shuffles)
        #pragma unroll
        for (int kf = 0; kf < 4; kf++) {
            uint32_t a[4];
            a[0] = pkh2(sc[2 * kf][0],     sc[2 * kf][1]);
            a[1] = pkh2(sc[2 * kf][2],     sc[2 * kf][3]);
            a[2] = pkh2(sc[2 * kf + 1][0], sc[2 * kf + 1][1]);
            a[3] = pkh2(sc[2 * kf + 1][2], sc[2 * kf + 1][3]);
            #pragma unroll
            for (int nf = 0; nf < 8; nf++) {
                uint32_t b[2];
                const __half* vr = &Vs[(s * KT + nf * 8 + g) * F_ST + kf * 16 + 2 * tg];
                b[0] = *(uint32_t*)vr;
                b[1] = *(uint32_t*)(vr + 8);
                mma_f16(o[nf], a, b);
            }
        }
        __syncthreads();
    }

    float inv0 = 1.f / l0, inv1 = 1.f / l1;
    #pragma unroll
    for (int nf = 0; nf < 8; nf++) {
        int c = nf * 8 + tg * 2;
        *(float2*)(Og + (long)(r0 + g)     * CDH + c) = make_float2(o[nf][0] * inv0, o[nf][1] * inv0);
        *(float2*)(Og + (long)(r0 + g + 8) * CDH + c) = make_float2(o[nf][2] * inv1, o[nf][3] * inv1);
    }
}

// ---------------- pack adj+smask ----------------
__global__ void pack_codes(const int* __restrict__ adj, const int* __restrict__ smask,
                           uint8_t* __restrict__ codes)
{
    long i = (long)blockIdx.x * 256 + threadIdx.x;
    int4 a = ((const int4*)adj)[i];
    int4 s = ((const int4*)smask)[i];
    uchar4 c;
    c.x = (uint8_t)(((a.x > 0) ? 2 : 0) | (s.x & 1));
    c.y = (uint8_t)(((a.y > 0) ? 2 : 0) | (s.y & 1));
    c.z = (uint8_t)(((a.z > 0) ? 2 : 0) | (s.z & 1));
    c.w = (uint8_t)(((a.w > 0) ? 2 : 0) | (s.w & 1));
    ((uchar4*)codes)[i] = c;
}

// ---------------- fused GAT attention (fp16 PV) ----------------
constexpr int G_CS = 80;
constexpr int SM_GATT = 2 * 64 * F_ST * 2 + CN * 4 + 2 * 128 * G_CS;  // 43008
__global__ void __launch_bounds__(256, 2) gatt_kernel(
    const float* __restrict__ e1, const float* __restrict__ e2,
    const float* __restrict__ rsc, const uint8_t* __restrict__ codes,
    const __half* __restrict__ hT, float* __restrict__ Agg)
{
    constexpr int JT = 64;
    extern __shared__ float smraw[];
    __half* Hs = (__half*)smraw;                   // 2*64*F_ST halves ([d][j])
    float* e2s = (float*)(Hs + 2 * JT * F_ST);     // 1024 floats
    uint8_t* Cs = (uint8_t*)(e2s + CN);            // 2*128*G_CS
    uint32_t Hs_b = (uint32_t)__cvta_generic_to_shared(Hs);
    uint32_t Cs_b = (uint32_t)__cvta_generic_to_shared(Cs);

    int nq = blockIdx.x, ib = blockIdx.y, b = blockIdx.z;
    const __half*  hB  = hT + ((long)(b * CHID + nq * 64)) * CN;     // rows d, cols j
    const uint8_t* cB  = codes + ((long)b * CN + ib * 128) * CN;
    const float*   e2B = e2 + (long)b * CN;
    float* AggB = Agg + ((long)b * CN + ib * 128) * CHID + nq * 64;

    int tid = threadIdx.x, warp = tid >> 5, lane = tid & 31;
    int g = lane >> 2, tg = lane & 3;
    int r0 = warp * 16;

    auto load_jt = [&](int t, int s) {
        // hT tile: 64 d-rows x 64 j halves
        #pragma unroll
        for (int i = 0; i < 2; i++) {
            int f = tid + i * 256;
            int r = f >> 3, ch = f & 7;
            cpasync16(Hs_b + (uint32_t)(((s * JT + r) * F_ST + ch * 8) * 2),
                      hB + (long)r * CN + t * JT + ch * 8);
        }
        // codes tile: 128 i-rows x 64 bytes
        #pragma unroll
        for (int i = 0; i < 2; i++) {
            int f = tid + i * 256;
            int r = f >> 2, c16 = (f & 3) * 16;
            cpasync16(Cs_b + (uint32_t)(s * 128 * G_CS + r * G_CS + c16),
                      cB + (long)r * CN + t * JT + c16);
        }
        cpcommit();
    };
    load_jt(0, 0);

    ((float4*)e2s)[tid] = ((const float4*)e2B)[tid];
    float e1v0 = e1[(long)b * CN + ib * 128 + r0 + g];
    float e1v1 = e1[(long)b * CN + ib * 128 + r0 + g + 8];
    float rA = rsc[0], rB2 = rsc[1];

    float m0 = -3.4e38f, m1 = -3.4e38f, l0 = 0.f, l1 = 0.f;
    float o[8][4];
    #pragma unroll
    for (int nf = 0; nf < 8; nf++)
        #pragma unroll
        for (int q = 0; q < 4; q++) o[nf][q] = 0.f;

    for (int t = 0; t < 16; t++) {
        int s = t & 1;
        if (t < 15) load_jt(t + 1, s ^ 1);
        if (t < 15) cpwait1(); else cpwait0();
        __syncthreads();

        float sc[8][4];
        #pragma unroll
        for (int nf = 0; nf < 8; nf++) {
            int lc = nf * 8 + tg * 2;
            float eA = e2s[t * JT + lc];
            float eB = e2s[t * JT + lc + 1];
            uint32_t c0 = *(const uint16_t*)&Cs[s * 128 * G_CS + (r0 + g) * G_CS + lc];
            uint32_t c1 = *(const uint16_t*)&Cs[s * 128 * G_CS + (r0 + g + 8) * G_CS + lc];
            float v;
            v = e1v0 + eA + ((c0 & 1u)   ? rB2 : rA); v = v >= 0.f ? v : ALPHAF * v; sc[nf][0] = (c0 & 2u)   ? v : NEGF;
            v = e1v0 + eB + ((c0 & 256u) ? rB2 : rA); v = v >= 0.f ? v : ALPHAF * v; sc[nf][1] = (c0 & 512u) ? v : NEGF;
            v = e1v1 + eA + ((c1 & 1u)   ? rB2 : rA); v = v >= 0.f ? v : ALPHAF * v; sc[nf][2] = (c1 & 2u)   ? v : NEGF;
            v = e1v1 + eB + ((c1 & 256u) ? rB2 : rA); v = v >= 0.f ? v : ALPHAF * v; sc[nf][3] = (c1 & 512u) ? v : NEGF;
        }

        float mx0 = -3.4e38f, mx1 = -3.4e38f;
        #pragma unroll
        for (int nf = 0; nf < 8; nf++) {
            mx0 = fmaxf(mx0, fmaxf(sc[nf][0], sc[nf][1]));
            mx1 = fmaxf(mx1, fmaxf(sc[nf][2], sc[nf][3]));
        }
        #pragma unroll
        for (int off = 1; off <= 2; off <<= 1) {
            mx0 = fmaxf(mx0, __shfl_xor_sync(0xffffffffu, mx0, off));
            mx1 = fmaxf(mx1, __shfl_xor_sync(0xffffffffu, mx1, off));
        }
        float mn0 = fmaxf(m0, mx0);
        float mn1 = fmaxf(m1, mx1);
        float cr0 = __expf(m0 - mn0);
        float cr1 = __expf(m1 - mn1);
        l0 *= cr0; l1 *= cr1;
        #pragma unroll
        for (int nf = 0; nf < 8; nf++) {
            o[nf][0] *= cr0; o[nf][1] *= cr0;
            o[nf][2] *= cr1; o[nf][3] *= cr1;
        }
        float rs0 = 0.f, rs1 = 0.f;
        #pragma unroll
        for (int nf = 0; nf < 8; nf++) {
            sc[nf][0] = __expf(sc[nf][0] - mn0);
            sc[nf][1] = __expf(sc[nf][1] - mn0);
            sc[nf][2] = __expf(sc[nf][2] - mn1);
            sc[nf][3] = __expf(sc[nf][3] - mn1);
            rs0 += sc[nf][0] + sc[nf][1];
            rs1 += sc[nf][2] + sc[nf][3];
        }
        #pragma unroll
        for (int off = 1; off <= 2; off <<= 1) {
            rs0 += __shfl_xor_sync(0xffffffffu, rs0, off);
            rs1 += __shfl_xor_sync(0xffffffffu, rs1, off);
        }
        l0 += rs0; l1 += rs1; m0 = mn0; m1 = mn1;

        #pragma unroll
        for (int kf = 0; kf < 4; kf++) {
            uint32_t a[4];
            a[0] = pkh2(sc[2 * kf][0],     sc[2 * kf][1]);
            a[1] = pkh2(sc[2 * kf][2],     sc[2 * kf][3]);
            a[2] = pkh2(sc[2 * kf + 1][0], sc[2 * kf + 1][1]);
            a[3] = pkh2(sc[2 * kf + 1][2], sc[2 * kf + 1][3]);
            #pragma unroll
            for (int nf = 0; nf < 8; nf++) {
                uint32_t b2[2];
                const __half* hr = &Hs[(s * JT + nf * 8 + g) * F_ST + kf * 16 + 2 * tg];
                b2[0] = *(uint32_t*)hr;
                b2[1] = *(uint32_t*)(hr + 8);
                mma_f16(o[nf], a, b2);
            }
        }
        __syncthreads();
    }

    float inv0 = 1.f / l0, inv1 = 1.f / l1;
    #pragma unroll
    for (int nf = 0; nf < 8; nf++) {
        int c = nf * 8 + tg * 2;
        float v0 = o[nf][0] * inv0, v1 = o[nf][1] * inv0;
        float v2 = o[nf][2] * inv1, v3 = o[nf][3] * inv1;
        v0 = v0 > 0.f ? v0 : expm1f(v0);
        v1 = v1 > 0.f ? v1 : expm1f(v1);
        v2 = v2 > 0.f ? v2 : expm1f(v2);
        v3 = v3 > 0.f ? v3 : expm1f(v3);
        *(float2*)(AggB + (long)(r0 + g)     * CHID + c) = make_float2(v0, v1);
        *(float2*)(AggB + (long)(r0 + g + 8) * CHID + c) = make_float2(v2, v3);
    }
}

// ---------------- fp32 tiled SGEMM (fc2 only) ----------------
template<int ACT>
__global__ void sgemm(const float* __restrict__ A, const float* __restrict__ Bm,
                      const float* __restrict__ bias, float* __restrict__ C,
                      int M, int N, int K)
{
    __shared__ float As[16][68];
    __shared__ float Bs[16][68];
    int tx = threadIdx.x;
    int tr = tx >> 4, tc = tx & 15;
    int row0 = blockIdx.y * 64, col0 = blockIdx.x * 64;

    float acc[4][4] = {};
    for (int k0 = 0; k0 < K; k0 += 16) {
        #pragma unroll
        for (int i = 0; i < 4; i++) {
            int idx = tx * 4 + i;
            int m = idx >> 4, k = idx & 15;
            int gr = row0 + m;
            As[k][m] = (gr < M) ? A[(long)gr * K + k0 + k] : 0.f;
        }
        #pragma unroll
        for (int i = 0; i < 4; i++) {
            int idx = tx * 4 + i;
            int k = idx >> 6, n = idx & 63;
            int gn = col0 + n;
            Bs[k][n] = (gn < N) ? Bm[(long)(k0 + k) * N + gn] : 0.f;
        }
        __syncthreads();
        #pragma unroll
        for (int k = 0; k < 16; k++) {
            float a[4], b[4];
            #pragma unroll
            for (int i = 0; i < 4; i++) a[i] = As[k][tr * 4 + i];
            #pragma unroll
            for (int j = 0; j < 4; j++) b[j] = Bs[k][tc * 4 + j];
            #pragma unroll
            for (int i = 0; i < 4; i++)
                #pragma unroll
                for (int j = 0; j < 4; j++)
                    acc[i][j] = fmaf(a[i], b[j], acc[i][j]);
        }
        __syncthreads();
    }
    #pragma unroll
    for (int i = 0; i < 4; i++) {
        int gr = row0 + tr * 4 + i;
        if (gr >= M) continue;
        #pragma unroll
        for (int j = 0; j < 4; j++) {
            int gn = col0 + tc * 4 + j;
            if (gn >= N) continue;
            float v = acc[i][j];
            if (bias) v += bias[gn];
            if (ACT == 1) v = v > 0.f ? v : 0.f;
            C[(long)gr * N + gn] = v;
        }
    }
}

// ---------------- logits: warp per row ----------------
__global__ void logits_kernel(const float* __restrict__ H, const float* __restrict__ W,
                              const float* __restrict__ bb, float* __restrict__ out)
{
    int warp = threadIdx.x >> 5, lane = threadIdx.x & 31;
    int row = blockIdx.x * 8 + warp;
    float hv[8];
    #pragma unroll
    for (int j = 0; j < 8; j++) hv[j] = H[(long)row * CHID + j * 32 + lane];
    float acc[CNC];
    #pragma unroll
    for (int c = 0; c < CNC; c++) {
        float a = 0.f;
        #pragma unroll
        for (int j = 0; j < 8; j++) a = fmaf(hv[j], W[(j * 32 + lane) * CNC + c], a);
        acc[c] = a;
    }
    #pragma unroll
    for (int c = 0; c < CNC; c++)
        #pragma unroll
        for (int off = 16; off > 0; off >>= 1)
            acc[c] += __shfl_xor_sync(0xffffffffu, acc[c], off);
    if (lane < CNC) out[(long)row * CNC + lane] = acc[lane] + bb[lane];
}

// ---------------- P_l_1 ----------------
__global__ void pl1_kernel(const float* __restrict__ sadj, const float* __restrict__ P,
                           float* __restrict__ out)
{
    long idx = (long)blockIdx.x * 256 + threadIdx.x;
    int d = idx & (CHID - 1);
    int n = (idx >> 8) & (CN - 1);
    int b = (int)(idx >> 18);
    const float* sa = sadj + (long)b * CM * CN + n;
    const float* Pb = P + (long)b * CM * CHID + d;
    float acc = 0.f;
    #pragma unroll
    for (int m = 0; m < CM; m++) acc = fmaf(sa[m * CN], Pb[m * CHID], acc);
    out[idx] = acc;
}

// ---------------- e1/e2 dots from hT ----------------
__global__ void dots_kernel(const __half* __restrict__ hT, const float* __restrict__ a1,
                            const float* __restrict__ a2,
                            float* __restrict__ e1, float* __restrict__ e2)
{
    int b = blockIdx.x >> 2, jc = blockIdx.x & 3;
    int j = jc * 256 + threadIdx.x;
    const __half* base = hT + (long)b * CHID * CN + j;
    float s1 = 0.f, s2 = 0.f;
    #pragma unroll 8
    for (int c = 0; c < CHID; c++) {
        float v = __half2float(base[(long)c * CN]);
        s1 = fmaf(v, a1[c], s1);
        s2 = fmaf(v, a2[c], s2);
    }
    e1[b * CN + j] = s1;
    e2[b * CN + j] = s2;
}

// ---------------- rel_sc ----------------
__global__ void relsc_kernel(const float* __restrict__ rel, const float* __restrict__ a3,
                             float* __restrict__ out)
{
    __shared__ float s[256];
    int r = blockIdx.x, t = threadIdx.x;
    s[t] = rel[r * CHID + t] * a3[t];
    __syncthreads();
    for (int o = 128; o > 0; o >>= 1) {
        if (t < o) s[t] += s[t + o];
        __syncthreads();
    }
    if (t == 0) out[r] = s[0];
}

// ---------------- LayerNorm: warp per row ----------------
__global__ void ln_kernel(const float* __restrict__ T, const float* __restrict__ Hold,
                          const float* __restrict__ g, const float* __restrict__ bb,
                          float* __restrict__ out)
{
    int warp = threadIdx.x >> 5, lane = threadIdx.x & 31;
    int row = blockIdx.x * 8 + warp;
    long base = (long)row * CHID;
    float v[8];
    float s = 0.f;
    #pragma unroll
    for (int j = 0; j < 8; j++) {
        int c = j * 32 + lane;
        v[j] = T[base + c] + Hold[base + c];
        s += v[j];
    }
    #pragma unroll
    for (int off = 16; off > 0; off >>= 1) s += __shfl_xor_sync(0xffffffffu, s, off);
    float mu = s * (1.f / CHID);
    float q = 0.f;
    #pragma unroll
    for (int j = 0; j < 8; j++) { v[j] -= mu; q = fmaf(v[j], v[j], q); }
    #pragma unroll
    for (int off = 16; off > 0; off >>= 1) q += __shfl_xor_sync(0xffffffffu, q, off);
    float rstd = rsqrtf(q * (1.f / CHID) + 1e-5f);
    #pragma unroll
    for (int j = 0; j < 8; j++) {
        int c = j * 32 + lane;
        out[base + c] = v[j] * rstd * g[c] + bb[c];
    }
}

// ---------------- fused P_agg + GRU3d ----------------
__global__ void pagggru_kernel(const float* __restrict__ sadj, const float* __restrict__ Hcur,
                               float* __restrict__ P,
                               const float* __restrict__ wz, const float* __restrict__ uz,
                               const float* __restrict__ wr, const float* __restrict__ ur,
                               const float* __restrict__ w,  const float* __restrict__ u)
{
    __shared__ float sp[CHID], sq[CHID];
    int bm = blockIdx.x;
    int b = bm >> 3;
    int c = threadIdx.x;
    const float* sa = sadj + (long)bm * CN;
    const float* Hb = Hcur + (long)b * CN * CHID + c;
    float acc = 0.f;
    #pragma unroll 4
    for (int n = 0; n < CN; n++) acc = fmaf(sa[n], Hb[(long)n * CHID], acc);
    sq[c] = acc;
    sp[c] = P[(long)bm * CHID + c];
    __syncthreads();
    float az = 0, bz = 0, ar = 0, br = 0, aw = 0, bw = 0;
    #pragma unroll 4
    for (int k = 0; k < CHID; k++) {
        float pk = sp[k], qk = sq[k];
        az = fmaf(pk, wz[k * CHID + c], az); bz = fmaf(qk, uz[k * CHID + c], bz);
        ar = fmaf(pk, wr[k * CHID + c], ar); br = fmaf(qk, ur[k * CHID + c], br);
        aw = fmaf(pk, w [k * CHID + c], aw); bw = fmaf(qk, u [k * CHID + c], bw);
    }
    float z  = 1.f / (1.f + expf(-(az + bz)));
    float rr = 1.f / (1.f + expf(-(ar + br)));
    float hh = tanhf(aw + rr * bw);
    P[(long)bm * CHID + c] = (1.f - z) * sp[c] + z * hh;
}

// ---------------- p_sim ----------------
__global__ void psim_kernel(const float* __restrict__ P, float* __restrict__ outp, int tail)
{
    __shared__ float red[64];
    int t = threadIdx.x;
    int b = t >> 3, m = t & 7;
    const float* Pb = P + (long)b * CM * CHID;
    float s = 0.f;
    for (int k2 = 0; k2 < CM; k2++) {
        if (k2 == m) continue;
        float d = 0.f;
        for (int dd = 0; dd < CHID; dd++)
            d = fmaf(Pb[m * CHID + dd], Pb[k2 * CHID + dd], d);
        s += d;
    }
    red[t] = s; __syncthreads();
    if ((t & 7) < 4) red[t] += red[t + 4]; __syncthreads();
    if ((t & 7) < 2) red[t] += red[t + 2]; __syncthreads();
    if ((t & 7) < 1) red[t] += red[t + 1]; __syncthreads();
    if (tail >= CB) {
        if (t < CB) outp[t] = red[t * 8] / (float)(CM * CM);
    } else {
        if (t == 0) {
            float tot = 0.f;
            for (int b2 = 0; b2 < CB; b2++) tot += red[b2 * 8];
            outp[0] = tot / (float)(CB * CM * CM);
        }
    }
}

// ---------------- host orchestration ----------------
extern "C" void kernel_launch(void* const* d_in, const int* in_sizes, int n_in,
                              void* d_out, int out_size)
{
    const float* x     = (const float*)d_in[0];
    const int*   adj   = (const int*)  d_in[1];
    const int*   smask = (const int*)  d_in[2];
    const float* sf    = (const float*)d_in[3];
    const float* sadj  = (const float*)d_in[4];
    const float* fc1w  = (const float*)d_in[6];
    const float* fc1b  = (const float*)d_in[7];
    const float* fc2w  = (const float*)d_in[8];
    const float* fc2b  = (const float*)d_in[9];
    const float* gatW  = (const float*)d_in[10];
    const float* gata  = (const float*)d_in[11];
    const float* rel   = (const float*)d_in[12];
    const float* gwz   = (const float*)d_in[13];
    const float* guz   = (const float*)d_in[14];
    const float* gwr   = (const float*)d_in[15];
    const float* gur   = (const float*)d_in[16];
    const float* gw    = (const float*)d_in[17];
    const float* gu    = (const float*)d_in[18];
    const float* wv    = (const float*)d_in[19];
    const float* bv    = (const float*)d_in[20];
    const float* wk    = (const float*)d_in[21];
    const float* bk    = (const float*)d_in[22];
    const float* wq    = (const float*)d_in[23];
    const float* bq    = (const float*)d_in[24];
    const float* wo    = (const float*)d_in[25];
    const float* bo    = (const float*)d_in[26];
    const float* lng   = (const float*)d_in[27];
    const float* lnb   = (const float*)d_in[28];
    const float* outw  = (const float*)d_in[29];
    const float* outb  = (const float*)d_in[30];
    float* out = (float*)d_out;

    float *H, *Hn, *P, *Pl1, *Agg, *ctx, *Tb, *e1, *e2, *rsc;
    __half *Qh, *Kh, *VT, *hT;
    uint8_t* codes;
    cudaGetSymbolAddress((void**)&H,    g_H);
    cudaGetSymbolAddress((void**)&Hn,   g_Hn);
    cudaGetSymbolAddress((void**)&P,    g_P);
    cudaGetSymbolAddress((void**)&Pl1,  g_Pl1);
    cudaGetSymbolAddress((void**)&Agg,  g_Agg);
    cudaGetSymbolAddress((void**)&ctx,  g_ctx);
    cudaGetSymbolAddress((void**)&Tb,   g_T);
    cudaGetSymbolAddress((void**)&Qh,   g_Qh);
    cudaGetSymbolAddress((void**)&Kh,   g_Kh);
    cudaGetSymbolAddress((void**)&VT,   g_VT);
    cudaGetSymbolAddress((void**)&hT,   g_hT);
    cudaGetSymbolAddress((void**)&codes, g_codes);
    cudaGetSymbolAddress((void**)&e1,   g_e1);
    cudaGetSymbolAddress((void**)&e2,   g_e2);
    cudaGetSymbolAddress((void**)&rsc,  g_rsc);

    cudaFuncSetAttribute(tgemm<0>, cudaFuncAttributeMaxDynamicSharedMemorySize, SM_TG);
    cudaFuncSetAttribute(tgemm<1>, cudaFuncAttributeMaxDynamicSharedMemorySize, SM_TG);
    cudaFuncSetAttribute(tgemm_pair, cudaFuncAttributeMaxDynamicSharedMemorySize, SM_TG);
    cudaFuncSetAttribute(flash_kernel, cudaFuncAttributeMaxDynamicSharedMemorySize, SM_FLASH);
    cudaFuncSetAttribute(gatt_kernel, cudaFuncAttributeMaxDynamicSharedMemorySize, SM_GATT);

    dim3 blk(256);
    const int BN = CB * CN;
    const long HH = (long)CHID * CHID;

    pack_codes<<<(int)((long)CB * CN * CN / 4 / 256), blk>>>(adj, smask, codes);
    tgemm<1><<<dim3(2, 64, 1), blk, SM_TG>>>(x, fc1w, fc1b, H, BN, CHID, CDIN, 0, 0, 0, 1.f);
    sgemm<1><<<dim3(4, 1, 1), blk>>>(sf, fc2w, fc2b, P, CB * CM, CHID, CDIN);

    for (int l = 0; l < CL; l++) {
        float* cur = l ? Hn : H;
        float* nxt = l ? H : Hn;

        pl1_kernel<<<BN * CHID / 256, blk>>>(sadj, P, Pl1);

        // paired: hT = (cur @ gatW)^T fp16 ; VT = (cur @ wv + bv) head-T fp16
        {
            G2 a;
            a.A[0] = cur;           a.A[1] = cur;
            a.B[0] = gatW + l * HH; a.B[1] = wv + l * HH;
            a.bias[0] = nullptr;    a.bias[1] = bv + l * CHID;
            a.C[0] = (float*)hT;    a.C[1] = (float*)VT;
            a.act[0] = 5;           a.act[1] = 6;
            tgemm_pair<<<dim3(2, 64, 2), blk, SM_TG>>>(a, BN, CHID, CHID);
        }
        dots_kernel<<<CB * 4, blk>>>(hT, gata + l * 3 * CHID, gata + l * 3 * CHID + CHID, e1, e2);
        relsc_kernel<<<2, blk>>>(rel + l * 2 * CHID, gata + l * 3 * CHID + 2 * CHID, rsc);
        gatt_kernel<<<dim3(4, 8, CB), blk, SM_GATT>>>(e1, e2, rsc, codes, hT, Agg);
        // paired: Kh = Pl1 @ wk + bk ; Qh = Agg @ wq + bq  (fp16 row-major)
        {
            G2 a;
            a.A[0] = Pl1;           a.A[1] = Agg;
            a.B[0] = wk + l * HH;   a.B[1] = wq + l * HH;
            a.bias[0] = bk + l * CHID; a.bias[1] = bq + l * CHID;
            a.C[0] = (float*)Kh;    a.C[1] = (float*)Qh;
            a.act[0] = 4;           a.act[1] = 4;
            tgemm_pair<<<dim3(2, 64, 2), blk, SM_TG>>>(a, BN, CHID, CHID);
        }
        flash_kernel<<<dim3(8, 32), blk, SM_FLASH>>>(Qh, Kh, VT, ctx);
        tgemm<0><<<dim3(2, 64, 1), blk, SM_TG>>>(ctx, wo + l * HH, bo + l * CHID, Tb,
                                                 BN, CHID, CHID, 0, 0, 0, 1.f);
        ln_kernel<<<BN / 8, blk>>>(Tb, cur, lng + l * CHID, lnb + l * CHID, nxt);

        pagggru_kernel<<<CB * CM, blk>>>(sadj, cur, P,
                                         gwz + l * HH, guz + l * HH,
                                         gwr + l * HH, gur + l * HH,
                                         gw + l * HH,  gu + l * HH);
    }

    logits_kernel<<<BN / 8, blk>>>(H, outw, outb, out);
    psim_kernel<<<1, 64>>>(P, out + (long)BN * CNC, out_size - BN * CNC);
}

// round 11
// speedup vs baseline: 1.1624x; 1.0190x over previous
#include <cuda_runtime.h>
#include <cuda_fp16.h>
#include <math.h>
#include <stdint.h>

// ---------------- problem constants ----------------
constexpr int CB   = 8;
constexpr int CN   = 1024;
constexpr int CM   = 8;
constexpr int CDIN = 1024;
constexpr int CHID = 256;
constexpr int CL   = 2;
constexpr int CNC  = 7;
constexpr int CDH  = 64;
#define NEGF  (-9e15f)
#define ALPHAF 0.1f

// ---------------- scratch ----------------
__device__ float  g_H   [CB*CN*CHID];
__device__ float  g_Hn  [CB*CN*CHID];
__device__ float  g_P   [CB*CM*CHID];
__device__ float  g_PW  [CB*CM*CHID];
__device__ float  g_Agg [CB*CN*CHID];
__device__ float  g_ctx [CB*CN*CHID];
__device__ float  g_T   [CB*CN*CHID];
__device__ __half g_Qh  [CB*CN*CHID];
__device__ __half g_Kh  [CB*CN*CHID];
__device__ __half g_VT  [CB*CN*CHID];   // [bh][d][j]
__device__ __half g_hT  [CB*CN*CHID];   // [b][c][n]
__device__ uint8_t g_codes[(long)CB*CN*CN];
__device__ float  g_e1  [CB*CN];
__device__ float  g_e2  [CB*CN];
__device__ float  g_rsc [2];

// ---------------- helpers ----------------
__device__ __forceinline__ uint32_t f2tf(float f) {
    uint32_t u;
    asm("cvt.rna.tf32.f32 %0, %1;" : "=r"(u) : "f"(f));
    return u;
}
__device__ __forceinline__ void mma_tf32(float c[4], const uint32_t a[4], const uint32_t b[2]) {
    asm volatile(
        "mma.sync.aligned.m16n8k8.row.col.f32.tf32.tf32.f32 "
        "{%0,%1,%2,%3}, {%4,%5,%6,%7}, {%8,%9}, {%0,%1,%2,%3};\n"
        : "+f"(c[0]), "+f"(c[1]), "+f"(c[2]), "+f"(c[3])
        : "r"(a[0]), "r"(a[1]), "r"(a[2]), "r"(a[3]), "r"(b[0]), "r"(b[1]));
}
__device__ __forceinline__ void mma_f16(float c[4], const uint32_t a[4], const uint32_t b[2]) {
    asm volatile(
        "mma.sync.aligned.m16n8k16.row.col.f32.f16.f16.f32 "
        "{%0,%1,%2,%3}, {%4,%5,%6,%7}, {%8,%9}, {%0,%1,%2,%3};\n"
        : "+f"(c[0]), "+f"(c[1]), "+f"(c[2]), "+f"(c[3])
        : "r"(a[0]), "r"(a[1]), "r"(a[2]), "r"(a[3]), "r"(b[0]), "r"(b[1]));
}
__device__ __forceinline__ uint32_t pkh2(float x, float y) {
    __half2 h = __floats2half2_rn(x, y);
    return *(uint32_t*)&h;
}
__device__ __forceinline__ void cpasync16(uint32_t saddr, const void* gptr) {
    asm volatile("cp.async.cg.shared.global [%0], [%1], 16;\n" :: "r"(saddr), "l"(gptr));
}
__device__ __forceinline__ void cpcommit() { asm volatile("cp.async.commit_group;\n"); }
__device__ __forceinline__ void cpwait0()  { asm volatile("cp.async.wait_group 0;\n"); }
__device__ __forceinline__ void cpwait1()  { asm volatile("cp.async.wait_group 1;\n"); }

// ================= core GEMM tile (128x128, KS=32, 2-stage, 2 CTAs/SM) =================
struct TileCtx {
    float *As, *Bs;
    uint32_t As_b, Bs_b;
    const float *Ag, *Bg;
    int K, N;
    int tid;
};
constexpr int T_strA = 36, T_strB = 132;
constexpr int T_AW = 128 * T_strA, T_BW = 32 * T_strB;
constexpr int SM_TG = (2 * (T_AW + T_BW)) * 4;   // 70656 bytes

__device__ __forceinline__ void tg_load_stage(TileCtx& c, int kt, int s) {
    int k0 = kt * 32;
    #pragma unroll
    for (int i = 0; i < 4; i++) {
        int f = c.tid + i * 256;
        int m = f >> 3, k4 = (f & 7) * 4;
        cpasync16(c.As_b + (uint32_t)(((s * 128 + m) * T_strA + k4) * 4),
                  c.Ag + (long)m * c.K + k0 + k4);
    }
    #pragma unroll
    for (int i = 0; i < 4; i++) {
        int f = c.tid + i * 256;
        int k = f >> 5, n4 = (f & 31) * 4;
        cpasync16(c.Bs_b + (uint32_t)(((s * 32 + k) * T_strB + n4) * 4),
                  c.Bg + (long)(k0 + k) * c.N + n4);
    }
    cpcommit();
}

// act: 0 none, 1 relu, 4 half row-major, 5 half batch-transpose, 6 half head-transpose
__device__ __forceinline__ void tg_body(
    TileCtx& c, const float* bias, float* C, int M, int N, int K,
    int row0, int col0, float scale, int act)
{
    int tid  = c.tid;
    int warp = tid >> 5, lane = tid & 31;
    int g = lane >> 2, tg = lane & 3;
    int mw = warp >> 2, nw = warp & 3;

    float acc[4][4][4];
    #pragma unroll
    for (int mi = 0; mi < 4; mi++)
        #pragma unroll
        for (int ni = 0; ni < 4; ni++)
            #pragma unroll
            for (int q = 0; q < 4; q++) acc[mi][ni][q] = 0.f;

    int nk = K / 32;
    tg_load_stage(c, 0, 0);

    for (int kt = 0; kt < nk; kt++) {
        cpwait0();
        __syncthreads();
        int s = kt & 1;
        if (kt + 1 < nk) tg_load_stage(c, kt + 1, s ^ 1);

        const float* Asb = c.As + s * T_AW;
        const float* Bsb = c.Bs + s * T_BW;
        #pragma unroll
        for (int ks = 0; ks < 32; ks += 8) {
            uint32_t a[4][4], b[4][2];
            #pragma unroll
            for (int mi = 0; mi < 4; mi++) {
                int mr = mw * 64 + mi * 16;
                a[mi][0] = f2tf(Asb[(mr + g)     * T_strA + ks + tg]);
                a[mi][1] = f2tf(Asb[(mr + g + 8) * T_strA + ks + tg]);
                a[mi][2] = f2tf(Asb[(mr + g)     * T_strA + ks + tg + 4]);
                a[mi][3] = f2tf(Asb[(mr + g + 8) * T_strA + ks + tg + 4]);
            }
            #pragma unroll
            for (int ni = 0; ni < 4; ni++) {
                int nc = nw * 32 + ni * 8;
                b[ni][0] = f2tf(Bsb[(ks + tg)     * T_strB + nc + g]);
                b[ni][1] = f2tf(Bsb[(ks + tg + 4) * T_strB + nc + g]);
            }
            #pragma unroll
            for (int mi = 0; mi < 4; mi++)
                #pragma unroll
                for (int ni = 0; ni < 4; ni++)
                    mma_tf32(acc[mi][ni], a[mi], b[ni]);
        }
    }

    #pragma unroll
    for (int mi = 0; mi < 4; mi++) {
        #pragma unroll
        for (int ni = 0; ni < 4; ni++) {
            int r = row0 + mw * 64 + mi * 16 + g;
            int cc0 = col0 + nw * 32 + ni * 8 + tg * 2;
            float b0 = bias ? bias[cc0] : 0.f;
            float b1 = bias ? bias[cc0 + 1] : 0.f;
            #pragma unroll
            for (int rr = 0; rr < 2; rr++) {
                int r_ = r + rr * 8;
                float v0 = acc[mi][ni][rr * 2 + 0] * scale + b0;
                float v1 = acc[mi][ni][rr * 2 + 1] * scale + b1;
                if (act == 0) {
                    *(float2*)(C + (long)r_ * N + cc0) = make_float2(v0, v1);
                } else if (act == 1) {
                    *(float2*)(C + (long)r_ * N + cc0) =
                        make_float2(fmaxf(v0, 0.f), fmaxf(v1, 0.f));
                } else if (act == 4) {
                    __half2 h = __floats2half2_rn(v0, v1);
                    *(__half2*)((__half*)C + (long)r_ * N + cc0) = h;
                } else if (act == 5) {          // hT: [b][c][n]
                    __half* CT = (__half*)C;
                    int b_ = r_ >> 10, j = r_ & 1023;
                    CT[((long)(b_ * CHID + cc0))     * CN + j] = __float2half_rn(v0);
                    CT[((long)(b_ * CHID + cc0 + 1)) * CN + j] = __float2half_rn(v1);
                } else {                        // 6: VT: [bh][d][j]
                    __half* CT = (__half*)C;
                    int bh = r_ >> 8;
                    int j = ((r_ & 255) << 2) | (cc0 >> 6);
                    int d = cc0 & 63;
                    long base = ((long)bh << 16) + ((long)d << 10) + j;
                    CT[base] = __float2half_rn(v0);
                    CT[base + 1024] = __float2half_rn(v1);
                }
            }
        }
    }
}

template<int ACT>
__global__ void __launch_bounds__(256, 2) tgemm(
    const float* __restrict__ A, const float* __restrict__ Bm,
    const float* __restrict__ bias, float* __restrict__ C,
    int M, int N, int K, long sA, long sB, long sC, float scale)
{
    extern __shared__ float smem[];
    int bz = blockIdx.z;
    TileCtx c;
    c.As = smem; c.Bs = smem + 2 * T_AW;
    c.As_b = (uint32_t)__cvta_generic_to_shared(c.As);
    c.Bs_b = (uint32_t)__cvta_generic_to_shared(c.Bs);
    c.K = K; c.N = N; c.tid = threadIdx.x;
    int row0 = blockIdx.y * 128, col0 = blockIdx.x * 128;
    c.Ag = A + (long)bz * sA + (long)row0 * K;
    c.Bg = Bm + (long)bz * sB + col0;
    tg_body(c, bias, C + (long)bz * sC, M, N, K, row0, col0, scale, ACT);
}

struct G2 { const float* A[2]; const float* B[2]; const float* bias[2]; float* C[2]; int act[2]; };
__global__ void __launch_bounds__(256, 2) tgemm_pair(G2 args, int M, int N, int K)
{
    extern __shared__ float smem[];
    int z = blockIdx.z;
    TileCtx c;
    c.As = smem; c.Bs = smem + 2 * T_AW;
    c.As_b = (uint32_t)__cvta_generic_to_shared(c.As);
    c.Bs_b = (uint32_t)__cvta_generic_to_shared(c.Bs);
    c.K = K; c.N = N; c.tid = threadIdx.x;
    int row0 = blockIdx.y * 128, col0 = blockIdx.x * 128;
    c.Ag = args.A[z] + (long)row0 * K;
    c.Bg = args.B[z] + col0;
    tg_body(c, args.bias[z], args.C[z], M, N, K, row0, col0, 1.f, args.act[z]);
}

// ---------------- fp16 flash attention, 64-row KV tiles ----------------
constexpr int F_ST = 72;   // half stride
constexpr int SM_FLASH = (128 * F_ST + 2 * 64 * F_ST + 2 * 64 * F_ST) * 2;  // 55296
__global__ void __launch_bounds__(256, 2) flash_kernel(
    const __half* __restrict__ Q, const __half* __restrict__ Kg_,
    const __half* __restrict__ Vt_, float* __restrict__ O)
{
    constexpr int KT = 64;
    extern __shared__ float smraw[];
    __half* Qs = (__half*)smraw;
    __half* Ks = Qs + 128 * F_ST;
    __half* Vs = Ks + 2 * KT * F_ST;
    uint32_t Qs_b = (uint32_t)__cvta_generic_to_shared(Qs);
    uint32_t Ks_b = (uint32_t)__cvta_generic_to_shared(Ks);
    uint32_t Vs_b = (uint32_t)__cvta_generic_to_shared(Vs);

    int bh = blockIdx.y;
    const __half* Qg = Q + (long)bh * CN * CDH + (long)blockIdx.x * 128 * CDH;
    const __half* Kg = Kg_ + (long)bh * CN * CDH;
    const __half* Vg = Vt_ + ((long)bh << 16);
    float* Og = O + (long)bh * CN * CDH + (long)blockIdx.x * 128 * CDH;

    int tid = threadIdx.x, warp = tid >> 5, lane = tid & 31;
    int g = lane >> 2, tg = lane & 3;
    int r0 = warp * 16;

    #pragma unroll
    for (int i = 0; i < 4; i++) {
        int f = tid + i * 256;
        int r = f >> 3, ch = f & 7;
        cpasync16(Qs_b + (uint32_t)((r * F_ST + ch * 8) * 2), Qg + r * CDH + ch * 8);
    }
    cpcommit();

    auto load_kv = [&](int t, int s) {
        const __half* Kt = Kg + t * KT * CDH;
        const __half* Vtb = Vg + t * KT;
        #pragma unroll
        for (int i = 0; i < 2; i++) {
            int f = tid + i * 256;
            int r = f >> 3, ch = f & 7;
            cpasync16(Ks_b + (uint32_t)(((s * KT + r) * F_ST + ch * 8) * 2),
                      Kt + r * CDH + ch * 8);
        }
        #pragma unroll
        for (int i = 0; i < 2; i++) {
            int f = tid + i * 256;
            int r = f >> 3, ch = f & 7;
            cpasync16(Vs_b + (uint32_t)(((s * KT + r) * F_ST + ch * 8) * 2),
                      Vtb + (long)r * CN + ch * 8);
        }
        cpcommit();
    };
    load_kv(0, 0);

    cpwait1();
    __syncthreads();

    uint32_t aq[4][4];
    #pragma unroll
    for (int kf = 0; kf < 4; kf++) {
        aq[kf][0] = *(uint32_t*)&Qs[(r0 + g)     * F_ST + kf * 16 + 2 * tg];
        aq[kf][1] = *(uint32_t*)&Qs[(r0 + g + 8) * F_ST + kf * 16 + 2 * tg];
        aq[kf][2] = *(uint32_t*)&Qs[(r0 + g)     * F_ST + kf * 16 + 2 * tg + 8];
        aq[kf][3] = *(uint32_t*)&Qs[(r0 + g + 8) * F_ST + kf * 16 + 2 * tg + 8];
    }

    float m0 = -3.4e38f, m1 = -3.4e38f, l0 = 0.f, l1 = 0.f;
    float o[8][4];
    #pragma unroll
    for (int nf = 0; nf < 8; nf++)
        #pragma unroll
        for (int q = 0; q < 4; q++) o[nf][q] = 0.f;

    for (int t = 0; t < 16; t++) {
        int s = t & 1;
        if (t < 15) load_kv(t + 1, s ^ 1);
        if (t < 15) cpwait1(); else cpwait0();
        __syncthreads();

        float sc[8][4];
        #pragma unroll
        for (int nf = 0; nf < 8; nf++)
            #pragma unroll
            for (int q = 0; q < 4; q++) sc[nf][q] = 0.f;
        #pragma unroll
        for (int kf = 0; kf < 4; kf++) {
            #pragma unroll
            for (int nf = 0; nf < 8; nf++) {
                uint32_t b[2];
                const __half* kr = &Ks[(s * KT + nf * 8 + g) * F_ST + kf * 16 + 2 * tg];
                b[0] = *(uint32_t*)kr;
                b[1] = *(uint32_t*)(kr + 8);
                mma_f16(sc[nf], aq[kf], b);
            }
        }

        float mx0 = -3.4e38f, mx1 = -3.4e38f;
        #pragma unroll
        for (int nf = 0; nf < 8; nf++) {
            mx0 = fmaxf(mx0, fmaxf(sc[nf][0], sc[nf][1]));
            mx1 = fmaxf(mx1, fmaxf(sc[nf][2], sc[nf][3]));
        }
        #pragma unroll
        for (int off = 1; off <= 2; off <<= 1) {
            mx0 = fmaxf(mx0, __shfl_xor_sync(0xffffffffu, mx0, off));
            mx1 = fmaxf(mx1, __shfl_xor_sync(0xffffffffu, mx1, off));
        }
        float mn0 = fmaxf(m0, mx0 * 0.125f);
        float mn1 = fmaxf(m1, mx1 * 0.125f);
        float cr0 = __expf(m0 - mn0);
        float cr1 = __expf(m1 - mn1);
        l0 *= cr0; l1 *= cr1;
        #pragma unroll
        for (int nf = 0; nf < 8; nf++) {
            o[nf][0] *= cr0; o[nf][1] *= cr0;
            o[nf][2] *= cr1; o[nf][3] *= cr1;
        }
        float rs0 = 0.f, rs1 = 0.f;
        #pragma unroll
        for (int nf = 0; nf < 8; nf++) {
            sc[nf][0] = __expf(sc[nf][0] * 0.125f - mn0);
            sc[nf][1] = __expf(sc[nf][1] * 0.125f - mn0);
            sc[nf][2] = __expf(sc[nf][2] * 0.125f - mn1);
            sc[nf][3] = __expf(sc[nf][3] * 0.125f - mn1);
            rs0 += sc[nf][0] + sc[nf][1];
            rs1 += sc[nf][2] + sc[nf][3];
        }
        #pragma unroll
        for (int off = 1; off <= 2; off <<= 1) {
            rs0 += __shfl_xor_sync(0xffffffffu, rs0, off);
            rs1 += __shfl_xor_sync(0xffffffffu, rs1, off);
        }
        l0 += rs0; l1 += rs1; m0 = mn0; m1 = mn1;

        #pragma unroll
        for (int kf = 0; kf < 4; kf++) {
            uint32_t a[4];
            a[0] = pkh2(sc[2 * kf][0],     sc[2 * kf][1]);
            a[1] = pkh2(sc[2 * kf][2],     sc[2 * kf][3]);
            a[2] = pkh2(sc[2 * kf + 1][0], sc[2 * kf + 1][1]);
            a[3] = pkh2(sc[2 * kf + 1][2], sc[2 * kf + 1][3]);
            #pragma unroll
            for (int nf = 0; nf < 8; nf++) {
                uint32_t b[2];
                const __half* vr = &Vs[(s * KT + nf * 8 + g) * F_ST + kf * 16 + 2 * tg];
                b[0] = *(uint32_t*)vr;
                b[1] = *(uint32_t*)(vr + 8);
                mma_f16(o[nf], a, b);
            }
        }
        __syncthreads();
    }

    float inv0 = 1.f / l0, inv1 = 1.f / l1;
    #pragma unroll
    for (int nf = 0; nf < 8; nf++) {
        int c = nf * 8 + tg * 2;
        *(float2*)(Og + (long)(r0 + g)     * CDH + c) = make_float2(o[nf][0] * inv0, o[nf][1] * inv0);
        *(float2*)(Og + (long)(r0 + g + 8) * CDH + c) = make_float2(o[nf][2] * inv1, o[nf][3] * inv1);
    }
}

// ---------------- pack adj+smask ----------------
__global__ void pack_codes(const int* __restrict__ adj, const int* __restrict__ smask,
                           uint8_t* __restrict__ codes)
{
    long i = (long)blockIdx.x * 256 + threadIdx.x;
    int4 a = ((const int4*)adj)[i];
    int4 s = ((const int4*)smask)[i];
    uchar4 c;
    c.x = (uint8_t)(((a.x > 0) ? 2 : 0) | (s.x & 1));
    c.y = (uint8_t)(((a.y > 0) ? 2 : 0) | (s.y & 1));
    c.z = (uint8_t)(((a.z > 0) ? 2 : 0) | (s.z & 1));
    c.w = (uint8_t)(((a.w > 0) ? 2 : 0) | (s.w & 1));
    ((uchar4*)codes)[i] = c;
}

// ---------------- fused GAT attention (fp16 PV) ----------------
constexpr int G_CS = 80;
constexpr int SM_GATT = 2 * 64 * F_ST * 2 + CN * 4 + 2 * 128 * G_CS;  // 43008
__global__ void __launch_bounds__(256, 2) gatt_kernel(
    const float* __restrict__ e1, const float* __restrict__ e2,
    const float* __restrict__ rsc, const uint8_t* __restrict__ codes,
    const __half* __restrict__ hT, float* __restrict__ Agg)
{
    constexpr int JT = 64;
    extern __shared__ float smraw[];
    __half* Hs = (__half*)smraw;
    float* e2s = (float*)(Hs + 2 * JT * F_ST);
    uint8_t* Cs = (uint8_t*)(e2s + CN);
    uint32_t Hs_b = (uint32_t)__cvta_generic_to_shared(Hs);
    uint32_t Cs_b = (uint32_t)__cvta_generic_to_shared(Cs);

    int nq = blockIdx.x, ib = blockIdx.y, b = blockIdx.z;
    const __half*  hB  = hT + ((long)(b * CHID + nq * 64)) * CN;
    const uint8_t* cB  = codes + ((long)b * CN + ib * 128) * CN;
    const float*   e2B = e2 + (long)b * CN;
    float* AggB = Agg + ((long)b * CN + ib * 128) * CHID + nq * 64;

    int tid = threadIdx.x, warp = tid >> 5, lane = tid & 31;
    int g = lane >> 2, tg = lane & 3;
    int r0 = warp * 16;

    auto load_jt = [&](int t, int s) {
        #pragma unroll
        for (int i = 0; i < 2; i++) {
            int f = tid + i * 256;
            int r = f >> 3, ch = f & 7;
            cpasync16(Hs_b + (uint32_t)(((s * JT + r) * F_ST + ch * 8) * 2),
                      hB + (long)r * CN + t * JT + ch * 8);
        }
        #pragma unroll
        for (int i = 0; i < 2; i++) {
            int f = tid + i * 256;
            int r = f >> 2, c16 = (f & 3) * 16;
            cpasync16(Cs_b + (uint32_t)(s * 128 * G_CS + r * G_CS + c16),
                      cB + (long)r * CN + t * JT + c16);
        }
        cpcommit();
    };
    load_jt(0, 0);

    ((float4*)e2s)[tid] = ((const float4*)e2B)[tid];
    float e1v0 = e1[(long)b * CN + ib * 128 + r0 + g];
    float e1v1 = e1[(long)b * CN + ib * 128 + r0 + g + 8];
    float rA = rsc[0], rB2 = rsc[1];

    float m0 = -3.4e38f, m1 = -3.4e38f, l0 = 0.f, l1 = 0.f;
    float o[8][4];
    #pragma unroll
    for (int nf = 0; nf < 8; nf++)
        #pragma unroll
        for (int q = 0; q < 4; q++) o[nf][q] = 0.f;

    for (int t = 0; t < 16; t++) {
        int s = t & 1;
        if (t < 15) load_jt(t + 1, s ^ 1);
        if (t < 15) cpwait1(); else cpwait0();
        __syncthreads();

        float sc[8][4];
        #pragma unroll
        for (int nf = 0; nf < 8; nf++) {
            int lc = nf * 8 + tg * 2;
            float eA = e2s[t * JT + lc];
            float eB = e2s[t * JT + lc + 1];
            uint32_t c0 = *(const uint16_t*)&Cs[s * 128 * G_CS + (r0 + g) * G_CS + lc];
            uint32_t c1 = *(const uint16_t*)&Cs[s * 128 * G_CS + (r0 + g + 8) * G_CS + lc];
            float v;
            v = e1v0 + eA + ((c0 & 1u)   ? rB2 : rA); v = v >= 0.f ? v : ALPHAF * v; sc[nf][0] = (c0 & 2u)   ? v : NEGF;
            v = e1v0 + eB + ((c0 & 256u) ? rB2 : rA); v = v >= 0.f ? v : ALPHAF * v; sc[nf][1] = (c0 & 512u) ? v : NEGF;
            v = e1v1 + eA + ((c1 & 1u)   ? rB2 : rA); v = v >= 0.f ? v : ALPHAF * v; sc[nf][2] = (c1 & 2u)   ? v : NEGF;
            v = e1v1 + eB + ((c1 & 256u) ? rB2 : rA); v = v >= 0.f ? v : ALPHAF * v; sc[nf][3] = (c1 & 512u) ? v : NEGF;
        }

        float mx0 = -3.4e38f, mx1 = -3.4e38f;
        #pragma unroll
        for (int nf = 0; nf < 8; nf++) {
            mx0 = fmaxf(mx0, fmaxf(sc[nf][0], sc[nf][1]));
            mx1 = fmaxf(mx1, fmaxf(sc[nf][2], sc[nf][3]));
        }
        #pragma unroll
        for (int off = 1; off <= 2; off <<= 1) {
            mx0 = fmaxf(mx0, __shfl_xor_sync(0xffffffffu, mx0, off));
            mx1 = fmaxf(mx1, __shfl_xor_sync(0xffffffffu, mx1, off));
        }
        float mn0 = fmaxf(m0, mx0);
        float mn1 = fmaxf(m1, mx1);
        float cr0 = __expf(m0 - mn0);
        float cr1 = __expf(m1 - mn1);
        l0 *= cr0; l1 *= cr1;
        #pragma unroll
        for (int nf = 0; nf < 8; nf++) {
            o[nf][0] *= cr0; o[nf][1] *= cr0;
            o[nf][2] *= cr1; o[nf][3] *= cr1;
        }
        float rs0 = 0.f, rs1 = 0.f;
        #pragma unroll
        for (int nf = 0; nf < 8; nf++) {
            sc[nf][0] = __expf(sc[nf][0] - mn0);
            sc[nf][1] = __expf(sc[nf][1] - mn0);
            sc[nf][2] = __expf(sc[nf][2] - mn1);
            sc[nf][3] = __expf(sc[nf][3] - mn1);
            rs0 += sc[nf][0] + sc[nf][1];
            rs1 += sc[nf][2] + sc[nf][3];
        }
        #pragma unroll
        for (int off = 1; off <= 2; off <<= 1) {
            rs0 += __shfl_xor_sync(0xffffffffu, rs0, off);
            rs1 += __shfl_xor_sync(0xffffffffu, rs1, off);
        }
        l0 += rs0; l1 += rs1; m0 = mn0; m1 = mn1;

        #pragma unroll
        for (int kf = 0; kf < 4; kf++) {
            uint32_t a[4];
            a[0] = pkh2(sc[2 * kf][0],     sc[2 * kf][1]);
            a[1] = pkh2(sc[2 * kf][2],     sc[2 * kf][3]);
            a[2] = pkh2(sc[2 * kf + 1][0], sc[2 * kf + 1][1]);
            a[3] = pkh2(sc[2 * kf + 1][2], sc[2 * kf + 1][3]);
            #pragma unroll
            for (int nf = 0; nf < 8; nf++) {
                uint32_t b2[2];
                const __half* hr = &Hs[(s * JT + nf * 8 + g) * F_ST + kf * 16 + 2 * tg];
                b2[0] = *(uint32_t*)hr;
                b2[1] = *(uint32_t*)(hr + 8);
                mma_f16(o[nf], a, b2);
            }
        }
        __syncthreads();
    }

    float inv0 = 1.f / l0, inv1 = 1.f / l1;
    #pragma unroll
    for (int nf = 0; nf < 8; nf++) {
        int c = nf * 8 + tg * 2;
        float v0 = o[nf][0] * inv0, v1 = o[nf][1] * inv0;
        float v2 = o[nf][2] * inv1, v3 = o[nf][3] * inv1;
        v0 = v0 > 0.f ? v0 : expm1f(v0);
        v1 = v1 > 0.f ? v1 : expm1f(v1);
        v2 = v2 > 0.f ? v2 : expm1f(v2);
        v3 = v3 > 0.f ? v3 : expm1f(v3);
        *(float2*)(AggB + (long)(r0 + g)     * CHID + c) = make_float2(v0, v1);
        *(float2*)(AggB + (long)(r0 + g + 8) * CHID + c) = make_float2(v2, v3);
    }
}

// ---------------- fp32 tiled SGEMM (fc2 only) ----------------
template<int ACT>
__global__ void sgemm(const float* __restrict__ A, const float* __restrict__ Bm,
                      const float* __restrict__ bias, float* __restrict__ C,
                      int M, int N, int K)
{
    __shared__ float As[16][68];
    __shared__ float Bs[16][68];
    int tx = threadIdx.x;
    int tr = tx >> 4, tc = tx & 15;
    int row0 = blockIdx.y * 64, col0 = blockIdx.x * 64;

    float acc[4][4] = {};
    for (int k0 = 0; k0 < K; k0 += 16) {
        #pragma unroll
        for (int i = 0; i < 4; i++) {
            int idx = tx * 4 + i;
            int m = idx >> 4, k = idx & 15;
            int gr = row0 + m;
            As[k][m] = (gr < M) ? A[(long)gr * K + k0 + k] : 0.f;
        }
        #pragma unroll
        for (int i = 0; i < 4; i++) {
            int idx = tx * 4 + i;
            int k = idx >> 6, n = idx & 63;
            int gn = col0 + n;
            Bs[k][n] = (gn < N) ? Bm[(long)(k0 + k) * N + gn] : 0.f;
        }
        __syncthreads();
        #pragma unroll
        for (int k = 0; k < 16; k++) {
            float a[4], b[4];
            #pragma unroll
            for (int i = 0; i < 4; i++) a[i] = As[k][tr * 4 + i];
            #pragma unroll
            for (int j = 0; j < 4; j++) b[j] = Bs[k][tc * 4 + j];
            #pragma unroll
            for (int i = 0; i < 4; i++)
                #pragma unroll
                for (int j = 0; j < 4; j++)
                    acc[i][j] = fmaf(a[i], b[j], acc[i][j]);
        }
        __syncthreads();
    }
    #pragma unroll
    for (int i = 0; i < 4; i++) {
        int gr = row0 + tr * 4 + i;
        if (gr >= M) continue;
        #pragma unroll
        for (int j = 0; j < 4; j++) {
            int gn = col0 + tc * 4 + j;
            if (gn >= N) continue;
            float v = acc[i][j];
            if (bias) v += bias[gn];
            if (ACT == 1) v = v > 0.f ? v : 0.f;
            C[(long)gr * N + gn] = v;
        }
    }
}

// ---------------- logits: warp per row ----------------
__global__ void logits_kernel(const float* __restrict__ H, const float* __restrict__ W,
                              const float* __restrict__ bb, float* __restrict__ out)
{
    int warp = threadIdx.x >> 5, lane = threadIdx.x & 31;
    int row = blockIdx.x * 8 + warp;
    float hv[8];
    #pragma unroll
    for (int j = 0; j < 8; j++) hv[j] = H[(long)row * CHID + j * 32 + lane];
    float acc[CNC];
    #pragma unroll
    for (int c = 0; c < CNC; c++) {
        float a = 0.f;
        #pragma unroll
        for (int j = 0; j < 8; j++) a = fmaf(hv[j], W[(j * 32 + lane) * CNC + c], a);
        acc[c] = a;
    }
    #pragma unroll
    for (int c = 0; c < CNC; c++)
        #pragma unroll
        for (int off = 16; off > 0; off >>= 1)
            acc[c] += __shfl_xor_sync(0xffffffffu, acc[c], off);
    if (lane < CNC) out[(long)row * CNC + lane] = acc[lane] + bb[lane];
}

// ---------------- PW = P @ wk  (tiny GEMM, fp32) ----------------
__global__ void pwk_kernel(const float* __restrict__ P, const float* __restrict__ wk,
                           float* __restrict__ PW)
{
    __shared__ float sp[CHID];
    int r = blockIdx.x, c = threadIdx.x;
    sp[c] = P[(long)r * CHID + c];
    __syncthreads();
    float acc = 0.f;
    #pragma unroll 4
    for (int k = 0; k < CHID; k++) acc = fmaf(sp[k], wk[k * CHID + c], acc);
    PW[(long)r * CHID + c] = acc;
}

// ---------------- Kh[b,n,d] = half( sum_m sadj[b,m,n]*PW[b,m,d] + bk[d] ) ----------------
__global__ void kcomb_kernel(const float* __restrict__ sadj, const float* __restrict__ PW,
                             const float* __restrict__ bk, __half* __restrict__ Kh)
{
    long idx = (long)blockIdx.x * 256 + threadIdx.x;
    int d = idx & (CHID - 1);
    int n = (idx >> 8) & (CN - 1);
    int b = (int)(idx >> 18);
    const float* sa = sadj + (long)b * CM * CN + n;
    const float* Pb = PW + (long)b * CM * CHID + d;
    float acc = bk[d];
    #pragma unroll
    for (int m = 0; m < CM; m++) acc = fmaf(sa[m * CN], Pb[m * CHID], acc);
    Kh[idx] = __float2half_rn(acc);
}

// ---------------- e1/e2 dots from hT (4-way k-split) ----------------
__global__ void dots_kernel(const __half* __restrict__ hT, const float* __restrict__ a1,
                            const float* __restrict__ a2,
                            float* __restrict__ e1, float* __restrict__ e2)
{
    __shared__ float s1[4][64], s2[4][64];
    int bI = blockIdx.x;                      // 0..127
    int b = bI >> 4, jb = bI & 15;
    int jloc = threadIdx.x & 63, part = threadIdx.x >> 6;
    int j = jb * 64 + jloc;
    const __half* base = hT + (long)b * CHID * CN + j;
    float t1 = 0.f, t2 = 0.f;
    #pragma unroll 8
    for (int c = part * 64; c < part * 64 + 64; c++) {
        float v = __half2float(base[(long)c * CN]);
        t1 = fmaf(v, a1[c], t1);
        t2 = fmaf(v, a2[c], t2);
    }
    s1[part][jloc] = t1; s2[part][jloc] = t2;
    __syncthreads();
    if (part == 0) {
        e1[b * CN + j] = s1[0][jloc] + s1[1][jloc] + s1[2][jloc] + s1[3][jloc];
        e2[b * CN + j] = s2[0][jloc] + s2[1][jloc] + s2[2][jloc] + s2[3][jloc];
    }
}

// ---------------- rel_sc ----------------
__global__ void relsc_kernel(const float* __restrict__ rel, const float* __restrict__ a3,
                             float* __restrict__ out)
{
    __shared__ float s[256];
    int r = blockIdx.x, t = threadIdx.x;
    s[t] = rel[r * CHID + t] * a3[t];
    __syncthreads();
    for (int o = 128; o > 0; o >>= 1) {
        if (t < o) s[t] += s[t + o];
        __syncthreads();
    }
    if (t == 0) out[r] = s[0];
}

// ---------------- LayerNorm: warp per row ----------------
__global__ void ln_kernel(const float* __restrict__ T, const float* __restrict__ Hold,
                          const float* __restrict__ g, const float* __restrict__ bb,
                          float* __restrict__ out)
{
    int warp = threadIdx.x >> 5, lane = threadIdx.x & 31;
    int row = blockIdx.x * 8 + warp;
    long base = (long)row * CHID;
    float v[8];
    float s = 0.f;
    #pragma unroll
    for (int j = 0; j < 8; j++) {
        int c = j * 32 + lane;
        v[j] = T[base + c] + Hold[base + c];
        s += v[j];
    }
    #pragma unroll
    for (int off = 16; off > 0; off >>= 1) s += __shfl_xor_sync(0xffffffffu, s, off);
    float mu = s * (1.f / CHID);
    float q = 0.f;
    #pragma unroll
    for (int j = 0; j < 8; j++) { v[j] -= mu; q = fmaf(v[j], v[j], q); }
    #pragma unroll
    for (int off = 16; off > 0; off >>= 1) q += __shfl_xor_sync(0xffffffffu, q, off);
    float rstd = rsqrtf(q * (1.f / CHID) + 1e-5f);
    #pragma unroll
    for (int j = 0; j < 8; j++) {
        int c = j * 32 + lane;
        out[base + c] = v[j] * rstd * g[c] + bb[c];
    }
}

// ---------------- fused P_agg + GRU3d ----------------
__global__ void pagggru_kernel(const float* __restrict__ sadj, const float* __restrict__ Hcur,
                               float* __restrict__ P,
                               const float* __restrict__ wz, const float* __restrict__ uz,
                               const float* __restrict__ wr, const float* __restrict__ ur,
                               const float* __restrict__ w,  const float* __restrict__ u)
{
    __shared__ float sp[CHID], sq[CHID];
    int bm = blockIdx.x;
    int b = bm >> 3;
    int c = threadIdx.x;
    const float* sa = sadj + (long)bm * CN;
    const float* Hb = Hcur + (long)b * CN * CHID + c;
    float acc = 0.f;
    #pragma unroll 4
    for (int n = 0; n < CN; n++) acc = fmaf(sa[n], Hb[(long)n * CHID], acc);
    sq[c] = acc;
    sp[c] = P[(long)bm * CHID + c];
    __syncthreads();
    float az = 0, bz = 0, ar = 0, br = 0, aw = 0, bw = 0;
    #pragma unroll 4
    for (int k = 0; k < CHID; k++) {
        float pk = sp[k], qk = sq[k];
        az = fmaf(pk, wz[k * CHID + c], az); bz = fmaf(qk, uz[k * CHID + c], bz);
        ar = fmaf(pk, wr[k * CHID + c], ar); br = fmaf(qk, ur[k * CHID + c], br);
        aw = fmaf(pk, w [k * CHID + c], aw); bw = fmaf(qk, u [k * CHID + c], bw);
    }
    float z  = 1.f / (1.f + expf(-(az + bz)));
    float rr = 1.f / (1.f + expf(-(ar + br)));
    float hh = tanhf(aw + rr * bw);
    P[(long)bm * CHID + c] = (1.f - z) * sp[c] + z * hh;
}

// ---------------- p_sim ----------------
__global__ void psim_kernel(const float* __restrict__ P, float* __restrict__ outp, int tail)
{
    __shared__ float red[64];
    int t = threadIdx.x;
    int b = t >> 3, m = t & 7;
    const float* Pb = P + (long)b * CM * CHID;
    float s = 0.f;
    for (int k2 = 0; k2 < CM; k2++) {
        if (k2 == m) continue;
        float d = 0.f;
        for (int dd = 0; dd < CHID; dd++)
            d = fmaf(Pb[m * CHID + dd], Pb[k2 * CHID + dd], d);
        s += d;
    }
    red[t] = s; __syncthreads();
    if ((t & 7) < 4) red[t] += red[t + 4]; __syncthreads();
    if ((t & 7) < 2) red[t] += red[t + 2]; __syncthreads();
    if ((t & 7) < 1) red[t] += red[t + 1]; __syncthreads();
    if (tail >= CB) {
        if (t < CB) outp[t] = red[t * 8] / (float)(CM * CM);
    } else {
        if (t == 0) {
            float tot = 0.f;
            for (int b2 = 0; b2 < CB; b2++) tot += red[b2 * 8];
            outp[0] = tot / (float)(CB * CM * CM);
        }
    }
}

// ---------------- host orchestration ----------------
extern "C" void kernel_launch(void* const* d_in, const int* in_sizes, int n_in,
                              void* d_out, int out_size)
{
    const float* x     = (const float*)d_in[0];
    const int*   adj   = (const int*)  d_in[1];
    const int*   smask = (const int*)  d_in[2];
    const float* sf    = (const float*)d_in[3];
    const float* sadj  = (const float*)d_in[4];
    const float* fc1w  = (const float*)d_in[6];
    const float* fc1b  = (const float*)d_in[7];
    const float* fc2w  = (const float*)d_in[8];
    const float* fc2b  = (const float*)d_in[9];
    const float* gatW  = (const float*)d_in[10];
    const float* gata  = (const float*)d_in[11];
    const float* rel   = (const float*)d_in[12];
    const float* gwz   = (const float*)d_in[13];
    const float* guz   = (const float*)d_in[14];
    const float* gwr   = (const float*)d_in[15];
    const float* gur   = (const float*)d_in[16];
    const float* gw    = (const float*)d_in[17];
    const float* gu    = (const float*)d_in[18];
    const float* wv    = (const float*)d_in[19];
    const float* bv    = (const float*)d_in[20];
    const float* wk    = (const float*)d_in[21];
    const float* bk    = (const float*)d_in[22];
    const float* wq    = (const float*)d_in[23];
    const float* bq    = (const float*)d_in[24];
    const float* wo    = (const float*)d_in[25];
    const float* bo    = (const float*)d_in[26];
    const float* lng   = (const float*)d_in[27];
    const float* lnb   = (const float*)d_in[28];
    const float* outw  = (const float*)d_in[29];
    const float* outb  = (const float*)d_in[30];
    float* out = (float*)d_out;

    float *H, *Hn, *P, *PW, *Agg, *ctx, *Tb, *e1, *e2, *rsc;
    __half *Qh, *Kh, *VT, *hT;
    uint8_t* codes;
    cudaGetSymbolAddress((void**)&H,    g_H);
    cudaGetSymbolAddress((void**)&Hn,   g_Hn);
    cudaGetSymbolAddress((void**)&P,    g_P);
    cudaGetSymbolAddress((void**)&PW,   g_PW);
    cudaGetSymbolAddress((void**)&Agg,  g_Agg);
    cudaGetSymbolAddress((void**)&ctx,  g_ctx);
    cudaGetSymbolAddress((void**)&Tb,   g_T);
    cudaGetSymbolAddress((void**)&Qh,   g_Qh);
    cudaGetSymbolAddress((void**)&Kh,   g_Kh);
    cudaGetSymbolAddress((void**)&VT,   g_VT);
    cudaGetSymbolAddress((void**)&hT,   g_hT);
    cudaGetSymbolAddress((void**)&codes, g_codes);
    cudaGetSymbolAddress((void**)&e1,   g_e1);
    cudaGetSymbolAddress((void**)&e2,   g_e2);
    cudaGetSymbolAddress((void**)&rsc,  g_rsc);

    cudaFuncSetAttribute(tgemm<0>, cudaFuncAttributeMaxDynamicSharedMemorySize, SM_TG);
    cudaFuncSetAttribute(tgemm<1>, cudaFuncAttributeMaxDynamicSharedMemorySize, SM_TG);
    cudaFuncSetAttribute(tgemm<4>, cudaFuncAttributeMaxDynamicSharedMemorySize, SM_TG);
    cudaFuncSetAttribute(tgemm_pair, cudaFuncAttributeMaxDynamicSharedMemorySize, SM_TG);
    cudaFuncSetAttribute(flash_kernel, cudaFuncAttributeMaxDynamicSharedMemorySize, SM_FLASH);
    cudaFuncSetAttribute(gatt_kernel, cudaFuncAttributeMaxDynamicSharedMemorySize, SM_GATT);

    dim3 blk(256);
    const int BN = CB * CN;
    const long HH = (long)CHID * CHID;

    pack_codes<<<(int)((long)CB * CN * CN / 4 / 256), blk>>>(adj, smask, codes);
    tgemm<1><<<dim3(2, 64, 1), blk, SM_TG>>>(x, fc1w, fc1b, H, BN, CHID, CDIN, 0, 0, 0, 1.f);
    sgemm<1><<<dim3(4, 1, 1), blk>>>(sf, fc2w, fc2b, P, CB * CM, CHID, CDIN);

    for (int l = 0; l < CL; l++) {
        float* cur = l ? Hn : H;
        float* nxt = l ? H : Hn;

        // K path via associativity: PW = P @ wk (tiny), Kh = sadj^T PW + bk (fp16)
        pwk_kernel<<<CB * CM, blk>>>(P, wk + l * HH, PW);
        kcomb_kernel<<<BN * CHID / 256, blk>>>(sadj, PW, bk + l * CHID, Kh);

        // paired: hT = (cur @ gatW)^T fp16 ; VT = (cur @ wv + bv) head-T fp16
        {
            G2 a;
            a.A[0] = cur;           a.A[1] = cur;
            a.B[0] = gatW + l * HH; a.B[1] = wv + l * HH;
            a.bias[0] = nullptr;    a.bias[1] = bv + l * CHID;
            a.C[0] = (float*)hT;    a.C[1] = (float*)VT;
            a.act[0] = 5;           a.act[1] = 6;
            tgemm_pair<<<dim3(2, 64, 2), blk, SM_TG>>>(a, BN, CHID, CHID);
        }
        dots_kernel<<<CB * 16, blk>>>(hT, gata + l * 3 * CHID, gata + l * 3 * CHID + CHID, e1, e2);
        relsc_kernel<<<2, blk>>>(rel + l * 2 * CHID, gata + l * 3 * CHID + 2 * CHID, rsc);
        gatt_kernel<<<dim3(4, 8, CB), blk, SM_GATT>>>(e1, e2, rsc, codes, hT, Agg);
        // Qh = Agg @ wq + bq (fp16 row-major)
        tgemm<4><<<dim3(2, 64, 1), blk, SM_TG>>>(Agg, wq + l * HH, bq + l * CHID, (float*)Qh,
                                                 BN, CHID, CHID, 0, 0, 0, 1.f);
        flash_kernel<<<dim3(8, 32), blk, SM_FLASH>>>(Qh, Kh, VT, ctx);
        tgemm<0><<<dim3(2, 64, 1), blk, SM_TG>>>(ctx, wo + l * HH, bo + l * CHID, Tb,
                                                 BN, CHID, CHID, 0, 0, 0, 1.f);
        ln_kernel<<<BN / 8, blk>>>(Tb, cur, lng + l * CHID, lnb + l * CHID, nxt);

        pagggru_kernel<<<CB * CM, blk>>>(sadj, cur, P,
                                         gwz + l * HH, guz + l * HH,
                                         gwr + l * HH, gur + l * HH,
                                         gw + l * HH,  gu + l * HH);
    }

    logits_kernel<<<BN / 8, blk>>>(H, outw, outb, out);
    psim_kernel<<<1, 64>>>(P, out + (long)BN * CNC, out_size - BN * CNC);
}

// round 12
// speedup vs baseline: 1.1799x; 1.0150x over previous
#include <cuda_runtime.h>
#include <cuda_fp16.h>
#include <math.h>
#include <stdint.h>

// ---------------- problem constants ----------------
constexpr int CB   = 8;
constexpr int CN   = 1024;
constexpr int CM   = 8;
constexpr int CDIN = 1024;
constexpr int CHID = 256;
constexpr int CL   = 2;
constexpr int CNC  = 7;
constexpr int CDH  = 64;
#define NEGF  (-9e15f)
#define ALPHAF 0.1f

// ---------------- scratch ----------------
__device__ float  g_H   [CB*CN*CHID];
__device__ float  g_Hn  [CB*CN*CHID];
__device__ float  g_P   [CB*CM*CHID];
__device__ float  g_PW  [CB*CM*CHID];
__device__ float  g_Agg [CB*CN*CHID];
__device__ float  g_ctx [CB*CN*CHID];
__device__ float  g_T   [CB*CN*CHID];
__device__ __half g_Qh  [CB*CN*CHID];
__device__ __half g_Kh  [CB*CN*CHID];
__device__ __half g_VT  [CB*CN*CHID];   // [bh][d][j]
__device__ __half g_hT  [CB*CN*CHID];   // [b][c][n]
__device__ uint8_t g_codes[(long)CB*CN*CN];
__device__ float  g_e1  [CB*CN];
__device__ float  g_e2  [CB*CN];
__device__ float  g_rsc [2];

// ---------------- helpers ----------------
__device__ __forceinline__ uint32_t f2tf(float f) {
    uint32_t u;
    asm("cvt.rna.tf32.f32 %0, %1;" : "=r"(u) : "f"(f));
    return u;
}
__device__ __forceinline__ void mma_tf32(float c[4], const uint32_t a[4], const uint32_t b[2]) {
    asm volatile(
        "mma.sync.aligned.m16n8k8.row.col.f32.tf32.tf32.f32 "
        "{%0,%1,%2,%3}, {%4,%5,%6,%7}, {%8,%9}, {%0,%1,%2,%3};\n"
        : "+f"(c[0]), "+f"(c[1]), "+f"(c[2]), "+f"(c[3])
        : "r"(a[0]), "r"(a[1]), "r"(a[2]), "r"(a[3]), "r"(b[0]), "r"(b[1]));
}
__device__ __forceinline__ void mma_f16(float c[4], const uint32_t a[4], const uint32_t b[2]) {
    asm volatile(
        "mma.sync.aligned.m16n8k16.row.col.f32.f16.f16.f32 "
        "{%0,%1,%2,%3}, {%4,%5,%6,%7}, {%8,%9}, {%0,%1,%2,%3};\n"
        : "+f"(c[0]), "+f"(c[1]), "+f"(c[2]), "+f"(c[3])
        : "r"(a[0]), "r"(a[1]), "r"(a[2]), "r"(a[3]), "r"(b[0]), "r"(b[1]));
}
__device__ __forceinline__ uint32_t pkh2(float x, float y) {
    __half2 h = __floats2half2_rn(x, y);
    return *(uint32_t*)&h;
}
__device__ __forceinline__ void cpasync16(uint32_t saddr, const void* gptr) {
    asm volatile("cp.async.cg.shared.global [%0], [%1], 16;\n" :: "r"(saddr), "l"(gptr));
}
__device__ __forceinline__ void cpcommit() { asm volatile("cp.async.commit_group;\n"); }
__device__ __forceinline__ void cpwait0()  { asm volatile("cp.async.wait_group 0;\n"); }
__device__ __forceinline__ void cpwait1()  { asm volatile("cp.async.wait_group 1;\n"); }

// ================= core GEMM tile (128x128, KS=32, 2-stage, 2 CTAs/SM) =================
struct TileCtx {
    float *As, *Bs;
    uint32_t As_b, Bs_b;
    const float *Ag, *Bg;
    int K, N;
    int tid;
};
constexpr int T_strA = 36, T_strB = 132;
constexpr int T_AW = 128 * T_strA, T_BW = 32 * T_strB;
constexpr int SM_TG = (2 * (T_AW + T_BW)) * 4;   // 70656 bytes

__device__ __forceinline__ void tg_load_stage(TileCtx& c, int kt, int s) {
    int k0 = kt * 32;
    #pragma unroll
    for (int i = 0; i < 4; i++) {
        int f = c.tid + i * 256;
        int m = f >> 3, k4 = (f & 7) * 4;
        cpasync16(c.As_b + (uint32_t)(((s * 128 + m) * T_strA + k4) * 4),
                  c.Ag + (long)m * c.K + k0 + k4);
    }
    #pragma unroll
    for (int i = 0; i < 4; i++) {
        int f = c.tid + i * 256;
        int k = f >> 5, n4 = (f & 31) * 4;
        cpasync16(c.Bs_b + (uint32_t)(((s * 32 + k) * T_strB + n4) * 4),
                  c.Bg + (long)(k0 + k) * c.N + n4);
    }
    cpcommit();
}

// act: 0 none, 1 relu, 4 half row-major, 5 half batch-transpose, 6 half head-transpose
__device__ __forceinline__ void tg_body(
    TileCtx& c, const float* bias, float* C, int M, int N, int K,
    int row0, int col0, float scale, int act)
{
    int tid  = c.tid;
    int warp = tid >> 5, lane = tid & 31;
    int g = lane >> 2, tg = lane & 3;
    int mw = warp >> 2, nw = warp & 3;

    float acc[4][4][4];
    #pragma unroll
    for (int mi = 0; mi < 4; mi++)
        #pragma unroll
        for (int ni = 0; ni < 4; ni++)
            #pragma unroll
            for (int q = 0; q < 4; q++) acc[mi][ni][q] = 0.f;

    int nk = K / 32;
    tg_load_stage(c, 0, 0);

    for (int kt = 0; kt < nk; kt++) {
        cpwait0();
        __syncthreads();
        int s = kt & 1;
        if (kt + 1 < nk) tg_load_stage(c, kt + 1, s ^ 1);

        const float* Asb = c.As + s * T_AW;
        const float* Bsb = c.Bs + s * T_BW;
        #pragma unroll
        for (int ks = 0; ks < 32; ks += 8) {
            uint32_t a[4][4], b[4][2];
            #pragma unroll
            for (int mi = 0; mi < 4; mi++) {
                int mr = mw * 64 + mi * 16;
                a[mi][0] = f2tf(Asb[(mr + g)     * T_strA + ks + tg]);
                a[mi][1] = f2tf(Asb[(mr + g + 8) * T_strA + ks + tg]);
                a[mi][2] = f2tf(Asb[(mr + g)     * T_strA + ks + tg + 4]);
                a[mi][3] = f2tf(Asb[(mr + g + 8) * T_strA + ks + tg + 4]);
            }
            #pragma unroll
            for (int ni = 0; ni < 4; ni++) {
                int nc = nw * 32 + ni * 8;
                b[ni][0] = f2tf(Bsb[(ks + tg)     * T_strB + nc + g]);
                b[ni][1] = f2tf(Bsb[(ks + tg + 4) * T_strB + nc + g]);
            }
            #pragma unroll
            for (int mi = 0; mi < 4; mi++)
                #pragma unroll
                for (int ni = 0; ni < 4; ni++)
                    mma_tf32(acc[mi][ni], a[mi], b[ni]);
        }
    }

    #pragma unroll
    for (int mi = 0; mi < 4; mi++) {
        #pragma unroll
        for (int ni = 0; ni < 4; ni++) {
            int r = row0 + mw * 64 + mi * 16 + g;
            int cc0 = col0 + nw * 32 + ni * 8 + tg * 2;
            float b0 = bias ? bias[cc0] : 0.f;
            float b1 = bias ? bias[cc0 + 1] : 0.f;
            #pragma unroll
            for (int rr = 0; rr < 2; rr++) {
                int r_ = r + rr * 8;
                float v0 = acc[mi][ni][rr * 2 + 0] * scale + b0;
                float v1 = acc[mi][ni][rr * 2 + 1] * scale + b1;
                if (act == 0) {
                    *(float2*)(C + (long)r_ * N + cc0) = make_float2(v0, v1);
                } else if (act == 1) {
                    *(float2*)(C + (long)r_ * N + cc0) =
                        make_float2(fmaxf(v0, 0.f), fmaxf(v1, 0.f));
                } else if (act == 4) {
                    __half2 h = __floats2half2_rn(v0, v1);
                    *(__half2*)((__half*)C + (long)r_ * N + cc0) = h;
                } else if (act == 5) {          // hT: [b][c][n]
                    __half* CT = (__half*)C;
                    int b_ = r_ >> 10, j = r_ & 1023;
                    CT[((long)(b_ * CHID + cc0))     * CN + j] = __float2half_rn(v0);
                    CT[((long)(b_ * CHID + cc0 + 1)) * CN + j] = __float2half_rn(v1);
                } else {                        // 6: VT: [bh][d][j]
                    __half* CT = (__half*)C;
                    int bh = r_ >> 8;
                    int j = ((r_ & 255) << 2) | (cc0 >> 6);
                    int d = cc0 & 63;
                    long base = ((long)bh << 16) + ((long)d << 10) + j;
                    CT[base] = __float2half_rn(v0);
                    CT[base + 1024] = __float2half_rn(v1);
                }
            }
        }
    }
}

template<int ACT>
__global__ void __launch_bounds__(256, 2) tgemm(
    const float* __restrict__ A, const float* __restrict__ Bm,
    const float* __restrict__ bias, float* __restrict__ C,
    int M, int N, int K, long sA, long sB, long sC, float scale)
{
    extern __shared__ float smem[];
    int bz = blockIdx.z;
    TileCtx c;
    c.As = smem; c.Bs = smem + 2 * T_AW;
    c.As_b = (uint32_t)__cvta_generic_to_shared(c.As);
    c.Bs_b = (uint32_t)__cvta_generic_to_shared(c.Bs);
    c.K = K; c.N = N; c.tid = threadIdx.x;
    int row0 = blockIdx.y * 128, col0 = blockIdx.x * 128;
    c.Ag = A + (long)bz * sA + (long)row0 * K;
    c.Bg = Bm + (long)bz * sB + col0;
    tg_body(c, bias, C + (long)bz * sC, M, N, K, row0, col0, scale, ACT);
}

struct G2 { const float* A[2]; const float* B[2]; const float* bias[2]; float* C[2]; int act[2]; };
__global__ void __launch_bounds__(256, 2) tgemm_pair(G2 args, int M, int N, int K)
{
    extern __shared__ float smem[];
    int z = blockIdx.z;
    TileCtx c;
    c.As = smem; c.Bs = smem + 2 * T_AW;
    c.As_b = (uint32_t)__cvta_generic_to_shared(c.As);
    c.Bs_b = (uint32_t)__cvta_generic_to_shared(c.Bs);
    c.K = K; c.N = N; c.tid = threadIdx.x;
    int row0 = blockIdx.y * 128, col0 = blockIdx.x * 128;
    c.Ag = args.A[z] + (long)row0 * K;
    c.Bg = args.B[z] + col0;
    tg_body(c, args.bias[z], args.C[z], M, N, K, row0, col0, 1.f, args.act[z]);
}

// ---------------- fp16 flash attention, 64-row KV tiles ----------------
constexpr int F_ST = 72;   // half stride
constexpr int SM_FLASH = (128 * F_ST + 2 * 64 * F_ST + 2 * 64 * F_ST) * 2;  // 55296
__global__ void __launch_bounds__(256, 2) flash_kernel(
    const __half* __restrict__ Q, const __half* __restrict__ Kg_,
    const __half* __restrict__ Vt_, float* __restrict__ O)
{
    constexpr int KT = 64;
    extern __shared__ float smraw[];
    __half* Qs = (__half*)smraw;
    __half* Ks = Qs + 128 * F_ST;
    __half* Vs = Ks + 2 * KT * F_ST;
    uint32_t Qs_b = (uint32_t)__cvta_generic_to_shared(Qs);
    uint32_t Ks_b = (uint32_t)__cvta_generic_to_shared(Ks);
    uint32_t Vs_b = (uint32_t)__cvta_generic_to_shared(Vs);

    int bh = blockIdx.y;
    const __half* Qg = Q + (long)bh * CN * CDH + (long)blockIdx.x * 128 * CDH;
    const __half* Kg = Kg_ + (long)bh * CN * CDH;
    const __half* Vg = Vt_ + ((long)bh << 16);
    float* Og = O + (long)bh * CN * CDH + (long)blockIdx.x * 128 * CDH;

    int tid = threadIdx.x, warp = tid >> 5, lane = tid & 31;
    int g = lane >> 2, tg = lane & 3;
    int r0 = warp * 16;

    #pragma unroll
    for (int i = 0; i < 4; i++) {
        int f = tid + i * 256;
        int r = f >> 3, ch = f & 7;
        cpasync16(Qs_b + (uint32_t)((r * F_ST + ch * 8) * 2), Qg + r * CDH + ch * 8);
    }
    cpcommit();

    auto load_kv = [&](int t, int s) {
        const __half* Kt = Kg + t * KT * CDH;
        const __half* Vtb = Vg + t * KT;
        #pragma unroll
        for (int i = 0; i < 2; i++) {
            int f = tid + i * 256;
            int r = f >> 3, ch = f & 7;
            cpasync16(Ks_b + (uint32_t)(((s * KT + r) * F_ST + ch * 8) * 2),
                      Kt + r * CDH + ch * 8);
        }
        #pragma unroll
        for (int i = 0; i < 2; i++) {
            int f = tid + i * 256;
            int r = f >> 3, ch = f & 7;
            cpasync16(Vs_b + (uint32_t)(((s * KT + r) * F_ST + ch * 8) * 2),
                      Vtb + (long)r * CN + ch * 8);
        }
        cpcommit();
    };
    load_kv(0, 0);

    cpwait1();
    __syncthreads();

    uint32_t aq[4][4];
    #pragma unroll
    for (int kf = 0; kf < 4; kf++) {
        aq[kf][0] = *(uint32_t*)&Qs[(r0 + g)     * F_ST + kf * 16 + 2 * tg];
        aq[kf][1] = *(uint32_t*)&Qs[(r0 + g + 8) * F_ST + kf * 16 + 2 * tg];
        aq[kf][2] = *(uint32_t*)&Qs[(r0 + g)     * F_ST + kf * 16 + 2 * tg + 8];
        aq[kf][3] = *(uint32_t*)&Qs[(r0 + g + 8) * F_ST + kf * 16 + 2 * tg + 8];
    }

    float m0 = -3.4e38f, m1 = -3.4e38f, l0 = 0.f, l1 = 0.f;
    float o[8][4];
    #pragma unroll
    for (int nf = 0; nf < 8; nf++)
        #pragma unroll
        for (int q = 0; q < 4; q++) o[nf][q] = 0.f;

    for (int t = 0; t < 16; t++) {
        int s = t & 1;
        if (t < 15) load_kv(t + 1, s ^ 1);
        if (t < 15) cpwait1(); else cpwait0();
        __syncthreads();

        float sc[8][4];
        #pragma unroll
        for (int nf = 0; nf < 8; nf++)
            #pragma unroll
            for (int q = 0; q < 4; q++) sc[nf][q] = 0.f;
        #pragma unroll
        for (int kf = 0; kf < 4; kf++) {
            #pragma unroll
            for (int nf = 0; nf < 8; nf++) {
                uint32_t b[2];
                const __half* kr = &Ks[(s * KT + nf * 8 + g) * F_ST + kf * 16 + 2 * tg];
                b[0] = *(uint32_t*)kr;
                b[1] = *(uint32_t*)(kr + 8);
                mma_f16(sc[nf], aq[kf], b);
            }
        }

        float mx0 = -3.4e38f, mx1 = -3.4e38f;
        #pragma unroll
        for (int nf = 0; nf < 8; nf++) {
            mx0 = fmaxf(mx0, fmaxf(sc[nf][0], sc[nf][1]));
            mx1 = fmaxf(mx1, fmaxf(sc[nf][2], sc[nf][3]));
        }
        #pragma unroll
        for (int off = 1; off <= 2; off <<= 1) {
            mx0 = fmaxf(mx0, __shfl_xor_sync(0xffffffffu, mx0, off));
            mx1 = fmaxf(mx1, __shfl_xor_sync(0xffffffffu, mx1, off));
        }
        float mn0 = fmaxf(m0, mx0 * 0.125f);
        float mn1 = fmaxf(m1, mx1 * 0.125f);
        float cr0 = __expf(m0 - mn0);
        float cr1 = __expf(m1 - mn1);
        l0 *= cr0; l1 *= cr1;
        #pragma unroll
        for (int nf = 0; nf < 8; nf++) {
            o[nf][0] *= cr0; o[nf][1] *= cr0;
            o[nf][2] *= cr1; o[nf][3] *= cr1;
        }
        float rs0 = 0.f, rs1 = 0.f;
        #pragma unroll
        for (int nf = 0; nf < 8; nf++) {
            sc[nf][0] = __expf(sc[nf][0] * 0.125f - mn0);
            sc[nf][1] = __expf(sc[nf][1] * 0.125f - mn0);
            sc[nf][2] = __expf(sc[nf][2] * 0.125f - mn1);
            sc[nf][3] = __expf(sc[nf][3] * 0.125f - mn1);
            rs0 += sc[nf][0] + sc[nf][1];
            rs1 += sc[nf][2] + sc[nf][3];
        }
        #pragma unroll
        for (int off = 1; off <= 2; off <<= 1) {
            rs0 += __shfl_xor_sync(0xffffffffu, rs0, off);
            rs1 += __shfl_xor_sync(0xffffffffu, rs1, off);
        }
        l0 += rs0; l1 += rs1; m0 = mn0; m1 = mn1;

        #pragma unroll
        for (int kf = 0; kf < 4; kf++) {
            uint32_t a[4];
            a[0] = pkh2(sc[2 * kf][0],     sc[2 * kf][1]);
            a[1] = pkh2(sc[2 * kf][2],     sc[2 * kf][3]);
            a[2] = pkh2(sc[2 * kf + 1][0], sc[2 * kf + 1][1]);
            a[3] = pkh2(sc[2 * kf + 1][2], sc[2 * kf + 1][3]);
            #pragma unroll
            for (int nf = 0; nf < 8; nf++) {
                uint32_t b[2];
                const __half* vr = &Vs[(s * KT + nf * 8 + g) * F_ST + kf * 16 + 2 * tg];
                b[0] = *(uint32_t*)vr;
                b[1] = *(uint32_t*)(vr + 8);
                mma_f16(o[nf], a, b);
            }
        }
        __syncthreads();
    }

    float inv0 = 1.f / l0, inv1 = 1.f / l1;
    #pragma unroll
    for (int nf = 0; nf < 8; nf++) {
        int c = nf * 8 + tg * 2;
        *(float2*)(Og + (long)(r0 + g)     * CDH + c) = make_float2(o[nf][0] * inv0, o[nf][1] * inv0);
        *(float2*)(Og + (long)(r0 + g + 8) * CDH + c) = make_float2(o[nf][2] * inv1, o[nf][3] * inv1);
    }
}

// ---------------- pack adj+smask ----------------
__global__ void pack_codes(const int* __restrict__ adj, const int* __restrict__ smask,
                           uint8_t* __restrict__ codes)
{
    long i = (long)blockIdx.x * 256 + threadIdx.x;
    int4 a = ((const int4*)adj)[i];
    int4 s = ((const int4*)smask)[i];
    uchar4 c;
    c.x = (uint8_t)(((a.x > 0) ? 2 : 0) | (s.x & 1));
    c.y = (uint8_t)(((a.y > 0) ? 2 : 0) | (s.y & 1));
    c.z = (uint8_t)(((a.z > 0) ? 2 : 0) | (s.z & 1));
    c.w = (uint8_t)(((a.w > 0) ? 2 : 0) | (s.w & 1));
    ((uchar4*)codes)[i] = c;
}

// ---------------- fused GAT attention (fp16 PV) ----------------
constexpr int G_CS = 80;
constexpr int SM_GATT = 2 * 64 * F_ST * 2 + CN * 4 + 2 * 128 * G_CS;  // 43008
__global__ void __launch_bounds__(256, 2) gatt_kernel(
    const float* __restrict__ e1, const float* __restrict__ e2,
    const float* __restrict__ rsc, const uint8_t* __restrict__ codes,
    const __half* __restrict__ hT, float* __restrict__ Agg)
{
    constexpr int JT = 64;
    extern __shared__ float smraw[];
    __half* Hs = (__half*)smraw;
    float* e2s = (float*)(Hs + 2 * JT * F_ST);
    uint8_t* Cs = (uint8_t*)(e2s + CN);
    uint32_t Hs_b = (uint32_t)__cvta_generic_to_shared(Hs);
    uint32_t Cs_b = (uint32_t)__cvta_generic_to_shared(Cs);

    int nq = blockIdx.x, ib = blockIdx.y, b = blockIdx.z;
    const __half*  hB  = hT + ((long)(b * CHID + nq * 64)) * CN;
    const uint8_t* cB  = codes + ((long)b * CN + ib * 128) * CN;
    const float*   e2B = e2 + (long)b * CN;
    float* AggB = Agg + ((long)b * CN + ib * 128) * CHID + nq * 64;

    int tid = threadIdx.x, warp = tid >> 5, lane = tid & 31;
    int g = lane >> 2, tg = lane & 3;
    int r0 = warp * 16;

    auto load_jt = [&](int t, int s) {
        #pragma unroll
        for (int i = 0; i < 2; i++) {
            int f = tid + i * 256;
            int r = f >> 3, ch = f & 7;
            cpasync16(Hs_b + (uint32_t)(((s * JT + r) * F_ST + ch * 8) * 2),
                      hB + (long)r * CN + t * JT + ch * 8);
        }
        #pragma unroll
        for (int i = 0; i < 2; i++) {
            int f = tid + i * 256;
            int r = f >> 2, c16 = (f & 3) * 16;
            cpasync16(Cs_b + (uint32_t)(s * 128 * G_CS + r * G_CS + c16),
                      cB + (long)r * CN + t * JT + c16);
        }
        cpcommit();
    };
    load_jt(0, 0);

    ((float4*)e2s)[tid] = ((const float4*)e2B)[tid];
    float e1v0 = e1[(long)b * CN + ib * 128 + r0 + g];
    float e1v1 = e1[(long)b * CN + ib * 128 + r0 + g + 8];
    float rA = rsc[0], rB2 = rsc[1];

    float m0 = -3.4e38f, m1 = -3.4e38f, l0 = 0.f, l1 = 0.f;
    float o[8][4];
    #pragma unroll
    for (int nf = 0; nf < 8; nf++)
        #pragma unroll
        for (int q = 0; q < 4; q++) o[nf][q] = 0.f;

    for (int t = 0; t < 16; t++) {
        int s = t & 1;
        if (t < 15) load_jt(t + 1, s ^ 1);
        if (t < 15) cpwait1(); else cpwait0();
        __syncthreads();

        float sc[8][4];
        #pragma unroll
        for (int nf = 0; nf < 8; nf++) {
            int lc = nf * 8 + tg * 2;
            float eA = e2s[t * JT + lc];
            float eB = e2s[t * JT + lc + 1];
            uint32_t c0 = *(const uint16_t*)&Cs[s * 128 * G_CS + (r0 + g) * G_CS + lc];
            uint32_t c1 = *(const uint16_t*)&Cs[s * 128 * G_CS + (r0 + g + 8) * G_CS + lc];
            float v;
            v = e1v0 + eA + ((c0 & 1u)   ? rB2 : rA); v = v >= 0.f ? v : ALPHAF * v; sc[nf][0] = (c0 & 2u)   ? v : NEGF;
            v = e1v0 + eB + ((c0 & 256u) ? rB2 : rA); v = v >= 0.f ? v : ALPHAF * v; sc[nf][1] = (c0 & 512u) ? v : NEGF;
            v = e1v1 + eA + ((c1 & 1u)   ? rB2 : rA); v = v >= 0.f ? v : ALPHAF * v; sc[nf][2] = (c1 & 2u)   ? v : NEGF;
            v = e1v1 + eB + ((c1 & 256u) ? rB2 : rA); v = v >= 0.f ? v : ALPHAF * v; sc[nf][3] = (c1 & 512u) ? v : NEGF;
        }

        float mx0 = -3.4e38f, mx1 = -3.4e38f;
        #pragma unroll
        for (int nf = 0; nf < 8; nf++) {
            mx0 = fmaxf(mx0, fmaxf(sc[nf][0], sc[nf][1]));
            mx1 = fmaxf(mx1, fmaxf(sc[nf][2], sc[nf][3]));
        }
        #pragma unroll
        for (int off = 1; off <= 2; off <<= 1) {
            mx0 = fmaxf(mx0, __shfl_xor_sync(0xffffffffu, mx0, off));
            mx1 = fmaxf(mx1, __shfl_xor_sync(0xffffffffu, mx1, off));
        }
        float mn0 = fmaxf(m0, mx0);
        float mn1 = fmaxf(m1, mx1);
        float cr0 = __expf(m0 - mn0);
        float cr1 = __expf(m1 - mn1);
        l0 *= cr0; l1 *= cr1;
        #pragma unroll
        for (int nf = 0; nf < 8; nf++) {
            o[nf][0] *= cr0; o[nf][1] *= cr0;
            o[nf][2] *= cr1; o[nf][3] *= cr1;
        }
        float rs0 = 0.f, rs1 = 0.f;
        #pragma unroll
        for (int nf = 0; nf < 8; nf++) {
            sc[nf][0] = __expf(sc[nf][0] - mn0);
            sc[nf][1] = __expf(sc[nf][1] - mn0);
            sc[nf][2] = __expf(sc[nf][2] - mn1);
            sc[nf][3] = __expf(sc[nf][3] - mn1);
            rs0 += sc[nf][0] + sc[nf][1];
            rs1 += sc[nf][2] + sc[nf][3];
        }
        #pragma unroll
        for (int off = 1; off <= 2; off <<= 1) {
            rs0 += __shfl_xor_sync(0xffffffffu, rs0, off);
            rs1 += __shfl_xor_sync(0xffffffffu, rs1, off);
        }
        l0 += rs0; l1 += rs1; m0 = mn0; m1 = mn1;

        #pragma unroll
        for (int kf = 0; kf < 4; kf++) {
            uint32_t a[4];
            a[0] = pkh2(sc[2 * kf][0],     sc[2 * kf][1]);
            a[1] = pkh2(sc[2 * kf][2],     sc[2 * kf][3]);
            a[2] = pkh2(sc[2 * kf + 1][0], sc[2 * kf + 1][1]);
            a[3] = pkh2(sc[2 * kf + 1][2], sc[2 * kf + 1][3]);
            #pragma unroll
            for (int nf = 0; nf < 8; nf++) {
                uint32_t b2[2];
                const __half* hr = &Hs[(s * JT + nf * 8 + g) * F_ST + kf * 16 + 2 * tg];
                b2[0] = *(uint32_t*)hr;
                b2[1] = *(uint32_t*)(hr + 8);
                mma_f16(o[nf], a, b2);
            }
        }
        __syncthreads();
    }

    float inv0 = 1.f / l0, inv1 = 1.f / l1;
    #pragma unroll
    for (int nf = 0; nf < 8; nf++) {
        int c = nf * 8 + tg * 2;
        float v0 = o[nf][0] * inv0, v1 = o[nf][1] * inv0;
        float v2 = o[nf][2] * inv1, v3 = o[nf][3] * inv1;
        v0 = v0 > 0.f ? v0 : expm1f(v0);
        v1 = v1 > 0.f ? v1 : expm1f(v1);
        v2 = v2 > 0.f ? v2 : expm1f(v2);
        v3 = v3 > 0.f ? v3 : expm1f(v3);
        *(float2*)(AggB + (long)(r0 + g)     * CHID + c) = make_float2(v0, v1);
        *(float2*)(AggB + (long)(r0 + g + 8) * CHID + c) = make_float2(v2, v3);
    }
}

// ---------------- fp32 tiled SGEMM (fc2 only) ----------------
template<int ACT>
__global__ void sgemm(const float* __restrict__ A, const float* __restrict__ Bm,
                      const float* __restrict__ bias, float* __restrict__ C,
                      int M, int N, int K)
{
    __shared__ float As[16][68];
    __shared__ float Bs[16][68];
    int tx = threadIdx.x;
    int tr = tx >> 4, tc = tx & 15;
    int row0 = blockIdx.y * 64, col0 = blockIdx.x * 64;

    float acc[4][4] = {};
    for (int k0 = 0; k0 < K; k0 += 16) {
        #pragma unroll
        for (int i = 0; i < 4; i++) {
            int idx = tx * 4 + i;
            int m = idx >> 4, k = idx & 15;
            int gr = row0 + m;
            As[k][m] = (gr < M) ? A[(long)gr * K + k0 + k] : 0.f;
        }
        #pragma unroll
        for (int i = 0; i < 4; i++) {
            int idx = tx * 4 + i;
            int k = idx >> 6, n = idx & 63;
            int gn = col0 + n;
            Bs[k][n] = (gn < N) ? Bm[(long)(k0 + k) * N + gn] : 0.f;
        }
        __syncthreads();
        #pragma unroll
        for (int k = 0; k < 16; k++) {
            float a[4], b[4];
            #pragma unroll
            for (int i = 0; i < 4; i++) a[i] = As[k][tr * 4 + i];
            #pragma unroll
            for (int j = 0; j < 4; j++) b[j] = Bs[k][tc * 4 + j];
            #pragma unroll
            for (int i = 0; i < 4; i++)
                #pragma unroll
                for (int j = 0; j < 4; j++)
                    acc[i][j] = fmaf(a[i], b[j], acc[i][j]);
        }
        __syncthreads();
    }
    #pragma unroll
    for (int i = 0; i < 4; i++) {
        int gr = row0 + tr * 4 + i;
        if (gr >= M) continue;
        #pragma unroll
        for (int j = 0; j < 4; j++) {
            int gn = col0 + tc * 4 + j;
            if (gn >= N) continue;
            float v = acc[i][j];
            if (bias) v += bias[gn];
            if (ACT == 1) v = v > 0.f ? v : 0.f;
            C[(long)gr * N + gn] = v;
        }
    }
}

// ---------------- logits: warp per row ----------------
__global__ void logits_kernel(const float* __restrict__ H, const float* __restrict__ W,
                              const float* __restrict__ bb, float* __restrict__ out)
{
    int warp = threadIdx.x >> 5, lane = threadIdx.x & 31;
    int row = blockIdx.x * 8 + warp;
    float hv[8];
    #pragma unroll
    for (int j = 0; j < 8; j++) hv[j] = H[(long)row * CHID + j * 32 + lane];
    float acc[CNC];
    #pragma unroll
    for (int c = 0; c < CNC; c++) {
        float a = 0.f;
        #pragma unroll
        for (int j = 0; j < 8; j++) a = fmaf(hv[j], W[(j * 32 + lane) * CNC + c], a);
        acc[c] = a;
    }
    #pragma unroll
    for (int c = 0; c < CNC; c++)
        #pragma unroll
        for (int off = 16; off > 0; off >>= 1)
            acc[c] += __shfl_xor_sync(0xffffffffu, acc[c], off);
    if (lane < CNC) out[(long)row * CNC + lane] = acc[lane] + bb[lane];
}

// ---------------- PW = P @ wk  (k-split, 256 blocks) ----------------
__global__ void pwk_kernel(const float* __restrict__ P, const float* __restrict__ wk,
                           float* __restrict__ PW)
{
    __shared__ float red[4][64];
    int r = blockIdx.x, dq = blockIdx.y;          // r: 0..63, dq: 0..3
    int dloc = threadIdx.x & 63, part = threadIdx.x >> 6;
    int d = dq * 64 + dloc;
    const float* Pr = P + (long)r * CHID;
    float acc = 0.f;
    #pragma unroll 8
    for (int k = part * 64; k < part * 64 + 64; k++)
        acc = fmaf(Pr[k], wk[k * CHID + d], acc);
    red[part][dloc] = acc;
    __syncthreads();
    if (part == 0)
        PW[(long)r * CHID + d] = red[0][dloc] + red[1][dloc] + red[2][dloc] + red[3][dloc];
}

// ---------------- Kh[b,n,d] = half( sum_m sadj[b,m,n]*PW[b,m,d] + bk[d] ) ----------------
__global__ void kcomb_kernel(const float* __restrict__ sadj, const float* __restrict__ PW,
                             const float* __restrict__ bk, __half* __restrict__ Kh)
{
    long idx = (long)blockIdx.x * 256 + threadIdx.x;
    int d = idx & (CHID - 1);
    int n = (idx >> 8) & (CN - 1);
    int b = (int)(idx >> 18);
    const float* sa = sadj + (long)b * CM * CN + n;
    const float* Pb = PW + (long)b * CM * CHID + d;
    float acc = bk[d];
    #pragma unroll
    for (int m = 0; m < CM; m++) acc = fmaf(sa[m * CN], Pb[m * CHID], acc);
    Kh[idx] = __float2half_rn(acc);
}

// ---------------- e1/e2 dots from hT (4-way k-split) ----------------
__global__ void dots_kernel(const __half* __restrict__ hT, const float* __restrict__ a1,
                            const float* __restrict__ a2,
                            float* __restrict__ e1, float* __restrict__ e2)
{
    __shared__ float s1[4][64], s2[4][64];
    int bI = blockIdx.x;                      // 0..127
    int b = bI >> 4, jb = bI & 15;
    int jloc = threadIdx.x & 63, part = threadIdx.x >> 6;
    int j = jb * 64 + jloc;
    const __half* base = hT + (long)b * CHID * CN + j;
    float t1 = 0.f, t2 = 0.f;
    #pragma unroll 8
    for (int c = part * 64; c < part * 64 + 64; c++) {
        float v = __half2float(base[(long)c * CN]);
        t1 = fmaf(v, a1[c], t1);
        t2 = fmaf(v, a2[c], t2);
    }
    s1[part][jloc] = t1; s2[part][jloc] = t2;
    __syncthreads();
    if (part == 0) {
        e1[b * CN + j] = s1[0][jloc] + s1[1][jloc] + s1[2][jloc] + s1[3][jloc];
        e2[b * CN + j] = s2[0][jloc] + s2[1][jloc] + s2[2][jloc] + s2[3][jloc];
    }
}

// ---------------- rel_sc ----------------
__global__ void relsc_kernel(const float* __restrict__ rel, const float* __restrict__ a3,
                             float* __restrict__ out)
{
    __shared__ float s[256];
    int r = blockIdx.x, t = threadIdx.x;
    s[t] = rel[r * CHID + t] * a3[t];
    __syncthreads();
    for (int o = 128; o > 0; o >>= 1) {
        if (t < o) s[t] += s[t + o];
        __syncthreads();
    }
    if (t == 0) out[r] = s[0];
}

// ---------------- LayerNorm: warp per row ----------------
__global__ void ln_kernel(const float* __restrict__ T, const float* __restrict__ Hold,
                          const float* __restrict__ g, const float* __restrict__ bb,
                          float* __restrict__ out)
{
    int warp = threadIdx.x >> 5, lane = threadIdx.x & 31;
    int row = blockIdx.x * 8 + warp;
    long base = (long)row * CHID;
    float v[8];
    float s = 0.f;
    #pragma unroll
    for (int j = 0; j < 8; j++) {
        int c = j * 32 + lane;
        v[j] = T[base + c] + Hold[base + c];
        s += v[j];
    }
    #pragma unroll
    for (int off = 16; off > 0; off >>= 1) s += __shfl_xor_sync(0xffffffffu, s, off);
    float mu = s * (1.f / CHID);
    float q = 0.f;
    #pragma unroll
    for (int j = 0; j < 8; j++) { v[j] -= mu; q = fmaf(v[j], v[j], q); }
    #pragma unroll
    for (int off = 16; off > 0; off >>= 1) q += __shfl_xor_sync(0xffffffffu, q, off);
    float rstd = rsqrtf(q * (1.f / CHID) + 1e-5f);
    #pragma unroll
    for (int j = 0; j < 8; j++) {
        int c = j * 32 + lane;
        out[base + c] = v[j] * rstd * g[c] + bb[c];
    }
}

// ---------------- fused P_agg + GRU3d ----------------
__global__ void pagggru_kernel(const float* __restrict__ sadj, const float* __restrict__ Hcur,
                               float* __restrict__ P,
                               const float* __restrict__ wz, const float* __restrict__ uz,
                               const float* __restrict__ wr, const float* __restrict__ ur,
                               const float* __restrict__ w,  const float* __restrict__ u)
{
    __shared__ float sp[CHID], sq[CHID];
    int bm = blockIdx.x;
    int b = bm >> 3;
    int c = threadIdx.x;
    const float* sa = sadj + (long)bm * CN;
    const float* Hb = Hcur + (long)b * CN * CHID + c;
    float acc = 0.f;
    #pragma unroll 4
    for (int n = 0; n < CN; n++) acc = fmaf(sa[n], Hb[(long)n * CHID], acc);
    sq[c] = acc;
    sp[c] = P[(long)bm * CHID + c];
    __syncthreads();
    float az = 0, bz = 0, ar = 0, br = 0, aw = 0, bw = 0;
    #pragma unroll 4
    for (int k = 0; k < CHID; k++) {
        float pk = sp[k], qk = sq[k];
        az = fmaf(pk, wz[k * CHID + c], az); bz = fmaf(qk, uz[k * CHID + c], bz);
        ar = fmaf(pk, wr[k * CHID + c], ar); br = fmaf(qk, ur[k * CHID + c], br);
        aw = fmaf(pk, w [k * CHID + c], aw); bw = fmaf(qk, u [k * CHID + c], bw);
    }
    float z  = 1.f / (1.f + expf(-(az + bz)));
    float rr = 1.f / (1.f + expf(-(ar + br)));
    float hh = tanhf(aw + rr * bw);
    P[(long)bm * CHID + c] = (1.f - z) * sp[c] + z * hh;
}

// ---------------- p_sim ----------------
__global__ void psim_kernel(const float* __restrict__ P, float* __restrict__ outp, int tail)
{
    __shared__ float red[64];
    int t = threadIdx.x;
    int b = t >> 3, m = t & 7;
    const float* Pb = P + (long)b * CM * CHID;
    float s = 0.f;
    for (int k2 = 0; k2 < CM; k2++) {
        if (k2 == m) continue;
        float d = 0.f;
        for (int dd = 0; dd < CHID; dd++)
            d = fmaf(Pb[m * CHID + dd], Pb[k2 * CHID + dd], d);
        s += d;
    }
    red[t] = s; __syncthreads();
    if ((t & 7) < 4) red[t] += red[t + 4]; __syncthreads();
    if ((t & 7) < 2) red[t] += red[t + 2]; __syncthreads();
    if ((t & 7) < 1) red[t] += red[t + 1]; __syncthreads();
    if (tail >= CB) {
        if (t < CB) outp[t] = red[t * 8] / (float)(CM * CM);
    } else {
        if (t == 0) {
            float tot = 0.f;
            for (int b2 = 0; b2 < CB; b2++) tot += red[b2 * 8];
            outp[0] = tot / (float)(CB * CM * CM);
        }
    }
}

// ---------------- host orchestration ----------------
extern "C" void kernel_launch(void* const* d_in, const int* in_sizes, int n_in,
                              void* d_out, int out_size)
{
    const float* x     = (const float*)d_in[0];
    const int*   adj   = (const int*)  d_in[1];
    const int*   smask = (const int*)  d_in[2];
    const float* sf    = (const float*)d_in[3];
    const float* sadj  = (const float*)d_in[4];
    const float* fc1w  = (const float*)d_in[6];
    const float* fc1b  = (const float*)d_in[7];
    const float* fc2w  = (const float*)d_in[8];
    const float* fc2b  = (const float*)d_in[9];
    const float* gatW  = (const float*)d_in[10];
    const float* gata  = (const float*)d_in[11];
    const float* rel   = (const float*)d_in[12];
    const float* gwz   = (const float*)d_in[13];
    const float* guz   = (const float*)d_in[14];
    const float* gwr   = (const float*)d_in[15];
    const float* gur   = (const float*)d_in[16];
    const float* gw    = (const float*)d_in[17];
    const float* gu    = (const float*)d_in[18];
    const float* wv    = (const float*)d_in[19];
    const float* bv    = (const float*)d_in[20];
    const float* wk    = (const float*)d_in[21];
    const float* bk    = (const float*)d_in[22];
    const float* wq    = (const float*)d_in[23];
    const float* bq    = (const float*)d_in[24];
    const float* wo    = (const float*)d_in[25];
    const float* bo    = (const float*)d_in[26];
    const float* lng   = (const float*)d_in[27];
    const float* lnb   = (const float*)d_in[28];
    const float* outw  = (const float*)d_in[29];
    const float* outb  = (const float*)d_in[30];
    float* out = (float*)d_out;

    float *H, *Hn, *P, *PW, *Agg, *ctx, *Tb, *e1, *e2, *rsc;
    __half *Qh, *Kh, *VT, *hT;
    uint8_t* codes;
    cudaGetSymbolAddress((void**)&H,    g_H);
    cudaGetSymbolAddress((void**)&Hn,   g_Hn);
    cudaGetSymbolAddress((void**)&P,    g_P);
    cudaGetSymbolAddress((void**)&PW,   g_PW);
    cudaGetSymbolAddress((void**)&Agg,  g_Agg);
    cudaGetSymbolAddress((void**)&ctx,  g_ctx);
    cudaGetSymbolAddress((void**)&Tb,   g_T);
    cudaGetSymbolAddress((void**)&Qh,   g_Qh);
    cudaGetSymbolAddress((void**)&Kh,   g_Kh);
    cudaGetSymbolAddress((void**)&VT,   g_VT);
    cudaGetSymbolAddress((void**)&hT,   g_hT);
    cudaGetSymbolAddress((void**)&codes, g_codes);
    cudaGetSymbolAddress((void**)&e1,   g_e1);
    cudaGetSymbolAddress((void**)&e2,   g_e2);
    cudaGetSymbolAddress((void**)&rsc,  g_rsc);

    cudaFuncSetAttribute(tgemm<0>, cudaFuncAttributeMaxDynamicSharedMemorySize, SM_TG);
    cudaFuncSetAttribute(tgemm<1>, cudaFuncAttributeMaxDynamicSharedMemorySize, SM_TG);
    cudaFuncSetAttribute(tgemm<4>, cudaFuncAttributeMaxDynamicSharedMemorySize, SM_TG);
    cudaFuncSetAttribute(tgemm_pair, cudaFuncAttributeMaxDynamicSharedMemorySize, SM_TG);
    cudaFuncSetAttribute(flash_kernel, cudaFuncAttributeMaxDynamicSharedMemorySize, SM_FLASH);
    cudaFuncSetAttribute(gatt_kernel, cudaFuncAttributeMaxDynamicSharedMemorySize, SM_GATT);

    dim3 blk(256);
    const int BN = CB * CN;
    const long HH = (long)CHID * CHID;

    pack_codes<<<(int)((long)CB * CN * CN / 4 / 256), blk>>>(adj, smask, codes);
    tgemm<1><<<dim3(2, 64, 1), blk, SM_TG>>>(x, fc1w, fc1b, H, BN, CHID, CDIN, 0, 0, 0, 1.f);
    sgemm<1><<<dim3(4, 1, 1), blk>>>(sf, fc2w, fc2b, P, CB * CM, CHID, CDIN);

    for (int l = 0; l < CL; l++) {
        float* cur = l ? Hn : H;
        float* nxt = l ? H : Hn;

        // K path via associativity: PW = P @ wk (k-split), Kh = sadj^T PW + bk (fp16)
        pwk_kernel<<<dim3(CB * CM, 4), blk>>>(P, wk + l * HH, PW);
        kcomb_kernel<<<BN * CHID / 256, blk>>>(sadj, PW, bk + l * CHID, Kh);

        // paired: hT = (cur @ gatW)^T fp16 ; VT = (cur @ wv + bv) head-T fp16
        {
            G2 a;
            a.A[0] = cur;           a.A[1] = cur;
            a.B[0] = gatW + l * HH; a.B[1] = wv + l * HH;
            a.bias[0] = nullptr;    a.bias[1] = bv + l * CHID;
            a.C[0] = (float*)hT;    a.C[1] = (float*)VT;
            a.act[0] = 5;           a.act[1] = 6;
            tgemm_pair<<<dim3(2, 64, 2), blk, SM_TG>>>(a, BN, CHID, CHID);
        }
        dots_kernel<<<CB * 16, blk>>>(hT, gata + l * 3 * CHID, gata + l * 3 * CHID + CHID, e1, e2);
        relsc_kernel<<<2, blk>>>(rel + l * 2 * CHID, gata + l * 3 * CHID + 2 * CHID, rsc);
        gatt_kernel<<<dim3(4, 8, CB), blk, SM_GATT>>>(e1, e2, rsc, codes, hT, Agg);
        // Qh = Agg @ wq + bq (fp16 row-major)
        tgemm<4><<<dim3(2, 64, 1), blk, SM_TG>>>(Agg, wq + l * HH, bq + l * CHID, (float*)Qh,
                                                 BN, CHID, CHID, 0, 0, 0, 1.f);
        flash_kernel<<<dim3(8, 32), blk, SM_FLASH>>>(Qh, Kh, VT, ctx);
        tgemm<0><<<dim3(2, 64, 1), blk, SM_TG>>>(ctx, wo + l * HH, bo + l * CHID, Tb,
                                                 BN, CHID, CHID, 0, 0, 0, 1.f);
        ln_kernel<<<BN / 8, blk>>>(Tb, cur, lng + l * CHID, lnb + l * CHID, nxt);

        pagggru_kernel<<<CB * CM, blk>>>(sadj, cur, P,
                                         gwz + l * HH, guz + l * HH,
                                         gwr + l * HH, gur + l * HH,
                                         gw + l * HH,  gu + l * HH);
    }

    logits_kernel<<<BN / 8, blk>>>(H, outw, outb, out);
    psim_kernel<<<1, 64>>>(P, out + (long)BN * CNC, out_size - BN * CNC);
}

// round 13
// speedup vs baseline: 1.6566x; 1.4040x over previous
#include <cuda_runtime.h>
#include <cuda_fp16.h>
#include <math.h>
#include <stdint.h>

// ---------------- problem constants ----------------
constexpr int CB   = 8;
constexpr int CN   = 1024;
constexpr int CM   = 8;
constexpr int CDIN = 1024;
constexpr int CHID = 256;
constexpr int CL   = 2;
constexpr int CNC  = 7;
constexpr int CDH  = 64;
#define NEGF  (-9e15f)
#define ALPHAF 0.1f

// ---------------- scratch ----------------
__device__ float  g_H   [CB*CN*CHID];
__device__ float  g_Hn  [CB*CN*CHID];
__device__ float  g_P   [CB*CM*CHID];
__device__ float  g_PW  [CB*CM*CHID];
__device__ float  g_PaggP[4*CB*CM*CHID];    // 4 n-partials
__device__ float  g_Agg [CB*CN*CHID];
__device__ float  g_ctx [CB*CN*CHID];
__device__ float  g_T   [CB*CN*CHID];
__device__ __half g_Qh  [CB*CN*CHID];
__device__ __half g_Kh  [CB*CN*CHID];
__device__ __half g_VT  [CB*CN*CHID];   // [bh][d][j]
__device__ __half g_hT  [CB*CN*CHID];   // [b][c][n]
__device__ uint8_t g_codes[(long)CB*CN*CN];
__device__ float  g_e1  [CB*CN];
__device__ float  g_e2  [CB*CN];
__device__ float  g_rsc [2];

// ---------------- helpers ----------------
__device__ __forceinline__ uint32_t f2tf(float f) {
    uint32_t u;
    asm("cvt.rna.tf32.f32 %0, %1;" : "=r"(u) : "f"(f));
    return u;
}
__device__ __forceinline__ void mma_tf32(float c[4], const uint32_t a[4], const uint32_t b[2]) {
    asm volatile(
        "mma.sync.aligned.m16n8k8.row.col.f32.tf32.tf32.f32 "
        "{%0,%1,%2,%3}, {%4,%5,%6,%7}, {%8,%9}, {%0,%1,%2,%3};\n"
        : "+f"(c[0]), "+f"(c[1]), "+f"(c[2]), "+f"(c[3])
        : "r"(a[0]), "r"(a[1]), "r"(a[2]), "r"(a[3]), "r"(b[0]), "r"(b[1]));
}
__device__ __forceinline__ void mma_f16(float c[4], const uint32_t a[4], const uint32_t b[2]) {
    asm volatile(
        "mma.sync.aligned.m16n8k16.row.col.f32.f16.f16.f32 "
        "{%0,%1,%2,%3}, {%4,%5,%6,%7}, {%8,%9}, {%0,%1,%2,%3};\n"
        : "+f"(c[0]), "+f"(c[1]), "+f"(c[2]), "+f"(c[3])
        : "r"(a[0]), "r"(a[1]), "r"(a[2]), "r"(a[3]), "r"(b[0]), "r"(b[1]));
}
__device__ __forceinline__ uint32_t pkh2(float x, float y) {
    __half2 h = __floats2half2_rn(x, y);
    return *(uint32_t*)&h;
}
__device__ __forceinline__ void cpasync16(uint32_t saddr, const void* gptr) {
    asm volatile("cp.async.cg.shared.global [%0], [%1], 16;\n" :: "r"(saddr), "l"(gptr));
}
__device__ __forceinline__ void cpcommit() { asm volatile("cp.async.commit_group;\n"); }
__device__ __forceinline__ void cpwait0()  { asm volatile("cp.async.wait_group 0;\n"); }
__device__ __forceinline__ void cpwait1()  { asm volatile("cp.async.wait_group 1;\n"); }

// ================= core GEMM tile (128x128, KS=32, 2-stage, 2 CTAs/SM) =================
struct TileCtx {
    float *As, *Bs;
    uint32_t As_b, Bs_b;
    const float *Ag, *Bg;
    int K, N;
    int tid;
};
constexpr int T_strA = 36, T_strB = 132;
constexpr int T_AW = 128 * T_strA, T_BW = 32 * T_strB;
constexpr int SM_TG = (2 * (T_AW + T_BW)) * 4;   // 70656 bytes

__device__ __forceinline__ void tg_load_stage(TileCtx& c, int kt, int s) {
    int k0 = kt * 32;
    #pragma unroll
    for (int i = 0; i < 4; i++) {
        int f = c.tid + i * 256;
        int m = f >> 3, k4 = (f & 7) * 4;
        cpasync16(c.As_b + (uint32_t)(((s * 128 + m) * T_strA + k4) * 4),
                  c.Ag + (long)m * c.K + k0 + k4);
    }
    #pragma unroll
    for (int i = 0; i < 4; i++) {
        int f = c.tid + i * 256;
        int k = f >> 5, n4 = (f & 31) * 4;
        cpasync16(c.Bs_b + (uint32_t)(((s * 32 + k) * T_strB + n4) * 4),
                  c.Bg + (long)(k0 + k) * c.N + n4);
    }
    cpcommit();
}

// act: 0 none, 1 relu, 4 half row-major, 5 half batch-transpose, 6 half head-transpose
__device__ __forceinline__ void tg_body(
    TileCtx& c, const float* bias, float* C, int M, int N, int K,
    int row0, int col0, float scale, int act)
{
    int tid  = c.tid;
    int warp = tid >> 5, lane = tid & 31;
    int g = lane >> 2, tg = lane & 3;
    int mw = warp >> 2, nw = warp & 3;

    float acc[4][4][4];
    #pragma unroll
    for (int mi = 0; mi < 4; mi++)
        #pragma unroll
        for (int ni = 0; ni < 4; ni++)
            #pragma unroll
            for (int q = 0; q < 4; q++) acc[mi][ni][q] = 0.f;

    int nk = K / 32;
    tg_load_stage(c, 0, 0);

    for (int kt = 0; kt < nk; kt++) {
        cpwait0();
        __syncthreads();
        int s = kt & 1;
        if (kt + 1 < nk) tg_load_stage(c, kt + 1, s ^ 1);

        const float* Asb = c.As + s * T_AW;
        const float* Bsb = c.Bs + s * T_BW;
        #pragma unroll
        for (int ks = 0; ks < 32; ks += 8) {
            uint32_t a[4][4], b[4][2];
            #pragma unroll
            for (int mi = 0; mi < 4; mi++) {
                int mr = mw * 64 + mi * 16;
                a[mi][0] = f2tf(Asb[(mr + g)     * T_strA + ks + tg]);
                a[mi][1] = f2tf(Asb[(mr + g + 8) * T_strA + ks + tg]);
                a[mi][2] = f2tf(Asb[(mr + g)     * T_strA + ks + tg + 4]);
                a[mi][3] = f2tf(Asb[(mr + g + 8) * T_strA + ks + tg + 4]);
            }
            #pragma unroll
            for (int ni = 0; ni < 4; ni++) {
                int nc = nw * 32 + ni * 8;
                b[ni][0] = f2tf(Bsb[(ks + tg)     * T_strB + nc + g]);
                b[ni][1] = f2tf(Bsb[(ks + tg + 4) * T_strB + nc + g]);
            }
            #pragma unroll
            for (int mi = 0; mi < 4; mi++)
                #pragma unroll
                for (int ni = 0; ni < 4; ni++)
                    mma_tf32(acc[mi][ni], a[mi], b[ni]);
        }
    }

    #pragma unroll
    for (int mi = 0; mi < 4; mi++) {
        #pragma unroll
        for (int ni = 0; ni < 4; ni++) {
            int r = row0 + mw * 64 + mi * 16 + g;
            int cc0 = col0 + nw * 32 + ni * 8 + tg * 2;
            float b0 = bias ? bias[cc0] : 0.f;
            float b1 = bias ? bias[cc0 + 1] : 0.f;
            #pragma unroll
            for (int rr = 0; rr < 2; rr++) {
                int r_ = r + rr * 8;
                float v0 = acc[mi][ni][rr * 2 + 0] * scale + b0;
                float v1 = acc[mi][ni][rr * 2 + 1] * scale + b1;
                if (act == 0) {
                    *(float2*)(C + (long)r_ * N + cc0) = make_float2(v0, v1);
                } else if (act == 1) {
                    *(float2*)(C + (long)r_ * N + cc0) =
                        make_float2(fmaxf(v0, 0.f), fmaxf(v1, 0.f));
                } else if (act == 4) {
                    __half2 h = __floats2half2_rn(v0, v1);
                    *(__half2*)((__half*)C + (long)r_ * N + cc0) = h;
                } else if (act == 5) {          // hT: [b][c][n]
                    __half* CT = (__half*)C;
                    int b_ = r_ >> 10, j = r_ & 1023;
                    CT[((long)(b_ * CHID + cc0))     * CN + j] = __float2half_rn(v0);
                    CT[((long)(b_ * CHID + cc0 + 1)) * CN + j] = __float2half_rn(v1);
                } else {                        // 6: VT: [bh][d][j]
                    __half* CT = (__half*)C;
                    int bh = r_ >> 8;
                    int j = ((r_ & 255) << 2) | (cc0 >> 6);
                    int d = cc0 & 63;
                    long base = ((long)bh << 16) + ((long)d << 10) + j;
                    CT[base] = __float2half_rn(v0);
                    CT[base + 1024] = __float2half_rn(v1);
                }
            }
        }
    }
}

template<int ACT>
__global__ void __launch_bounds__(256, 2) tgemm(
    const float* __restrict__ A, const float* __restrict__ Bm,
    const float* __restrict__ bias, float* __restrict__ C,
    int M, int N, int K, long sA, long sB, long sC, float scale)
{
    extern __shared__ float smem[];
    int bz = blockIdx.z;
    TileCtx c;
    c.As = smem; c.Bs = smem + 2 * T_AW;
    c.As_b = (uint32_t)__cvta_generic_to_shared(c.As);
    c.Bs_b = (uint32_t)__cvta_generic_to_shared(c.Bs);
    c.K = K; c.N = N; c.tid = threadIdx.x;
    int row0 = blockIdx.y * 128, col0 = blockIdx.x * 128;
    c.Ag = A + (long)bz * sA + (long)row0 * K;
    c.Bg = Bm + (long)bz * sB + col0;
    tg_body(c, bias, C + (long)bz * sC, M, N, K, row0, col0, scale, ACT);
}

struct G2 { const float* A[2]; const float* B[2]; const float* bias[2]; float* C[2]; int act[2]; };
__global__ void __launch_bounds__(256, 2) tgemm_pair(G2 args, int M, int N, int K)
{
    extern __shared__ float smem[];
    int z = blockIdx.z;
    TileCtx c;
    c.As = smem; c.Bs = smem + 2 * T_AW;
    c.As_b = (uint32_t)__cvta_generic_to_shared(c.As);
    c.Bs_b = (uint32_t)__cvta_generic_to_shared(c.Bs);
    c.K = K; c.N = N; c.tid = threadIdx.x;
    int row0 = blockIdx.y * 128, col0 = blockIdx.x * 128;
    c.Ag = args.A[z] + (long)row0 * K;
    c.Bg = args.B[z] + col0;
    tg_body(c, args.bias[z], args.C[z], M, N, K, row0, col0, 1.f, args.act[z]);
}

// ---------------- fp16 flash attention, 64-row KV tiles ----------------
constexpr int F_ST = 72;   // half stride
constexpr int SM_FLASH = (128 * F_ST + 2 * 64 * F_ST + 2 * 64 * F_ST) * 2;  // 55296
__global__ void __launch_bounds__(256, 2) flash_kernel(
    const __half* __restrict__ Q, const __half* __restrict__ Kg_,
    const __half* __restrict__ Vt_, float* __restrict__ O)
{
    constexpr int KT = 64;
    extern __shared__ float smraw[];
    __half* Qs = (__half*)smraw;
    __half* Ks = Qs + 128 * F_ST;
    __half* Vs = Ks + 2 * KT * F_ST;
    uint32_t Qs_b = (uint32_t)__cvta_generic_to_shared(Qs);
    uint32_t Ks_b = (uint32_t)__cvta_generic_to_shared(Ks);
    uint32_t Vs_b = (uint32_t)__cvta_generic_to_shared(Vs);

    int bh = blockIdx.y;
    const __half* Qg = Q + (long)bh * CN * CDH + (long)blockIdx.x * 128 * CDH;
    const __half* Kg = Kg_ + (long)bh * CN * CDH;
    const __half* Vg = Vt_ + ((long)bh << 16);
    float* Og = O + (long)bh * CN * CDH + (long)blockIdx.x * 128 * CDH;

    int tid = threadIdx.x, warp = tid >> 5, lane = tid & 31;
    int g = lane >> 2, tg = lane & 3;
    int r0 = warp * 16;

    #pragma unroll
    for (int i = 0; i < 4; i++) {
        int f = tid + i * 256;
        int r = f >> 3, ch = f & 7;
        cpasync16(Qs_b + (uint32_t)((r * F_ST + ch * 8) * 2), Qg + r * CDH + ch * 8);
    }
    cpcommit();

    auto load_kv = [&](int t, int s) {
        const __half* Kt = Kg + t * KT * CDH;
        const __half* Vtb = Vg + t * KT;
        #pragma unroll
        for (int i = 0; i < 2; i++) {
            int f = tid + i * 256;
            int r = f >> 3, ch = f & 7;
            cpasync16(Ks_b + (uint32_t)(((s * KT + r) * F_ST + ch * 8) * 2),
                      Kt + r * CDH + ch * 8);
        }
        #pragma unroll
        for (int i = 0; i < 2; i++) {
            int f = tid + i * 256;
            int r = f >> 3, ch = f & 7;
            cpasync16(Vs_b + (uint32_t)(((s * KT + r) * F_ST + ch * 8) * 2),
                      Vtb + (long)r * CN + ch * 8);
        }
        cpcommit();
    };
    load_kv(0, 0);

    cpwait1();
    __syncthreads();

    uint32_t aq[4][4];
    #pragma unroll
    for (int kf = 0; kf < 4; kf++) {
        aq[kf][0] = *(uint32_t*)&Qs[(r0 + g)     * F_ST + kf * 16 + 2 * tg];
        aq[kf][1] = *(uint32_t*)&Qs[(r0 + g + 8) * F_ST + kf * 16 + 2 * tg];
        aq[kf][2] = *(uint32_t*)&Qs[(r0 + g)     * F_ST + kf * 16 + 2 * tg + 8];
        aq[kf][3] = *(uint32_t*)&Qs[(r0 + g + 8) * F_ST + kf * 16 + 2 * tg + 8];
    }

    float m0 = -3.4e38f, m1 = -3.4e38f, l0 = 0.f, l1 = 0.f;
    float o[8][4];
    #pragma unroll
    for (int nf = 0; nf < 8; nf++)
        #pragma unroll
        for (int q = 0; q < 4; q++) o[nf][q] = 0.f;

    for (int t = 0; t < 16; t++) {
        int s = t & 1;
        if (t < 15) load_kv(t + 1, s ^ 1);
        if (t < 15) cpwait1(); else cpwait0();
        __syncthreads();

        float sc[8][4];
        #pragma unroll
        for (int nf = 0; nf < 8; nf++)
            #pragma unroll
            for (int q = 0; q < 4; q++) sc[nf][q] = 0.f;
        #pragma unroll
        for (int kf = 0; kf < 4; kf++) {
            #pragma unroll
            for (int nf = 0; nf < 8; nf++) {
                uint32_t b[2];
                const __half* kr = &Ks[(s * KT + nf * 8 + g) * F_ST + kf * 16 + 2 * tg];
                b[0] = *(uint32_t*)kr;
                b[1] = *(uint32_t*)(kr + 8);
                mma_f16(sc[nf], aq[kf], b);
            }
        }

        float mx0 = -3.4e38f, mx1 = -3.4e38f;
        #pragma unroll
        for (int nf = 0; nf < 8; nf++) {
            mx0 = fmaxf(mx0, fmaxf(sc[nf][0], sc[nf][1]));
            mx1 = fmaxf(mx1, fmaxf(sc[nf][2], sc[nf][3]));
        }
        #pragma unroll
        for (int off = 1; off <= 2; off <<= 1) {
            mx0 = fmaxf(mx0, __shfl_xor_sync(0xffffffffu, mx0, off));
            mx1 = fmaxf(mx1, __shfl_xor_sync(0xffffffffu, mx1, off));
        }
        float mn0 = fmaxf(m0, mx0 * 0.125f);
        float mn1 = fmaxf(m1, mx1 * 0.125f);
        float cr0 = __expf(m0 - mn0);
        float cr1 = __expf(m1 - mn1);
        l0 *= cr0; l1 *= cr1;
        #pragma unroll
        for (int nf = 0; nf < 8; nf++) {
            o[nf][0] *= cr0; o[nf][1] *= cr0;
            o[nf][2] *= cr1; o[nf][3] *= cr1;
        }
        float rs0 = 0.f, rs1 = 0.f;
        #pragma unroll
        for (int nf = 0; nf < 8; nf++) {
            sc[nf][0] = __expf(sc[nf][0] * 0.125f - mn0);
            sc[nf][1] = __expf(sc[nf][1] * 0.125f - mn0);
            sc[nf][2] = __expf(sc[nf][2] * 0.125f - mn1);
            sc[nf][3] = __expf(sc[nf][3] * 0.125f - mn1);
            rs0 += sc[nf][0] + sc[nf][1];
            rs1 += sc[nf][2] + sc[nf][3];
        }
        #pragma unroll
        for (int off = 1; off <= 2; off <<= 1) {
            rs0 += __shfl_xor_sync(0xffffffffu, rs0, off);
            rs1 += __shfl_xor_sync(0xffffffffu, rs1, off);
        }
        l0 += rs0; l1 += rs1; m0 = mn0; m1 = mn1;

        #pragma unroll
        for (int kf = 0; kf < 4; kf++) {
            uint32_t a[4];
            a[0] = pkh2(sc[2 * kf][0],     sc[2 * kf][1]);
            a[1] = pkh2(sc[2 * kf][2],     sc[2 * kf][3]);
            a[2] = pkh2(sc[2 * kf + 1][0], sc[2 * kf + 1][1]);
            a[3] = pkh2(sc[2 * kf + 1][2], sc[2 * kf + 1][3]);
            #pragma unroll
            for (int nf = 0; nf < 8; nf++) {
                uint32_t b[2];
                const __half* vr = &Vs[(s * KT + nf * 8 + g) * F_ST + kf * 16 + 2 * tg];
                b[0] = *(uint32_t*)vr;
                b[1] = *(uint32_t*)(vr + 8);
                mma_f16(o[nf], a, b);
            }
        }
        __syncthreads();
    }

    float inv0 = 1.f / l0, inv1 = 1.f / l1;
    #pragma unroll
    for (int nf = 0; nf < 8; nf++) {
        int c = nf * 8 + tg * 2;
        *(float2*)(Og + (long)(r0 + g)     * CDH + c) = make_float2(o[nf][0] * inv0, o[nf][1] * inv0);
        *(float2*)(Og + (long)(r0 + g + 8) * CDH + c) = make_float2(o[nf][2] * inv1, o[nf][3] * inv1);
    }
}

// ---------------- pack adj+smask ----------------
__global__ void pack_codes(const int* __restrict__ adj, const int* __restrict__ smask,
                           uint8_t* __restrict__ codes)
{
    long i = (long)blockIdx.x * 256 + threadIdx.x;
    int4 a = ((const int4*)adj)[i];
    int4 s = ((const int4*)smask)[i];
    uchar4 c;
    c.x = (uint8_t)(((a.x > 0) ? 2 : 0) | (s.x & 1));
    c.y = (uint8_t)(((a.y > 0) ? 2 : 0) | (s.y & 1));
    c.z = (uint8_t)(((a.z > 0) ? 2 : 0) | (s.z & 1));
    c.w = (uint8_t)(((a.w > 0) ? 2 : 0) | (s.w & 1));
    ((uchar4*)codes)[i] = c;
}

// ---------------- fused GAT attention (fp16 PV) ----------------
constexpr int G_CS = 80;
constexpr int SM_GATT = 2 * 64 * F_ST * 2 + CN * 4 + 2 * 128 * G_CS;  // 43008
__global__ void __launch_bounds__(256, 2) gatt_kernel(
    const float* __restrict__ e1, const float* __restrict__ e2,
    const float* __restrict__ rsc, const uint8_t* __restrict__ codes,
    const __half* __restrict__ hT, float* __restrict__ Agg)
{
    constexpr int JT = 64;
    extern __shared__ float smraw[];
    __half* Hs = (__half*)smraw;
    float* e2s = (float*)(Hs + 2 * JT * F_ST);
    uint8_t* Cs = (uint8_t*)(e2s + CN);
    uint32_t Hs_b = (uint32_t)__cvta_generic_to_shared(Hs);
    uint32_t Cs_b = (uint32_t)__cvta_generic_to_shared(Cs);

    int nq = blockIdx.x, ib = blockIdx.y, b = blockIdx.z;
    const __half*  hB  = hT + ((long)(b * CHID + nq * 64)) * CN;
    const uint8_t* cB  = codes + ((long)b * CN + ib * 128) * CN;
    const float*   e2B = e2 + (long)b * CN;
    float* AggB = Agg + ((long)b * CN + ib * 128) * CHID + nq * 64;

    int tid = threadIdx.x, warp = tid >> 5, lane = tid & 31;
    int g = lane >> 2, tg = lane & 3;
    int r0 = warp * 16;

    auto load_jt = [&](int t, int s) {
        #pragma unroll
        for (int i = 0; i < 2; i++) {
            int f = tid + i * 256;
            int r = f >> 3, ch = f & 7;
            cpasync16(Hs_b + (uint32_t)(((s * JT + r) * F_ST + ch * 8) * 2),
                      hB + (long)r * CN + t * JT + ch * 8);
        }
        #pragma unroll
        for (int i = 0; i < 2; i++) {
            int f = tid + i * 256;
            int r = f >> 2, c16 = (f & 3) * 16;
            cpasync16(Cs_b + (uint32_t)(s * 128 * G_CS + r * G_CS + c16),
                      cB + (long)r * CN + t * JT + c16);
        }
        cpcommit();
    };
    load_jt(0, 0);

    ((float4*)e2s)[tid] = ((const float4*)e2B)[tid];
    float e1v0 = e1[(long)b * CN + ib * 128 + r0 + g];
    float e1v1 = e1[(long)b * CN + ib * 128 + r0 + g + 8];
    float rA = rsc[0], rB2 = rsc[1];

    float m0 = -3.4e38f, m1 = -3.4e38f, l0 = 0.f, l1 = 0.f;
    float o[8][4];
    #pragma unroll
    for (int nf = 0; nf < 8; nf++)
        #pragma unroll
        for (int q = 0; q < 4; q++) o[nf][q] = 0.f;

    for (int t = 0; t < 16; t++) {
        int s = t & 1;
        if (t < 15) load_jt(t + 1, s ^ 1);
        if (t < 15) cpwait1(); else cpwait0();
        __syncthreads();

        float sc[8][4];
        #pragma unroll
        for (int nf = 0; nf < 8; nf++) {
            int lc = nf * 8 + tg * 2;
            float eA = e2s[t * JT + lc];
            float eB = e2s[t * JT + lc + 1];
            uint32_t c0 = *(const uint16_t*)&Cs[s * 128 * G_CS + (r0 + g) * G_CS + lc];
            uint32_t c1 = *(const uint16_t*)&Cs[s * 128 * G_CS + (r0 + g + 8) * G_CS + lc];
            float v;
            v = e1v0 + eA + ((c0 & 1u)   ? rB2 : rA); v = v >= 0.f ? v : ALPHAF * v; sc[nf][0] = (c0 & 2u)   ? v : NEGF;
            v = e1v0 + eB + ((c0 & 256u) ? rB2 : rA); v = v >= 0.f ? v : ALPHAF * v; sc[nf][1] = (c0 & 512u) ? v : NEGF;
            v = e1v1 + eA + ((c1 & 1u)   ? rB2 : rA); v = v >= 0.f ? v : ALPHAF * v; sc[nf][2] = (c1 & 2u)   ? v : NEGF;
            v = e1v1 + eB + ((c1 & 256u) ? rB2 : rA); v = v >= 0.f ? v : ALPHAF * v; sc[nf][3] = (c1 & 512u) ? v : NEGF;
        }

        float mx0 = -3.4e38f, mx1 = -3.4e38f;
        #pragma unroll
        for (int nf = 0; nf < 8; nf++) {
            mx0 = fmaxf(mx0, fmaxf(sc[nf][0], sc[nf][1]));
            mx1 = fmaxf(mx1, fmaxf(sc[nf][2], sc[nf][3]));
        }
        #pragma unroll
        for (int off = 1; off <= 2; off <<= 1) {
            mx0 = fmaxf(mx0, __shfl_xor_sync(0xffffffffu, mx0, off));
            mx1 = fmaxf(mx1, __shfl_xor_sync(0xffffffffu, mx1, off));
        }
        float mn0 = fmaxf(m0, mx0);
        float mn1 = fmaxf(m1, mx1);
        float cr0 = __expf(m0 - mn0);
        float cr1 = __expf(m1 - mn1);
        l0 *= cr0; l1 *= cr1;
        #pragma unroll
        for (int nf = 0; nf < 8; nf++) {
            o[nf][0] *= cr0; o[nf][1] *= cr0;
            o[nf][2] *= cr1; o[nf][3] *= cr1;
        }
        float rs0 = 0.f, rs1 = 0.f;
        #pragma unroll
        for (int nf = 0; nf < 8; nf++) {
            sc[nf][0] = __expf(sc[nf][0] - mn0);
            sc[nf][1] = __expf(sc[nf][1] - mn0);
            sc[nf][2] = __expf(sc[nf][2] - mn1);
            sc[nf][3] = __expf(sc[nf][3] - mn1);
            rs0 += sc[nf][0] + sc[nf][1];
            rs1 += sc[nf][2] + sc[nf][3];
        }
        #pragma unroll
        for (int off = 1; off <= 2; off <<= 1) {
            rs0 += __shfl_xor_sync(0xffffffffu, rs0, off);
            rs1 += __shfl_xor_sync(0xffffffffu, rs1, off);
        }
        l0 += rs0; l1 += rs1; m0 = mn0; m1 = mn1;

        #pragma unroll
        for (int kf = 0; kf < 4; kf++) {
            uint32_t a[4];
            a[0] = pkh2(sc[2 * kf][0],     sc[2 * kf][1]);
            a[1] = pkh2(sc[2 * kf][2],     sc[2 * kf][3]);
            a[2] = pkh2(sc[2 * kf + 1][0], sc[2 * kf + 1][1]);
            a[3] = pkh2(sc[2 * kf + 1][2], sc[2 * kf + 1][3]);
            #pragma unroll
            for (int nf = 0; nf < 8; nf++) {
                uint32_t b2[2];
                const __half* hr = &Hs[(s * JT + nf * 8 + g) * F_ST + kf * 16 + 2 * tg];
                b2[0] = *(uint32_t*)hr;
                b2[1] = *(uint32_t*)(hr + 8);
                mma_f16(o[nf], a, b2);
            }
        }
        __syncthreads();
    }

    float inv0 = 1.f / l0, inv1 = 1.f / l1;
    #pragma unroll
    for (int nf = 0; nf < 8; nf++) {
        int c = nf * 8 + tg * 2;
        float v0 = o[nf][0] * inv0, v1 = o[nf][1] * inv0;
        float v2 = o[nf][2] * inv1, v3 = o[nf][3] * inv1;
        v0 = v0 > 0.f ? v0 : expm1f(v0);
        v1 = v1 > 0.f ? v1 : expm1f(v1);
        v2 = v2 > 0.f ? v2 : expm1f(v2);
        v3 = v3 > 0.f ? v3 : expm1f(v3);
        *(float2*)(AggB + (long)(r0 + g)     * CHID + c) = make_float2(v0, v1);
        *(float2*)(AggB + (long)(r0 + g + 8) * CHID + c) = make_float2(v2, v3);
    }
}

// ---------------- fp32 tiled SGEMM (fc2 only) ----------------
template<int ACT>
__global__ void sgemm(const float* __restrict__ A, const float* __restrict__ Bm,
                      const float* __restrict__ bias, float* __restrict__ C,
                      int M, int N, int K)
{
    __shared__ float As[16][68];
    __shared__ float Bs[16][68];
    int tx = threadIdx.x;
    int tr = tx >> 4, tc = tx & 15;
    int row0 = blockIdx.y * 64, col0 = blockIdx.x * 64;

    float acc[4][4] = {};
    for (int k0 = 0; k0 < K; k0 += 16) {
        #pragma unroll
        for (int i = 0; i < 4; i++) {
            int idx = tx * 4 + i;
            int m = idx >> 4, k = idx & 15;
            int gr = row0 + m;
            As[k][m] = (gr < M) ? A[(long)gr * K + k0 + k] : 0.f;
        }
        #pragma unroll
        for (int i = 0; i < 4; i++) {
            int idx = tx * 4 + i;
            int k = idx >> 6, n = idx & 63;
            int gn = col0 + n;
            Bs[k][n] = (gn < N) ? Bm[(long)(k0 + k) * N + gn] : 0.f;
        }
        __syncthreads();
        #pragma unroll
        for (int k = 0; k < 16; k++) {
            float a[4], b[4];
            #pragma unroll
            for (int i = 0; i < 4; i++) a[i] = As[k][tr * 4 + i];
            #pragma unroll
            for (int j = 0; j < 4; j++) b[j] = Bs[k][tc * 4 + j];
            #pragma unroll
            for (int i = 0; i < 4; i++)
                #pragma unroll
                for (int j = 0; j < 4; j++)
                    acc[i][j] = fmaf(a[i], b[j], acc[i][j]);
        }
        __syncthreads();
    }
    #pragma unroll
    for (int i = 0; i < 4; i++) {
        int gr = row0 + tr * 4 + i;
        if (gr >= M) continue;
        #pragma unroll
        for (int j = 0; j < 4; j++) {
            int gn = col0 + tc * 4 + j;
            if (gn >= N) continue;
            float v = acc[i][j];
            if (bias) v += bias[gn];
            if (ACT == 1) v = v > 0.f ? v : 0.f;
            C[(long)gr * N + gn] = v;
        }
    }
}

// ---------------- logits: warp per row ----------------
__global__ void logits_kernel(const float* __restrict__ H, const float* __restrict__ W,
                              const float* __restrict__ bb, float* __restrict__ out)
{
    int warp = threadIdx.x >> 5, lane = threadIdx.x & 31;
    int row = blockIdx.x * 8 + warp;
    float hv[8];
    #pragma unroll
    for (int j = 0; j < 8; j++) hv[j] = H[(long)row * CHID + j * 32 + lane];
    float acc[CNC];
    #pragma unroll
    for (int c = 0; c < CNC; c++) {
        float a = 0.f;
        #pragma unroll
        for (int j = 0; j < 8; j++) a = fmaf(hv[j], W[(j * 32 + lane) * CNC + c], a);
        acc[c] = a;
    }
    #pragma unroll
    for (int c = 0; c < CNC; c++)
        #pragma unroll
        for (int off = 16; off > 0; off >>= 1)
            acc[c] += __shfl_xor_sync(0xffffffffu, acc[c], off);
    if (lane < CNC) out[(long)row * CNC + lane] = acc[lane] + bb[lane];
}

// ---------------- PW = P @ wk  (k-split, ILP accumulators) ----------------
__global__ void pwk_kernel(const float* __restrict__ P, const float* __restrict__ wk,
                           float* __restrict__ PW)
{
    __shared__ float red[4][64];
    int r = blockIdx.x, dq = blockIdx.y;
    int dloc = threadIdx.x & 63, part = threadIdx.x >> 6;
    int d = dq * 64 + dloc;
    const float* Pr = P + (long)r * CHID;
    float a0 = 0.f, a1 = 0.f, a2 = 0.f, a3 = 0.f;
    int k0 = part * 64;
    #pragma unroll 4
    for (int k = 0; k < 64; k += 4) {
        a0 = fmaf(Pr[k0 + k],     wk[(k0 + k)     * CHID + d], a0);
        a1 = fmaf(Pr[k0 + k + 1], wk[(k0 + k + 1) * CHID + d], a1);
        a2 = fmaf(Pr[k0 + k + 2], wk[(k0 + k + 2) * CHID + d], a2);
        a3 = fmaf(Pr[k0 + k + 3], wk[(k0 + k + 3) * CHID + d], a3);
    }
    red[part][dloc] = (a0 + a1) + (a2 + a3);
    __syncthreads();
    if (part == 0)
        PW[(long)r * CHID + d] = red[0][dloc] + red[1][dloc] + red[2][dloc] + red[3][dloc];
}

// ---------------- Kh[b,n,d] = half( sum_m sadj[b,m,n]*PW[b,m,d] + bk[d] ) ----------------
__global__ void kcomb_kernel(const float* __restrict__ sadj, const float* __restrict__ PW,
                             const float* __restrict__ bk, __half* __restrict__ Kh)
{
    long idx = (long)blockIdx.x * 256 + threadIdx.x;
    int d = idx & (CHID - 1);
    int n = (idx >> 8) & (CN - 1);
    int b = (int)(idx >> 18);
    const float* sa = sadj + (long)b * CM * CN + n;
    const float* Pb = PW + (long)b * CM * CHID + d;
    float acc = bk[d];
    #pragma unroll
    for (int m = 0; m < CM; m++) acc = fmaf(sa[m * CN], Pb[m * CHID], acc);
    Kh[idx] = __float2half_rn(acc);
}

// ---------------- e1/e2 dots from hT (4-way k-split) ----------------
__global__ void dots_kernel(const __half* __restrict__ hT, const float* __restrict__ a1,
                            const float* __restrict__ a2,
                            float* __restrict__ e1, float* __restrict__ e2)
{
    __shared__ float s1[4][64], s2[4][64];
    int bI = blockIdx.x;
    int b = bI >> 4, jb = bI & 15;
    int jloc = threadIdx.x & 63, part = threadIdx.x >> 6;
    int j = jb * 64 + jloc;
    const __half* base = hT + (long)b * CHID * CN + j;
    float t1 = 0.f, t2 = 0.f;
    #pragma unroll 8
    for (int c = part * 64; c < part * 64 + 64; c++) {
        float v = __half2float(base[(long)c * CN]);
        t1 = fmaf(v, a1[c], t1);
        t2 = fmaf(v, a2[c], t2);
    }
    s1[part][jloc] = t1; s2[part][jloc] = t2;
    __syncthreads();
    if (part == 0) {
        e1[b * CN + j] = s1[0][jloc] + s1[1][jloc] + s1[2][jloc] + s1[3][jloc];
        e2[b * CN + j] = s2[0][jloc] + s2[1][jloc] + s2[2][jloc] + s2[3][jloc];
    }
}

// ---------------- rel_sc ----------------
__global__ void relsc_kernel(const float* __restrict__ rel, const float* __restrict__ a3,
                             float* __restrict__ out)
{
    __shared__ float s[256];
    int r = blockIdx.x, t = threadIdx.x;
    s[t] = rel[r * CHID + t] * a3[t];
    __syncthreads();
    for (int o = 128; o > 0; o >>= 1) {
        if (t < o) s[t] += s[t + o];
        __syncthreads();
    }
    if (t == 0) out[r] = s[0];
}

// ---------------- LayerNorm: warp per row ----------------
__global__ void ln_kernel(const float* __restrict__ T, const float* __restrict__ Hold,
                          const float* __restrict__ g, const float* __restrict__ bb,
                          float* __restrict__ out)
{
    int warp = threadIdx.x >> 5, lane = threadIdx.x & 31;
    int row = blockIdx.x * 8 + warp;
    long base = (long)row * CHID;
    float v[8];
    float s = 0.f;
    #pragma unroll
    for (int j = 0; j < 8; j++) {
        int c = j * 32 + lane;
        v[j] = T[base + c] + Hold[base + c];
        s += v[j];
    }
    #pragma unroll
    for (int off = 16; off > 0; off >>= 1) s += __shfl_xor_sync(0xffffffffu, s, off);
    float mu = s * (1.f / CHID);
    float q = 0.f;
    #pragma unroll
    for (int j = 0; j < 8; j++) { v[j] -= mu; q = fmaf(v[j], v[j], q); }
    #pragma unroll
    for (int off = 16; off > 0; off >>= 1) q += __shfl_xor_sync(0xffffffffu, q, off);
    float rstd = rsqrtf(q * (1.f / CHID) + 1e-5f);
    #pragma unroll
    for (int j = 0; j < 8; j++) {
        int c = j * 32 + lane;
        out[base + c] = v[j] * rstd * g[c] + bb[c];
    }
}

// ---------------- Pagg partials: grid (64, 4), n-split ----------------
__global__ void pagg_part_kernel(const float* __restrict__ sadj, const float* __restrict__ Hcur,
                                 float* __restrict__ PaggP)
{
    int bm = blockIdx.x, part = blockIdx.y;      // part: 0..3
    int b = bm >> 3;
    int c = threadIdx.x;
    const float* sa = sadj + (long)bm * CN + part * 256;
    const float* Hb = Hcur + ((long)b * CN + part * 256) * CHID + c;
    float a0 = 0.f, a1 = 0.f, a2 = 0.f, a3 = 0.f;
    #pragma unroll 4
    for (int n = 0; n < 256; n += 4) {
        a0 = fmaf(sa[n],     Hb[(long)(n)     * CHID], a0);
        a1 = fmaf(sa[n + 1], Hb[(long)(n + 1) * CHID], a1);
        a2 = fmaf(sa[n + 2], Hb[(long)(n + 2) * CHID], a2);
        a3 = fmaf(sa[n + 3], Hb[(long)(n + 3) * CHID], a3);
    }
    PaggP[((long)part * 64 + bm) * CHID + c] = (a0 + a1) + (a2 + a3);
}

// ---------------- GRU: grid (64, 4 d-chunks), k-split in-block ----------------
__global__ void gru_kernel(const float* __restrict__ PaggP, float* __restrict__ P,
                           float* __restrict__ Pnew,
                           const float* __restrict__ wz, const float* __restrict__ uz,
                           const float* __restrict__ wr, const float* __restrict__ ur,
                           const float* __restrict__ w,  const float* __restrict__ u)
{
    __shared__ float sp[CHID], sq[CHID];
    __shared__ float red[6][4][64];
    int bm = blockIdx.x, dq = blockIdx.y;
    int dloc = threadIdx.x & 63, part = threadIdx.x >> 6;
    int d = dq * 64 + dloc;
    // load P row and combined Pagg row
    sp[threadIdx.x] = P[(long)bm * CHID + threadIdx.x];
    sq[threadIdx.x] = PaggP[(long)bm * CHID + threadIdx.x]
                    + PaggP[((long)64 + bm) * CHID + threadIdx.x]
                    + PaggP[((long)128 + bm) * CHID + threadIdx.x]
                    + PaggP[((long)192 + bm) * CHID + threadIdx.x];
    __syncthreads();
    float az = 0, bz = 0, ar = 0, br = 0, aw = 0, bw = 0;
    int k0 = part * 64;
    #pragma unroll 4
    for (int k = k0; k < k0 + 64; k++) {
        float pk = sp[k], qk = sq[k];
        az = fmaf(pk, wz[k * CHID + d], az); bz = fmaf(qk, uz[k * CHID + d], bz);
        ar = fmaf(pk, wr[k * CHID + d], ar); br = fmaf(qk, ur[k * CHID + d], br);
        aw = fmaf(pk, w [k * CHID + d], aw); bw = fmaf(qk, u [k * CHID + d], bw);
    }
    red[0][part][dloc] = az; red[1][part][dloc] = bz;
    red[2][part][dloc] = ar; red[3][part][dloc] = br;
    red[4][part][dloc] = aw; red[5][part][dloc] = bw;
    __syncthreads();
    if (part == 0) {
        float tz = red[0][0][dloc] + red[0][1][dloc] + red[0][2][dloc] + red[0][3][dloc]
                 + red[1][0][dloc] + red[1][1][dloc] + red[1][2][dloc] + red[1][3][dloc];
        float tr_ = red[2][0][dloc] + red[2][1][dloc] + red[2][2][dloc] + red[2][3][dloc]
                  + red[3][0][dloc] + red[3][1][dloc] + red[3][2][dloc] + red[3][3][dloc];
        float tw = red[4][0][dloc] + red[4][1][dloc] + red[4][2][dloc] + red[4][3][dloc];
        float tu = red[5][0][dloc] + red[5][1][dloc] + red[5][2][dloc] + red[5][3][dloc];
        float z  = 1.f / (1.f + expf(-tz));
        float rr = 1.f / (1.f + expf(-tr_));
        float hh = tanhf(tw + rr * tu);
        Pnew[(long)bm * CHID + d] = (1.f - z) * sp[d] + z * hh;
    }
}

// ---------------- p_sim ----------------
__global__ void psim_kernel(const float* __restrict__ P, float* __restrict__ outp, int tail)
{
    __shared__ float red[64];
    int t = threadIdx.x;
    int b = t >> 3, m = t & 7;
    const float* Pb = P + (long)b * CM * CHID;
    float s = 0.f;
    for (int k2 = 0; k2 < CM; k2++) {
        if (k2 == m) continue;
        float d = 0.f;
        for (int dd = 0; dd < CHID; dd++)
            d = fmaf(Pb[m * CHID + dd], Pb[k2 * CHID + dd], d);
        s += d;
    }
    red[t] = s; __syncthreads();
    if ((t & 7) < 4) red[t] += red[t + 4]; __syncthreads();
    if ((t & 7) < 2) red[t] += red[t + 2]; __syncthreads();
    if ((t & 7) < 1) red[t] += red[t + 1]; __syncthreads();
    if (tail >= CB) {
        if (t < CB) outp[t] = red[t * 8] / (float)(CM * CM);
    } else {
        if (t == 0) {
            float tot = 0.f;
            for (int b2 = 0; b2 < CB; b2++) tot += red[b2 * 8];
            outp[0] = tot / (float)(CB * CM * CM);
        }
    }
}

// ---------------- host orchestration ----------------
extern "C" void kernel_launch(void* const* d_in, const int* in_sizes, int n_in,
                              void* d_out, int out_size)
{
    const float* x     = (const float*)d_in[0];
    const int*   adj   = (const int*)  d_in[1];
    const int*   smask = (const int*)  d_in[2];
    const float* sf    = (const float*)d_in[3];
    const float* sadj  = (const float*)d_in[4];
    const float* fc1w  = (const float*)d_in[6];
    const float* fc1b  = (const float*)d_in[7];
    const float* fc2w  = (const float*)d_in[8];
    const float* fc2b  = (const float*)d_in[9];
    const float* gatW  = (const float*)d_in[10];
    const float* gata  = (const float*)d_in[11];
    const float* rel   = (const float*)d_in[12];
    const float* gwz   = (const float*)d_in[13];
    const float* guz   = (const float*)d_in[14];
    const float* gwr   = (const float*)d_in[15];
    const float* gur   = (const float*)d_in[16];
    const float* gw    = (const float*)d_in[17];
    const float* gu    = (const float*)d_in[18];
    const float* wv    = (const float*)d_in[19];
    const float* bv    = (const float*)d_in[20];
    const float* wk    = (const float*)d_in[21];
    const float* bk    = (const float*)d_in[22];
    const float* wq    = (const float*)d_in[23];
    const float* bq    = (const float*)d_in[24];
    const float* wo    = (const float*)d_in[25];
    const float* bo    = (const float*)d_in[26];
    const float* lng   = (const float*)d_in[27];
    const float* lnb   = (const float*)d_in[28];
    const float* outw  = (const float*)d_in[29];
    const float* outb  = (const float*)d_in[30];
    float* out = (float*)d_out;

    float *H, *Hn, *P, *PW, *PaggP, *Agg, *ctx, *Tb, *e1, *e2, *rsc;
    __half *Qh, *Kh, *VT, *hT;
    uint8_t* codes;
    cudaGetSymbolAddress((void**)&H,    g_H);
    cudaGetSymbolAddress((void**)&Hn,   g_Hn);
    cudaGetSymbolAddress((void**)&P,    g_P);
    cudaGetSymbolAddress((void**)&PW,   g_PW);
    cudaGetSymbolAddress((void**)&PaggP, g_PaggP);
    cudaGetSymbolAddress((void**)&Agg,  g_Agg);
    cudaGetSymbolAddress((void**)&ctx,  g_ctx);
    cudaGetSymbolAddress((void**)&Tb,   g_T);
    cudaGetSymbolAddress((void**)&Qh,   g_Qh);
    cudaGetSymbolAddress((void**)&Kh,   g_Kh);
    cudaGetSymbolAddress((void**)&VT,   g_VT);
    cudaGetSymbolAddress((void**)&hT,   g_hT);
    cudaGetSymbolAddress((void**)&codes, g_codes);
    cudaGetSymbolAddress((void**)&e1,   g_e1);
    cudaGetSymbolAddress((void**)&e2,   g_e2);
    cudaGetSymbolAddress((void**)&rsc,  g_rsc);

    cudaFuncSetAttribute(tgemm<0>, cudaFuncAttributeMaxDynamicSharedMemorySize, SM_TG);
    cudaFuncSetAttribute(tgemm<1>, cudaFuncAttributeMaxDynamicSharedMemorySize, SM_TG);
    cudaFuncSetAttribute(tgemm<4>, cudaFuncAttributeMaxDynamicSharedMemorySize, SM_TG);
    cudaFuncSetAttribute(tgemm_pair, cudaFuncAttributeMaxDynamicSharedMemorySize, SM_TG);
    cudaFuncSetAttribute(flash_kernel, cudaFuncAttributeMaxDynamicSharedMemorySize, SM_FLASH);
    cudaFuncSetAttribute(gatt_kernel, cudaFuncAttributeMaxDynamicSharedMemorySize, SM_GATT);

    dim3 blk(256);
    const int BN = CB * CN;
    const long HH = (long)CHID * CHID;

    pack_codes<<<(int)((long)CB * CN * CN / 4 / 256), blk>>>(adj, smask, codes);
    tgemm<1><<<dim3(2, 64, 1), blk, SM_TG>>>(x, fc1w, fc1b, H, BN, CHID, CDIN, 0, 0, 0, 1.f);
    sgemm<1><<<dim3(4, 1, 1), blk>>>(sf, fc2w, fc2b, P, CB * CM, CHID, CDIN);

    for (int l = 0; l < CL; l++) {
        float* cur = l ? Hn : H;
        float* nxt = l ? H : Hn;

        // K path via associativity
        pwk_kernel<<<dim3(CB * CM, 4), blk>>>(P, wk + l * HH, PW);
        kcomb_kernel<<<BN * CHID / 256, blk>>>(sadj, PW, bk + l * CHID, Kh);

        // paired: hT = (cur @ gatW)^T fp16 ; VT = (cur @ wv + bv) head-T fp16
        {
            G2 a;
            a.A[0] = cur;           a.A[1] = cur;
            a.B[0] = gatW + l * HH; a.B[1] = wv + l * HH;
            a.bias[0] = nullptr;    a.bias[1] = bv + l * CHID;
            a.C[0] = (float*)hT;    a.C[1] = (float*)VT;
            a.act[0] = 5;           a.act[1] = 6;
            tgemm_pair<<<dim3(2, 64, 2), blk, SM_TG>>>(a, BN, CHID, CHID);
        }
        dots_kernel<<<CB * 16, blk>>>(hT, gata + l * 3 * CHID, gata + l * 3 * CHID + CHID, e1, e2);
        relsc_kernel<<<2, blk>>>(rel + l * 2 * CHID, gata + l * 3 * CHID + 2 * CHID, rsc);
        gatt_kernel<<<dim3(4, 8, CB), blk, SM_GATT>>>(e1, e2, rsc, codes, hT, Agg);
        // Qh = Agg @ wq + bq
        tgemm<4><<<dim3(2, 64, 1), blk, SM_TG>>>(Agg, wq + l * HH, bq + l * CHID, (float*)Qh,
                                                 BN, CHID, CHID, 0, 0, 0, 1.f);
        flash_kernel<<<dim3(8, 32), blk, SM_FLASH>>>(Qh, Kh, VT, ctx);
        tgemm<0><<<dim3(2, 64, 1), blk, SM_TG>>>(ctx, wo + l * HH, bo + l * CHID, Tb,
                                                 BN, CHID, CHID, 0, 0, 0, 1.f);
        ln_kernel<<<BN / 8, blk>>>(Tb, cur, lng + l * CHID, lnb + l * CHID, nxt);

        // GRU speaker update (parallelized; uses pre-update H)
        pagg_part_kernel<<<dim3(CB * CM, 4), blk>>>(sadj, cur, PaggP);
        gru_kernel<<<dim3(CB * CM, 4), blk>>>(PaggP, P, P,
                                              gwz + l * HH, guz + l * HH,
                                              gwr + l * HH, gur + l * HH,
                                              gw + l * HH,  gu + l * HH);
    }

    logits_kernel<<<BN / 8, blk>>>(H, outw, outb, out);
    psim_kernel<<<1, 64>>>(P, out + (long)BN * CNC, out_size - BN * CNC);
}

// round 14
// speedup vs baseline: 1.6950x; 1.0232x over previous
#include <cuda_runtime.h>
#include <cuda_fp16.h>
#include <math.h>
#include <stdint.h>

// ---------------- problem constants ----------------
constexpr int CB   = 8;
constexpr int CN   = 1024;
constexpr int CM   = 8;
constexpr int CDIN = 1024;
constexpr int CHID = 256;
constexpr int CL   = 2;
constexpr int CNC  = 7;
constexpr int CDH  = 64;
#define NEGF  (-9e15f)
#define ALPHAF 0.1f
#define L2EF  1.4426950408889634f

// ---------------- scratch ----------------
__device__ float  g_H   [CB*CN*CHID];
__device__ float  g_Hn  [CB*CN*CHID];
__device__ float  g_P   [CB*CM*CHID];
__device__ float  g_PW  [CB*CM*CHID];
__device__ float  g_PaggP[4*CB*CM*CHID];
__device__ float  g_Agg [CB*CN*CHID];
__device__ float  g_ctx [CB*CN*CHID];
__device__ float  g_T   [CB*CN*CHID];
__device__ __half g_Qh  [CB*CN*CHID];
__device__ __half g_Kh  [CB*CN*CHID];
__device__ __half g_VT  [CB*CN*CHID];   // [bh][d][j]
__device__ __half g_hT  [CB*CN*CHID];   // [b][c][n]
__device__ uint8_t g_codes[(long)CB*CN*CN];
__device__ float  g_e1  [CB*CN];
__device__ float  g_e2  [CB*CN];
__device__ float  g_rsc [2];

// ---------------- helpers ----------------
__device__ __forceinline__ uint32_t f2tf(float f) {
    uint32_t u;
    asm("cvt.rna.tf32.f32 %0, %1;" : "=r"(u) : "f"(f));
    return u;
}
__device__ __forceinline__ void mma_tf32(float c[4], const uint32_t a[4], const uint32_t b[2]) {
    asm volatile(
        "mma.sync.aligned.m16n8k8.row.col.f32.tf32.tf32.f32 "
        "{%0,%1,%2,%3}, {%4,%5,%6,%7}, {%8,%9}, {%0,%1,%2,%3};\n"
        : "+f"(c[0]), "+f"(c[1]), "+f"(c[2]), "+f"(c[3])
        : "r"(a[0]), "r"(a[1]), "r"(a[2]), "r"(a[3]), "r"(b[0]), "r"(b[1]));
}
__device__ __forceinline__ void mma_f16(float c[4], const uint32_t a[4], const uint32_t b[2]) {
    asm volatile(
        "mma.sync.aligned.m16n8k16.row.col.f32.f16.f16.f32 "
        "{%0,%1,%2,%3}, {%4,%5,%6,%7}, {%8,%9}, {%0,%1,%2,%3};\n"
        : "+f"(c[0]), "+f"(c[1]), "+f"(c[2]), "+f"(c[3])
        : "r"(a[0]), "r"(a[1]), "r"(a[2]), "r"(a[3]), "r"(b[0]), "r"(b[1]));
}
// 2 exponentials (base-2) in one MUFU op; inputs are log2-domain floats.
__device__ __forceinline__ uint32_t ex2h2(float x, float y) {
    __half2 h = __floats2half2_rn(x, y);
    uint32_t r;
    asm("ex2.approx.f16x2 %0, %1;" : "=r"(r) : "r"(*(uint32_t*)&h));
    return r;
}
__device__ __forceinline__ void cpasync16(uint32_t saddr, const void* gptr) {
    asm volatile("cp.async.cg.shared.global [%0], [%1], 16;\n" :: "r"(saddr), "l"(gptr));
}
__device__ __forceinline__ void cpcommit() { asm volatile("cp.async.commit_group;\n"); }
__device__ __forceinline__ void cpwait0()  { asm volatile("cp.async.wait_group 0;\n"); }
__device__ __forceinline__ void cpwait1()  { asm volatile("cp.async.wait_group 1;\n"); }

// ================= core GEMM tile (128x128, KS=32, 2-stage, 2 CTAs/SM) =================
struct TileCtx {
    float *As, *Bs;
    uint32_t As_b, Bs_b;
    const float *Ag, *Bg;
    int K, N;
    int tid;
};
constexpr int T_strA = 36, T_strB = 132;
constexpr int T_AW = 128 * T_strA, T_BW = 32 * T_strB;
constexpr int SM_TG = (2 * (T_AW + T_BW)) * 4;   // 70656 bytes

__device__ __forceinline__ void tg_load_stage(TileCtx& c, int kt, int s) {
    int k0 = kt * 32;
    #pragma unroll
    for (int i = 0; i < 4; i++) {
        int f = c.tid + i * 256;
        int m = f >> 3, k4 = (f & 7) * 4;
        cpasync16(c.As_b + (uint32_t)(((s * 128 + m) * T_strA + k4) * 4),
                  c.Ag + (long)m * c.K + k0 + k4);
    }
    #pragma unroll
    for (int i = 0; i < 4; i++) {
        int f = c.tid + i * 256;
        int k = f >> 5, n4 = (f & 31) * 4;
        cpasync16(c.Bs_b + (uint32_t)(((s * 32 + k) * T_strB + n4) * 4),
                  c.Bg + (long)(k0 + k) * c.N + n4);
    }
    cpcommit();
}

// act: 0 none, 1 relu, 4 half row-major, 5 half batch-transpose, 6 half head-transpose
__device__ __forceinline__ void tg_body(
    TileCtx& c, const float* bias, float* C, int M, int N, int K,
    int row0, int col0, float scale, int act)
{
    int tid  = c.tid;
    int warp = tid >> 5, lane = tid & 31;
    int g = lane >> 2, tg = lane & 3;
    int mw = warp >> 2, nw = warp & 3;

    float acc[4][4][4];
    #pragma unroll
    for (int mi = 0; mi < 4; mi++)
        #pragma unroll
        for (int ni = 0; ni < 4; ni++)
            #pragma unroll
            for (int q = 0; q < 4; q++) acc[mi][ni][q] = 0.f;

    int nk = K / 32;
    tg_load_stage(c, 0, 0);

    for (int kt = 0; kt < nk; kt++) {
        cpwait0();
        __syncthreads();
        int s = kt & 1;
        if (kt + 1 < nk) tg_load_stage(c, kt + 1, s ^ 1);

        const float* Asb = c.As + s * T_AW;
        const float* Bsb = c.Bs + s * T_BW;
        #pragma unroll
        for (int ks = 0; ks < 32; ks += 8) {
            uint32_t a[4][4], b[4][2];
            #pragma unroll
            for (int mi = 0; mi < 4; mi++) {
                int mr = mw * 64 + mi * 16;
                a[mi][0] = f2tf(Asb[(mr + g)     * T_strA + ks + tg]);
                a[mi][1] = f2tf(Asb[(mr + g + 8) * T_strA + ks + tg]);
                a[mi][2] = f2tf(Asb[(mr + g)     * T_strA + ks + tg + 4]);
                a[mi][3] = f2tf(Asb[(mr + g + 8) * T_strA + ks + tg + 4]);
            }
            #pragma unroll
            for (int ni = 0; ni < 4; ni++) {
                int nc = nw * 32 + ni * 8;
                b[ni][0] = f2tf(Bsb[(ks + tg)     * T_strB + nc + g]);
                b[ni][1] = f2tf(Bsb[(ks + tg + 4) * T_strB + nc + g]);
            }
            #pragma unroll
            for (int mi = 0; mi < 4; mi++)
                #pragma unroll
                for (int ni = 0; ni < 4; ni++)
                    mma_tf32(acc[mi][ni], a[mi], b[ni]);
        }
    }

    #pragma unroll
    for (int mi = 0; mi < 4; mi++) {
        #pragma unroll
        for (int ni = 0; ni < 4; ni++) {
            int r = row0 + mw * 64 + mi * 16 + g;
            int cc0 = col0 + nw * 32 + ni * 8 + tg * 2;
            float b0 = bias ? bias[cc0] : 0.f;
            float b1 = bias ? bias[cc0 + 1] : 0.f;
            #pragma unroll
            for (int rr = 0; rr < 2; rr++) {
                int r_ = r + rr * 8;
                float v0 = acc[mi][ni][rr * 2 + 0] * scale + b0;
                float v1 = acc[mi][ni][rr * 2 + 1] * scale + b1;
                if (act == 0) {
                    *(float2*)(C + (long)r_ * N + cc0) = make_float2(v0, v1);
                } else if (act == 1) {
                    *(float2*)(C + (long)r_ * N + cc0) =
                        make_float2(fmaxf(v0, 0.f), fmaxf(v1, 0.f));
                } else if (act == 4) {
                    __half2 h = __floats2half2_rn(v0, v1);
                    *(__half2*)((__half*)C + (long)r_ * N + cc0) = h;
                } else if (act == 5) {          // hT: [b][c][n]
                    __half* CT = (__half*)C;
                    int b_ = r_ >> 10, j = r_ & 1023;
                    CT[((long)(b_ * CHID + cc0))     * CN + j] = __float2half_rn(v0);
                    CT[((long)(b_ * CHID + cc0 + 1)) * CN + j] = __float2half_rn(v1);
                } else {                        // 6: VT: [bh][d][j]
                    __half* CT = (__half*)C;
                    int bh = r_ >> 8;
                    int j = ((r_ & 255) << 2) | (cc0 >> 6);
                    int d = cc0 & 63;
                    long base = ((long)bh << 16) + ((long)d << 10) + j;
                    CT[base] = __float2half_rn(v0);
                    CT[base + 1024] = __float2half_rn(v1);
                }
            }
        }
    }
}

template<int ACT>
__global__ void __launch_bounds__(256, 2) tgemm(
    const float* __restrict__ A, const float* __restrict__ Bm,
    const float* __restrict__ bias, float* __restrict__ C,
    int M, int N, int K, long sA, long sB, long sC, float scale)
{
    extern __shared__ float smem[];
    int bz = blockIdx.z;
    TileCtx c;
    c.As = smem; c.Bs = smem + 2 * T_AW;
    c.As_b = (uint32_t)__cvta_generic_to_shared(c.As);
    c.Bs_b = (uint32_t)__cvta_generic_to_shared(c.Bs);
    c.K = K; c.N = N; c.tid = threadIdx.x;
    int row0 = blockIdx.y * 128, col0 = blockIdx.x * 128;
    c.Ag = A + (long)bz * sA + (long)row0 * K;
    c.Bg = Bm + (long)bz * sB + col0;
    tg_body(c, bias, C + (long)bz * sC, M, N, K, row0, col0, scale, ACT);
}

struct G2 { const float* A[2]; const float* B[2]; const float* bias[2]; float* C[2]; int act[2]; };
__global__ void __launch_bounds__(256, 2) tgemm_pair(G2 args, int M, int N, int K)
{
    extern __shared__ float smem[];
    int z = blockIdx.z;
    TileCtx c;
    c.As = smem; c.Bs = smem + 2 * T_AW;
    c.As_b = (uint32_t)__cvta_generic_to_shared(c.As);
    c.Bs_b = (uint32_t)__cvta_generic_to_shared(c.Bs);
    c.K = K; c.N = N; c.tid = threadIdx.x;
    int row0 = blockIdx.y * 128, col0 = blockIdx.x * 128;
    c.Ag = args.A[z] + (long)row0 * K;
    c.Bg = args.B[z] + col0;
    tg_body(c, args.bias[z], args.C[z], M, N, K, row0, col0, 1.f, args.act[z]);
}

// ---------------- fp16 flash attention, 64-row KV tiles, f16x2 exp ----------------
constexpr int F_ST = 72;   // half stride
constexpr int SM_FLASH = (128 * F_ST + 2 * 64 * F_ST + 2 * 64 * F_ST) * 2;  // 55296
__global__ void __launch_bounds__(256, 2) flash_kernel(
    const __half* __restrict__ Q, const __half* __restrict__ Kg_,
    const __half* __restrict__ Vt_, float* __restrict__ O)
{
    constexpr int KT = 64;
    extern __shared__ float smraw[];
    __half* Qs = (__half*)smraw;
    __half* Ks = Qs + 128 * F_ST;
    __half* Vs = Ks + 2 * KT * F_ST;
    uint32_t Qs_b = (uint32_t)__cvta_generic_to_shared(Qs);
    uint32_t Ks_b = (uint32_t)__cvta_generic_to_shared(Ks);
    uint32_t Vs_b = (uint32_t)__cvta_generic_to_shared(Vs);

    int bh = blockIdx.y;
    const __half* Qg = Q + (long)bh * CN * CDH + (long)blockIdx.x * 128 * CDH;
    const __half* Kg = Kg_ + (long)bh * CN * CDH;
    const __half* Vg = Vt_ + ((long)bh << 16);
    float* Og = O + (long)bh * CN * CDH + (long)blockIdx.x * 128 * CDH;

    int tid = threadIdx.x, warp = tid >> 5, lane = tid & 31;
    int g = lane >> 2, tg = lane & 3;
    int r0 = warp * 16;

    #pragma unroll
    for (int i = 0; i < 4; i++) {
        int f = tid + i * 256;
        int r = f >> 3, ch = f & 7;
        cpasync16(Qs_b + (uint32_t)((r * F_ST + ch * 8) * 2), Qg + r * CDH + ch * 8);
    }
    cpcommit();

    auto load_kv = [&](int t, int s) {
        const __half* Kt = Kg + t * KT * CDH;
        const __half* Vtb = Vg + t * KT;
        #pragma unroll
        for (int i = 0; i < 2; i++) {
            int f = tid + i * 256;
            int r = f >> 3, ch = f & 7;
            cpasync16(Ks_b + (uint32_t)(((s * KT + r) * F_ST + ch * 8) * 2),
                      Kt + r * CDH + ch * 8);
        }
        #pragma unroll
        for (int i = 0; i < 2; i++) {
            int f = tid + i * 256;
            int r = f >> 3, ch = f & 7;
            cpasync16(Vs_b + (uint32_t)(((s * KT + r) * F_ST + ch * 8) * 2),
                      Vtb + (long)r * CN + ch * 8);
        }
        cpcommit();
    };
    load_kv(0, 0);

    cpwait1();
    __syncthreads();

    uint32_t aq[4][4];
    #pragma unroll
    for (int kf = 0; kf < 4; kf++) {
        aq[kf][0] = *(uint32_t*)&Qs[(r0 + g)     * F_ST + kf * 16 + 2 * tg];
        aq[kf][1] = *(uint32_t*)&Qs[(r0 + g + 8) * F_ST + kf * 16 + 2 * tg];
        aq[kf][2] = *(uint32_t*)&Qs[(r0 + g)     * F_ST + kf * 16 + 2 * tg + 8];
        aq[kf][3] = *(uint32_t*)&Qs[(r0 + g + 8) * F_ST + kf * 16 + 2 * tg + 8];
    }

    const uint32_t bones[2] = {0x3C003C00u, 0x3C003C00u};
    float m0 = -3.4e38f, m1 = -3.4e38f;
    float lacc[4] = {0.f, 0.f, 0.f, 0.f};
    float o[8][4];
    #pragma unroll
    for (int nf = 0; nf < 8; nf++)
        #pragma unroll
        for (int q = 0; q < 4; q++) o[nf][q] = 0.f;

    for (int t = 0; t < 16; t++) {
        int s = t & 1;
        if (t < 15) load_kv(t + 1, s ^ 1);
        if (t < 15) cpwait1(); else cpwait0();
        __syncthreads();

        float sc[8][4];
        #pragma unroll
        for (int nf = 0; nf < 8; nf++)
            #pragma unroll
            for (int q = 0; q < 4; q++) sc[nf][q] = 0.f;
        #pragma unroll
        for (int kf = 0; kf < 4; kf++) {
            #pragma unroll
            for (int nf = 0; nf < 8; nf++) {
                uint32_t b[2];
                const __half* kr = &Ks[(s * KT + nf * 8 + g) * F_ST + kf * 16 + 2 * tg];
                b[0] = *(uint32_t*)kr;
                b[1] = *(uint32_t*)(kr + 8);
                mma_f16(sc[nf], aq[kf], b);
            }
        }

        float mx0 = -3.4e38f, mx1 = -3.4e38f;
        #pragma unroll
        for (int nf = 0; nf < 8; nf++) {
            mx0 = fmaxf(mx0, fmaxf(sc[nf][0], sc[nf][1]));
            mx1 = fmaxf(mx1, fmaxf(sc[nf][2], sc[nf][3]));
        }
        #pragma unroll
        for (int off = 1; off <= 2; off <<= 1) {
            mx0 = fmaxf(mx0, __shfl_xor_sync(0xffffffffu, mx0, off));
            mx1 = fmaxf(mx1, __shfl_xor_sync(0xffffffffu, mx1, off));
        }
        float mn0 = fmaxf(m0, mx0 * 0.125f);
        float mn1 = fmaxf(m1, mx1 * 0.125f);
        float cr0 = __expf(m0 - mn0);
        float cr1 = __expf(m1 - mn1);
        lacc[0] *= cr0; lacc[1] *= cr0; lacc[2] *= cr1; lacc[3] *= cr1;
        #pragma unroll
        for (int nf = 0; nf < 8; nf++) {
            o[nf][0] *= cr0; o[nf][1] *= cr0;
            o[nf][2] *= cr1; o[nf][3] *= cr1;
        }
        m0 = mn0; m1 = mn1;

        // p in fp16 pairs via f16x2 ex2 (log2-domain)
        constexpr float CSC = 0.125f * L2EF;
        float mnl0 = mn0 * L2EF, mnl1 = mn1 * L2EF;
        uint32_t ph[8][2];
        #pragma unroll
        for (int nf = 0; nf < 8; nf++) {
            ph[nf][0] = ex2h2(fmaf(sc[nf][0], CSC, -mnl0), fmaf(sc[nf][1], CSC, -mnl0));
            ph[nf][1] = ex2h2(fmaf(sc[nf][2], CSC, -mnl1), fmaf(sc[nf][3], CSC, -mnl1));
        }

        // O += P @ V ; l += P @ ones
        #pragma unroll
        for (int kf = 0; kf < 4; kf++) {
            uint32_t a[4];
            a[0] = ph[2 * kf][0];
            a[1] = ph[2 * kf][1];
            a[2] = ph[2 * kf + 1][0];
            a[3] = ph[2 * kf + 1][1];
            mma_f16(lacc, a, bones);
            #pragma unroll
            for (int nf = 0; nf < 8; nf++) {
                uint32_t b[2];
                const __half* vr = &Vs[(s * KT + nf * 8 + g) * F_ST + kf * 16 + 2 * tg];
                b[0] = *(uint32_t*)vr;
                b[1] = *(uint32_t*)(vr + 8);
                mma_f16(o[nf], a, b);
            }
        }
        __syncthreads();
    }

    float inv0 = 1.f / lacc[0], inv1 = 1.f / lacc[2];
    #pragma unroll
    for (int nf = 0; nf < 8; nf++) {
        int c = nf * 8 + tg * 2;
        *(float2*)(Og + (long)(r0 + g)     * CDH + c) = make_float2(o[nf][0] * inv0, o[nf][1] * inv0);
        *(float2*)(Og + (long)(r0 + g + 8) * CDH + c) = make_float2(o[nf][2] * inv1, o[nf][3] * inv1);
    }
}

// ---------------- pack adj+smask ----------------
__global__ void pack_codes(const int* __restrict__ adj, const int* __restrict__ smask,
                           uint8_t* __restrict__ codes)
{
    long i = (long)blockIdx.x * 256 + threadIdx.x;
    int4 a = ((const int4*)adj)[i];
    int4 s = ((const int4*)smask)[i];
    uchar4 c;
    c.x = (uint8_t)(((a.x > 0) ? 2 : 0) | (s.x & 1));
    c.y = (uint8_t)(((a.y > 0) ? 2 : 0) | (s.y & 1));
    c.z = (uint8_t)(((a.z > 0) ? 2 : 0) | (s.z & 1));
    c.w = (uint8_t)(((a.w > 0) ? 2 : 0) | (s.w & 1));
    ((uchar4*)codes)[i] = c;
}

// ---------------- fused GAT attention (fp16 PV, f16x2 exp) ----------------
constexpr int G_CS = 80;
constexpr int SM_GATT = 2 * 64 * F_ST * 2 + CN * 4 + 2 * 128 * G_CS;  // 43008
__global__ void __launch_bounds__(256, 2) gatt_kernel(
    const float* __restrict__ e1, const float* __restrict__ e2,
    const float* __restrict__ rsc, const uint8_t* __restrict__ codes,
    const __half* __restrict__ hT, float* __restrict__ Agg)
{
    constexpr int JT = 64;
    extern __shared__ float smraw[];
    __half* Hs = (__half*)smraw;
    float* e2s = (float*)(Hs + 2 * JT * F_ST);
    uint8_t* Cs = (uint8_t*)(e2s + CN);
    uint32_t Hs_b = (uint32_t)__cvta_generic_to_shared(Hs);
    uint32_t Cs_b = (uint32_t)__cvta_generic_to_shared(Cs);

    int nq = blockIdx.x, ib = blockIdx.y, b = blockIdx.z;
    const __half*  hB  = hT + ((long)(b * CHID + nq * 64)) * CN;
    const uint8_t* cB  = codes + ((long)b * CN + ib * 128) * CN;
    const float*   e2B = e2 + (long)b * CN;
    float* AggB = Agg + ((long)b * CN + ib * 128) * CHID + nq * 64;

    int tid = threadIdx.x, warp = tid >> 5, lane = tid & 31;
    int g = lane >> 2, tg = lane & 3;
    int r0 = warp * 16;

    auto load_jt = [&](int t, int s) {
        #pragma unroll
        for (int i = 0; i < 2; i++) {
            int f = tid + i * 256;
            int r = f >> 3, ch = f & 7;
            cpasync16(Hs_b + (uint32_t)(((s * JT + r) * F_ST + ch * 8) * 2),
                      hB + (long)r * CN + t * JT + ch * 8);
        }
        #pragma unroll
        for (int i = 0; i < 2; i++) {
            int f = tid + i * 256;
            int r = f >> 2, c16 = (f & 3) * 16;
            cpasync16(Cs_b + (uint32_t)(s * 128 * G_CS + r * G_CS + c16),
                      cB + (long)r * CN + t * JT + c16);
        }
        cpcommit();
    };
    load_jt(0, 0);

    ((float4*)e2s)[tid] = ((const float4*)e2B)[tid];
    float e1v0 = e1[(long)b * CN + ib * 128 + r0 + g];
    float e1v1 = e1[(long)b * CN + ib * 128 + r0 + g + 8];
    float rA = rsc[0], rB2 = rsc[1];

    const uint32_t bones[2] = {0x3C003C00u, 0x3C003C00u};
    float m0 = -3.4e38f, m1 = -3.4e38f;
    float lacc[4] = {0.f, 0.f, 0.f, 0.f};
    float o[8][4];
    #pragma unroll
    for (int nf = 0; nf < 8; nf++)
        #pragma unroll
        for (int q = 0; q < 4; q++) o[nf][q] = 0.f;

    for (int t = 0; t < 16; t++) {
        int s = t & 1;
        if (t < 15) load_jt(t + 1, s ^ 1);
        if (t < 15) cpwait1(); else cpwait0();
        __syncthreads();

        float sc[8][4];
        #pragma unroll
        for (int nf = 0; nf < 8; nf++) {
            int lc = nf * 8 + tg * 2;
            float eA = e2s[t * JT + lc];
            float eB = e2s[t * JT + lc + 1];
            uint32_t c0 = *(const uint16_t*)&Cs[s * 128 * G_CS + (r0 + g) * G_CS + lc];
            uint32_t c1 = *(const uint16_t*)&Cs[s * 128 * G_CS + (r0 + g + 8) * G_CS + lc];
            float v;
            v = e1v0 + eA + ((c0 & 1u)   ? rB2 : rA); v = v >= 0.f ? v : ALPHAF * v; sc[nf][0] = (c0 & 2u)   ? v : NEGF;
            v = e1v0 + eB + ((c0 & 256u) ? rB2 : rA); v = v >= 0.f ? v : ALPHAF * v; sc[nf][1] = (c0 & 512u) ? v : NEGF;
            v = e1v1 + eA + ((c1 & 1u)   ? rB2 : rA); v = v >= 0.f ? v : ALPHAF * v; sc[nf][2] = (c1 & 2u)   ? v : NEGF;
            v = e1v1 + eB + ((c1 & 256u) ? rB2 : rA); v = v >= 0.f ? v : ALPHAF * v; sc[nf][3] = (c1 & 512u) ? v : NEGF;
        }

        float mx0 = -3.4e38f, mx1 = -3.4e38f;
        #pragma unroll
        for (int nf = 0; nf < 8; nf++) {
            mx0 = fmaxf(mx0, fmaxf(sc[nf][0], sc[nf][1]));
            mx1 = fmaxf(mx1, fmaxf(sc[nf][2], sc[nf][3]));
        }
        #pragma unroll
        for (int off = 1; off <= 2; off <<= 1) {
            mx0 = fmaxf(mx0, __shfl_xor_sync(0xffffffffu, mx0, off));
            mx1 = fmaxf(mx1, __shfl_xor_sync(0xffffffffu, mx1, off));
        }
        float mn0 = fmaxf(m0, mx0);
        float mn1 = fmaxf(m1, mx1);
        float cr0 = __expf(m0 - mn0);
        float cr1 = __expf(m1 - mn1);
        lacc[0] *= cr0; lacc[1] *= cr0; lacc[2] *= cr1; lacc[3] *= cr1;
        #pragma unroll
        for (int nf = 0; nf < 8; nf++) {
            o[nf][0] *= cr0; o[nf][1] *= cr0;
            o[nf][2] *= cr1; o[nf][3] *= cr1;
        }
        m0 = mn0; m1 = mn1;

        float mnl0 = mn0 * L2EF, mnl1 = mn1 * L2EF;
        uint32_t ph[8][2];
        #pragma unroll
        for (int nf = 0; nf < 8; nf++) {
            ph[nf][0] = ex2h2(fmaf(sc[nf][0], L2EF, -mnl0), fmaf(sc[nf][1], L2EF, -mnl0));
            ph[nf][1] = ex2h2(fmaf(sc[nf][2], L2EF, -mnl1), fmaf(sc[nf][3], L2EF, -mnl1));
        }

        #pragma unroll
        for (int kf = 0; kf < 4; kf++) {
            uint32_t a[4];
            a[0] = ph[2 * kf][0];
            a[1] = ph[2 * kf][1];
            a[2] = ph[2 * kf + 1][0];
            a[3] = ph[2 * kf + 1][1];
            mma_f16(lacc, a, bones);
            #pragma unroll
            for (int nf = 0; nf < 8; nf++) {
                uint32_t b2[2];
                const __half* hr = &Hs[(s * JT + nf * 8 + g) * F_ST + kf * 16 + 2 * tg];
                b2[0] = *(uint32_t*)hr;
                b2[1] = *(uint32_t*)(hr + 8);
                mma_f16(o[nf], a, b2);
            }
        }
        __syncthreads();
    }

    float inv0 = 1.f / lacc[0], inv1 = 1.f / lacc[2];
    #pragma unroll
    for (int nf = 0; nf < 8; nf++) {
        int c = nf * 8 + tg * 2;
        float v0 = o[nf][0] * inv0, v1 = o[nf][1] * inv0;
        float v2 = o[nf][2] * inv1, v3 = o[nf][3] * inv1;
        v0 = v0 > 0.f ? v0 : expm1f(v0);
        v1 = v1 > 0.f ? v1 : expm1f(v1);
        v2 = v2 > 0.f ? v2 : expm1f(v2);
        v3 = v3 > 0.f ? v3 : expm1f(v3);
        *(float2*)(AggB + (long)(r0 + g)     * CHID + c) = make_float2(v0, v1);
        *(float2*)(AggB + (long)(r0 + g + 8) * CHID + c) = make_float2(v2, v3);
    }
}

// ---------------- fp32 tiled SGEMM (fc2 only) ----------------
template<int ACT>
__global__ void sgemm(const float* __restrict__ A, const float* __restrict__ Bm,
                      const float* __restrict__ bias, float* __restrict__ C,
                      int M, int N, int K)
{
    __shared__ float As[16][68];
    __shared__ float Bs[16][68];
    int tx = threadIdx.x;
    int tr = tx >> 4, tc = tx & 15;
    int row0 = blockIdx.y * 64, col0 = blockIdx.x * 64;

    float acc[4][4] = {};
    for (int k0 = 0; k0 < K; k0 += 16) {
        #pragma unroll
        for (int i = 0; i < 4; i++) {
            int idx = tx * 4 + i;
            int m = idx >> 4, k = idx & 15;
            int gr = row0 + m;
            As[k][m] = (gr < M) ? A[(long)gr * K + k0 + k] : 0.f;
        }
        #pragma unroll
        for (int i = 0; i < 4; i++) {
            int idx = tx * 4 + i;
            int k = idx >> 6, n = idx & 63;
            int gn = col0 + n;
            Bs[k][n] = (gn < N) ? Bm[(long)(k0 + k) * N + gn] : 0.f;
        }
        __syncthreads();
        #pragma unroll
        for (int k = 0; k < 16; k++) {
            float a[4], b[4];
            #pragma unroll
            for (int i = 0; i < 4; i++) a[i] = As[k][tr * 4 + i];
            #pragma unroll
            for (int j = 0; j < 4; j++) b[j] = Bs[k][tc * 4 + j];
            #pragma unroll
            for (int i = 0; i < 4; i++)
                #pragma unroll
                for (int j = 0; j < 4; j++)
                    acc[i][j] = fmaf(a[i], b[j], acc[i][j]);
        }
        __syncthreads();
    }
    #pragma unroll
    for (int i = 0; i < 4; i++) {
        int gr = row0 + tr * 4 + i;
        if (gr >= M) continue;
        #pragma unroll
        for (int j = 0; j < 4; j++) {
            int gn = col0 + tc * 4 + j;
            if (gn >= N) continue;
            float v = acc[i][j];
            if (bias) v += bias[gn];
            if (ACT == 1) v = v > 0.f ? v : 0.f;
            C[(long)gr * N + gn] = v;
        }
    }
}

// ---------------- logits: warp per row ----------------
__global__ void logits_kernel(const float* __restrict__ H, const float* __restrict__ W,
                              const float* __restrict__ bb, float* __restrict__ out)
{
    int warp = threadIdx.x >> 5, lane = threadIdx.x & 31;
    int row = blockIdx.x * 8 + warp;
    float hv[8];
    #pragma unroll
    for (int j = 0; j < 8; j++) hv[j] = H[(long)row * CHID + j * 32 + lane];
    float acc[CNC];
    #pragma unroll
    for (int c = 0; c < CNC; c++) {
        float a = 0.f;
        #pragma unroll
        for (int j = 0; j < 8; j++) a = fmaf(hv[j], W[(j * 32 + lane) * CNC + c], a);
        acc[c] = a;
    }
    #pragma unroll
    for (int c = 0; c < CNC; c++)
        #pragma unroll
        for (int off = 16; off > 0; off >>= 1)
            acc[c] += __shfl_xor_sync(0xffffffffu, acc[c], off);
    if (lane < CNC) out[(long)row * CNC + lane] = acc[lane] + bb[lane];
}

// ---------------- PW = P @ wk ----------------
__global__ void pwk_kernel(const float* __restrict__ P, const float* __restrict__ wk,
                           float* __restrict__ PW)
{
    __shared__ float red[4][64];
    int r = blockIdx.x, dq = blockIdx.y;
    int dloc = threadIdx.x & 63, part = threadIdx.x >> 6;
    int d = dq * 64 + dloc;
    const float* Pr = P + (long)r * CHID;
    float a0 = 0.f, a1 = 0.f, a2 = 0.f, a3 = 0.f;
    int k0 = part * 64;
    #pragma unroll 4
    for (int k = 0; k < 64; k += 4) {
        a0 = fmaf(Pr[k0 + k],     wk[(k0 + k)     * CHID + d], a0);
        a1 = fmaf(Pr[k0 + k + 1], wk[(k0 + k + 1) * CHID + d], a1);
        a2 = fmaf(Pr[k0 + k + 2], wk[(k0 + k + 2) * CHID + d], a2);
        a3 = fmaf(Pr[k0 + k + 3], wk[(k0 + k + 3) * CHID + d], a3);
    }
    red[part][dloc] = (a0 + a1) + (a2 + a3);
    __syncthreads();
    if (part == 0)
        PW[(long)r * CHID + d] = red[0][dloc] + red[1][dloc] + red[2][dloc] + red[3][dloc];
}

// ---------------- Kh ----------------
__global__ void kcomb_kernel(const float* __restrict__ sadj, const float* __restrict__ PW,
                             const float* __restrict__ bk, __half* __restrict__ Kh)
{
    long idx = (long)blockIdx.x * 256 + threadIdx.x;
    int d = idx & (CHID - 1);
    int n = (idx >> 8) & (CN - 1);
    int b = (int)(idx >> 18);
    const float* sa = sadj + (long)b * CM * CN + n;
    const float* Pb = PW + (long)b * CM * CHID + d;
    float acc = bk[d];
    #pragma unroll
    for (int m = 0; m < CM; m++) acc = fmaf(sa[m * CN], Pb[m * CHID], acc);
    Kh[idx] = __float2half_rn(acc);
}

// ---------------- e1/e2 dots ----------------
__global__ void dots_kernel(const __half* __restrict__ hT, const float* __restrict__ a1,
                            const float* __restrict__ a2,
                            float* __restrict__ e1, float* __restrict__ e2)
{
    __shared__ float s1[4][64], s2[4][64];
    int bI = blockIdx.x;
    int b = bI >> 4, jb = bI & 15;
    int jloc = threadIdx.x & 63, part = threadIdx.x >> 6;
    int j = jb * 64 + jloc;
    const __half* base = hT + (long)b * CHID * CN + j;
    float t1 = 0.f, t2 = 0.f;
    #pragma unroll 8
    for (int c = part * 64; c < part * 64 + 64; c++) {
        float v = __half2float(base[(long)c * CN]);
        t1 = fmaf(v, a1[c], t1);
        t2 = fmaf(v, a2[c], t2);
    }
    s1[part][jloc] = t1; s2[part][jloc] = t2;
    __syncthreads();
    if (part == 0) {
        e1[b * CN + j] = s1[0][jloc] + s1[1][jloc] + s1[2][jloc] + s1[3][jloc];
        e2[b * CN + j] = s2[0][jloc] + s2[1][jloc] + s2[2][jloc] + s2[3][jloc];
    }
}

// ---------------- rel_sc ----------------
__global__ void relsc_kernel(const float* __restrict__ rel, const float* __restrict__ a3,
                             float* __restrict__ out)
{
    __shared__ float s[256];
    int r = blockIdx.x, t = threadIdx.x;
    s[t] = rel[r * CHID + t] * a3[t];
    __syncthreads();
    for (int o = 128; o > 0; o >>= 1) {
        if (t < o) s[t] += s[t + o];
        __syncthreads();
    }
    if (t == 0) out[r] = s[0];
}

// ---------------- LayerNorm ----------------
__global__ void ln_kernel(const float* __restrict__ T, const float* __restrict__ Hold,
                          const float* __restrict__ g, const float* __restrict__ bb,
                          float* __restrict__ out)
{
    int warp = threadIdx.x >> 5, lane = threadIdx.x & 31;
    int row = blockIdx.x * 8 + warp;
    long base = (long)row * CHID;
    float v[8];
    float s = 0.f;
    #pragma unroll
    for (int j = 0; j < 8; j++) {
        int c = j * 32 + lane;
        v[j] = T[base + c] + Hold[base + c];
        s += v[j];
    }
    #pragma unroll
    for (int off = 16; off > 0; off >>= 1) s += __shfl_xor_sync(0xffffffffu, s, off);
    float mu = s * (1.f / CHID);
    float q = 0.f;
    #pragma unroll
    for (int j = 0; j < 8; j++) { v[j] -= mu; q = fmaf(v[j], v[j], q); }
    #pragma unroll
    for (int off = 16; off > 0; off >>= 1) q += __shfl_xor_sync(0xffffffffu, q, off);
    float rstd = rsqrtf(q * (1.f / CHID) + 1e-5f);
    #pragma unroll
    for (int j = 0; j < 8; j++) {
        int c = j * 32 + lane;
        out[base + c] = v[j] * rstd * g[c] + bb[c];
    }
}

// ---------------- Pagg partials ----------------
__global__ void pagg_part_kernel(const float* __restrict__ sadj, const float* __restrict__ Hcur,
                                 float* __restrict__ PaggP)
{
    int bm = blockIdx.x, part = blockIdx.y;
    int b = bm >> 3;
    int c = threadIdx.x;
    const float* sa = sadj + (long)bm * CN + part * 256;
    const float* Hb = Hcur + ((long)b * CN + part * 256) * CHID + c;
    float a0 = 0.f, a1 = 0.f, a2 = 0.f, a3 = 0.f;
    #pragma unroll 4
    for (int n = 0; n < 256; n += 4) {
        a0 = fmaf(sa[n],     Hb[(long)(n)     * CHID], a0);
        a1 = fmaf(sa[n + 1], Hb[(long)(n + 1) * CHID], a1);
        a2 = fmaf(sa[n + 2], Hb[(long)(n + 2) * CHID], a2);
        a3 = fmaf(sa[n + 3], Hb[(long)(n + 3) * CHID], a3);
    }
    PaggP[((long)part * 64 + bm) * CHID + c] = (a0 + a1) + (a2 + a3);
}

// ---------------- GRU ----------------
__global__ void gru_kernel(const float* __restrict__ PaggP, float* __restrict__ P,
                           float* __restrict__ Pnew,
                           const float* __restrict__ wz, const float* __restrict__ uz,
                           const float* __restrict__ wr, const float* __restrict__ ur,
                           const float* __restrict__ w,  const float* __restrict__ u)
{
    __shared__ float sp[CHID], sq[CHID];
    __shared__ float red[6][4][64];
    int bm = blockIdx.x, dq = blockIdx.y;
    int dloc = threadIdx.x & 63, part = threadIdx.x >> 6;
    int d = dq * 64 + dloc;
    sp[threadIdx.x] = P[(long)bm * CHID + threadIdx.x];
    sq[threadIdx.x] = PaggP[(long)bm * CHID + threadIdx.x]
                    + PaggP[((long)64 + bm) * CHID + threadIdx.x]
                    + PaggP[((long)128 + bm) * CHID + threadIdx.x]
                    + PaggP[((long)192 + bm) * CHID + threadIdx.x];
    __syncthreads();
    float az = 0, bz = 0, ar = 0, br = 0, aw = 0, bw = 0;
    int k0 = part * 64;
    #pragma unroll 4
    for (int k = k0; k < k0 + 64; k++) {
        float pk = sp[k], qk = sq[k];
        az = fmaf(pk, wz[k * CHID + d], az); bz = fmaf(qk, uz[k * CHID + d], bz);
        ar = fmaf(pk, wr[k * CHID + d], ar); br = fmaf(qk, ur[k * CHID + d], br);
        aw = fmaf(pk, w [k * CHID + d], aw); bw = fmaf(qk, u [k * CHID + d], bw);
    }
    red[0][part][dloc] = az; red[1][part][dloc] = bz;
    red[2][part][dloc] = ar; red[3][part][dloc] = br;
    red[4][part][dloc] = aw; red[5][part][dloc] = bw;
    __syncthreads();
    if (part == 0) {
        float tz = red[0][0][dloc] + red[0][1][dloc] + red[0][2][dloc] + red[0][3][dloc]
                 + red[1][0][dloc] + red[1][1][dloc] + red[1][2][dloc] + red[1][3][dloc];
        float tr_ = red[2][0][dloc] + red[2][1][dloc] + red[2][2][dloc] + red[2][3][dloc]
                  + red[3][0][dloc] + red[3][1][dloc] + red[3][2][dloc] + red[3][3][dloc];
        float tw = red[4][0][dloc] + red[4][1][dloc] + red[4][2][dloc] + red[4][3][dloc];
        float tu = red[5][0][dloc] + red[5][1][dloc] + red[5][2][dloc] + red[5][3][dloc];
        float z  = 1.f / (1.f + expf(-tz));
        float rr = 1.f / (1.f + expf(-tr_));
        float hh = tanhf(tw + rr * tu);
        Pnew[(long)bm * CHID + d] = (1.f - z) * sp[d] + z * hh;
    }
}

// ---------------- p_sim ----------------
__global__ void psim_kernel(const float* __restrict__ P, float* __restrict__ outp, int tail)
{
    __shared__ float red[64];
    int t = threadIdx.x;
    int b = t >> 3, m = t & 7;
    const float* Pb = P + (long)b * CM * CHID;
    float s = 0.f;
    for (int k2 = 0; k2 < CM; k2++) {
        if (k2 == m) continue;
        float d = 0.f;
        for (int dd = 0; dd < CHID; dd++)
            d = fmaf(Pb[m * CHID + dd], Pb[k2 * CHID + dd], d);
        s += d;
    }
    red[t] = s; __syncthreads();
    if ((t & 7) < 4) red[t] += red[t + 4]; __syncthreads();
    if ((t & 7) < 2) red[t] += red[t + 2]; __syncthreads();
    if ((t & 7) < 1) red[t] += red[t + 1]; __syncthreads();
    if (tail >= CB) {
        if (t < CB) outp[t] = red[t * 8] / (float)(CM * CM);
    } else {
        if (t == 0) {
            float tot = 0.f;
            for (int b2 = 0; b2 < CB; b2++) tot += red[b2 * 8];
            outp[0] = tot / (float)(CB * CM * CM);
        }
    }
}

// ---------------- host orchestration ----------------
extern "C" void kernel_launch(void* const* d_in, const int* in_sizes, int n_in,
                              void* d_out, int out_size)
{
    const float* x     = (const float*)d_in[0];
    const int*   adj   = (const int*)  d_in[1];
    const int*   smask = (const int*)  d_in[2];
    const float* sf    = (const float*)d_in[3];
    const float* sadj  = (const float*)d_in[4];
    const float* fc1w  = (const float*)d_in[6];
    const float* fc1b  = (const float*)d_in[7];
    const float* fc2w  = (const float*)d_in[8];
    const float* fc2b  = (const float*)d_in[9];
    const float* gatW  = (const float*)d_in[10];
    const float* gata  = (const float*)d_in[11];
    const float* rel   = (const float*)d_in[12];
    const float* gwz   = (const float*)d_in[13];
    const float* guz   = (const float*)d_in[14];
    const float* gwr   = (const float*)d_in[15];
    const float* gur   = (const float*)d_in[16];
    const float* gw    = (const float*)d_in[17];
    const float* gu    = (const float*)d_in[18];
    const float* wv    = (const float*)d_in[19];
    const float* bv    = (const float*)d_in[20];
    const float* wk    = (const float*)d_in[21];
    const float* bk    = (const float*)d_in[22];
    const float* wq    = (const float*)d_in[23];
    const float* bq    = (const float*)d_in[24];
    const float* wo    = (const float*)d_in[25];
    const float* bo    = (const float*)d_in[26];
    const float* lng   = (const float*)d_in[27];
    const float* lnb   = (const float*)d_in[28];
    const float* outw  = (const float*)d_in[29];
    const float* outb  = (const float*)d_in[30];
    float* out = (float*)d_out;

    float *H, *Hn, *P, *PW, *PaggP, *Agg, *ctx, *Tb, *e1, *e2, *rsc;
    __half *Qh, *Kh, *VT, *hT;
    uint8_t* codes;
    cudaGetSymbolAddress((void**)&H,    g_H);
    cudaGetSymbolAddress((void**)&Hn,   g_Hn);
    cudaGetSymbolAddress((void**)&P,    g_P);
    cudaGetSymbolAddress((void**)&PW,   g_PW);
    cudaGetSymbolAddress((void**)&PaggP, g_PaggP);
    cudaGetSymbolAddress((void**)&Agg,  g_Agg);
    cudaGetSymbolAddress((void**)&ctx,  g_ctx);
    cudaGetSymbolAddress((void**)&Tb,   g_T);
    cudaGetSymbolAddress((void**)&Qh,   g_Qh);
    cudaGetSymbolAddress((void**)&Kh,   g_Kh);
    cudaGetSymbolAddress((void**)&VT,   g_VT);
    cudaGetSymbolAddress((void**)&hT,   g_hT);
    cudaGetSymbolAddress((void**)&codes, g_codes);
    cudaGetSymbolAddress((void**)&e1,   g_e1);
    cudaGetSymbolAddress((void**)&e2,   g_e2);
    cudaGetSymbolAddress((void**)&rsc,  g_rsc);

    cudaFuncSetAttribute(tgemm<0>, cudaFuncAttributeMaxDynamicSharedMemorySize, SM_TG);
    cudaFuncSetAttribute(tgemm<1>, cudaFuncAttributeMaxDynamicSharedMemorySize, SM_TG);
    cudaFuncSetAttribute(tgemm<4>, cudaFuncAttributeMaxDynamicSharedMemorySize, SM_TG);
    cudaFuncSetAttribute(tgemm_pair, cudaFuncAttributeMaxDynamicSharedMemorySize, SM_TG);
    cudaFuncSetAttribute(flash_kernel, cudaFuncAttributeMaxDynamicSharedMemorySize, SM_FLASH);
    cudaFuncSetAttribute(gatt_kernel, cudaFuncAttributeMaxDynamicSharedMemorySize, SM_GATT);

    dim3 blk(256);
    const int BN = CB * CN;
    const long HH = (long)CHID * CHID;

    pack_codes<<<(int)((long)CB * CN * CN / 4 / 256), blk>>>(adj, smask, codes);
    tgemm<1><<<dim3(2, 64, 1), blk, SM_TG>>>(x, fc1w, fc1b, H, BN, CHID, CDIN, 0, 0, 0, 1.f);
    sgemm<1><<<dim3(4, 1, 1), blk>>>(sf, fc2w, fc2b, P, CB * CM, CHID, CDIN);

    for (int l = 0; l < CL; l++) {
        float* cur = l ? Hn : H;
        float* nxt = l ? H : Hn;

        pwk_kernel<<<dim3(CB * CM, 4), blk>>>(P, wk + l * HH, PW);
        kcomb_kernel<<<BN * CHID / 256, blk>>>(sadj, PW, bk + l * CHID, Kh);

        {
            G2 a;
            a.A[0] = cur;           a.A[1] = cur;
            a.B[0] = gatW + l * HH; a.B[1] = wv + l * HH;
            a.bias[0] = nullptr;    a.bias[1] = bv + l * CHID;
            a.C[0] = (float*)hT;    a.C[1] = (float*)VT;
            a.act[0] = 5;           a.act[1] = 6;
            tgemm_pair<<<dim3(2, 64, 2), blk, SM_TG>>>(a, BN, CHID, CHID);
        }
        dots_kernel<<<CB * 16, blk>>>(hT, gata + l * 3 * CHID, gata + l * 3 * CHID + CHID, e1, e2);
        relsc_kernel<<<2, blk>>>(rel + l * 2 * CHID, gata + l * 3 * CHID + 2 * CHID, rsc);
        gatt_kernel<<<dim3(4, 8, CB), blk, SM_GATT>>>(e1, e2, rsc, codes, hT, Agg);
        tgemm<4><<<dim3(2, 64, 1), blk, SM_TG>>>(Agg, wq + l * HH, bq + l * CHID, (float*)Qh,
                                                 BN, CHID, CHID, 0, 0, 0, 1.f);
        flash_kernel<<<dim3(8, 32), blk, SM_FLASH>>>(Qh, Kh, VT, ctx);
        tgemm<0><<<dim3(2, 64, 1), blk, SM_TG>>>(ctx, wo + l * HH, bo + l * CHID, Tb,
                                                 BN, CHID, CHID, 0, 0, 0, 1.f);
        ln_kernel<<<BN / 8, blk>>>(Tb, cur, lng + l * CHID, lnb + l * CHID, nxt);

        pagg_part_kernel<<<dim3(CB * CM, 4), blk>>>(sadj, cur, PaggP);
        gru_kernel<<<dim3(CB * CM, 4), blk>>>(PaggP, P, P,
                                              gwz + l * HH, guz + l * HH,
                                              gwr + l * HH, gur + l * HH,
                                              gw + l * HH,  gu + l * HH);
    }

    logits_kernel<<<BN / 8, blk>>>(H, outw, outb, out);
    psim_kernel<<<1, 64>>>(P, out + (long)BN * CNC, out_size - BN * CNC);
}

// round 15
// speedup vs baseline: 1.7647x; 1.0411x over previous
#include <cuda_runtime.h>
#include <cuda_fp16.h>
#include <math.h>
#include <stdint.h>

// ---------------- problem constants ----------------
constexpr int CB   = 8;
constexpr int CN   = 1024;
constexpr int CM   = 8;
constexpr int CDIN = 1024;
constexpr int CHID = 256;
constexpr int CL   = 2;
constexpr int CNC  = 7;
constexpr int CDH  = 64;
#define NEGF  (-9e15f)
#define ALPHAF 0.1f
#define L2EF  1.4426950408889634f

// ---------------- scratch ----------------
__device__ float  g_H   [CB*CN*CHID];
__device__ float  g_Hn  [CB*CN*CHID];
__device__ float  g_P   [CB*CM*CHID];
__device__ float  g_PW  [CB*CM*CHID];
__device__ float  g_PaggP[4*CB*CM*CHID];
__device__ float  g_Agg [CB*CN*CHID];
__device__ float  g_ctx [CB*CN*CHID];
__device__ float  g_T   [CB*CN*CHID];
__device__ __align__(16) __half g_Qh  [CB*CN*CHID];
__device__ __align__(16) __half g_Kh  [CB*CN*CHID];
__device__ __align__(16) __half g_VT  [CB*CN*CHID];   // [bh][d][j]
__device__ __align__(16) __half g_hT  [CB*CN*CHID];   // [b][c][n]
__device__ __align__(16) __half g_WT8 [8*CHID*CHID];  // fp16 [N][K] weights
__device__ __align__(16) __half g_WTfc1[CHID*CDIN];   // fc1w^T fp16 [256][1024]
__device__ uint8_t g_codes[(long)CB*CN*CN];
__device__ float  g_e1  [CB*CN];
__device__ float  g_e2  [CB*CN];
__device__ float  g_rsc [2];

// ---------------- helpers ----------------
__device__ __forceinline__ void mma_f16(float c[4], const uint32_t a[4], const uint32_t b[2]) {
    asm volatile(
        "mma.sync.aligned.m16n8k16.row.col.f32.f16.f16.f32 "
        "{%0,%1,%2,%3}, {%4,%5,%6,%7}, {%8,%9}, {%0,%1,%2,%3};\n"
        : "+f"(c[0]), "+f"(c[1]), "+f"(c[2]), "+f"(c[3])
        : "r"(a[0]), "r"(a[1]), "r"(a[2]), "r"(a[3]), "r"(b[0]), "r"(b[1]));
}
__device__ __forceinline__ uint32_t pkh2(float x, float y) {
    __half2 h = __floats2half2_rn(x, y);
    return *(uint32_t*)&h;
}
__device__ __forceinline__ uint32_t ex2h2(float x, float y) {
    __half2 h = __floats2half2_rn(x, y);
    uint32_t r;
    asm("ex2.approx.f16x2 %0, %1;" : "=r"(r) : "r"(*(uint32_t*)&h));
    return r;
}
__device__ __forceinline__ void cpasync16(uint32_t saddr, const void* gptr) {
    asm volatile("cp.async.cg.shared.global [%0], [%1], 16;\n" :: "r"(saddr), "l"(gptr));
}
__device__ __forceinline__ void cpcommit() { asm volatile("cp.async.commit_group;\n"); }
__device__ __forceinline__ void cpwait0()  { asm volatile("cp.async.wait_group 0;\n"); }
__device__ __forceinline__ void cpwait1()  { asm volatile("cp.async.wait_group 1;\n"); }

// ---------------- weight transpose+fp16 pack (once per replay) ----------------
struct W8 { const float* src[8]; };
__global__ void wpack8_kernel(W8 w, __half* dst)
{
    __shared__ float tile[32][33];
    int mi = blockIdx.z;
    const float* W = w.src[mi];
    __half* WT = dst + (long)mi * CHID * CHID;
    int k0 = blockIdx.x * 32, n0 = blockIdx.y * 32;
    int tx = threadIdx.x & 31, ty = threadIdx.x >> 5;
    #pragma unroll
    for (int i = 0; i < 32; i += 8)
        tile[ty + i][tx] = W[(long)(k0 + ty + i) * CHID + n0 + tx];
    __syncthreads();
    #pragma unroll
    for (int i = 0; i < 32; i += 8)
        WT[(long)(n0 + ty + i) * CHID + k0 + tx] = __float2half_rn(tile[tx][ty + i]);
}
__global__ void wpack_fc1_kernel(const float* __restrict__ W, __half* __restrict__ WT)
{
    __shared__ float tile[32][33];
    int k0 = blockIdx.x * 32, n0 = blockIdx.y * 32;
    int tx = threadIdx.x & 31, ty = threadIdx.x >> 5;
    #pragma unroll
    for (int i = 0; i < 32; i += 8)
        tile[ty + i][tx] = W[(long)(k0 + ty + i) * CHID + n0 + tx];
    __syncthreads();
    #pragma unroll
    for (int i = 0; i < 32; i += 8)
        WT[(long)(n0 + ty + i) * CDIN + k0 + tx] = __float2half_rn(tile[tx][ty + i]);
}

// ================= fp16 GEMM tile (128x128, KS=32, 2-stage, 2 CTAs/SM) =================
// A fp32 row-major [M,K]; B = fp16 W^T [N,K] (k-major rows). C += A@W.
struct TileCtx {
    float *As; __half *Bs;
    uint32_t As_b, Bs_b;
    const float *Ag; const __half *Bg;
    int K, N;
    int tid;
};
constexpr int T_strA = 36;                  // floats
constexpr int T_strB = 40;                  // halves
constexpr int T_AW = 128 * T_strA;          // floats/stage
constexpr int T_BW = 128 * T_strB;          // halves/stage
constexpr int SM_TG = 2 * (T_AW * 4 + T_BW * 2);   // 57344 bytes

__device__ __forceinline__ void tg_load_stage(TileCtx& c, int kt, int s) {
    int k0 = kt * 32;
    #pragma unroll
    for (int i = 0; i < 4; i++) {
        int f = c.tid + i * 256;
        int m = f >> 3, k4 = (f & 7) * 4;
        cpasync16(c.As_b + (uint32_t)(((s * 128 + m) * T_strA + k4) * 4),
                  c.Ag + (long)m * c.K + k0 + k4);
    }
    #pragma unroll
    for (int i = 0; i < 2; i++) {
        int f = c.tid + i * 256;
        int n = f >> 2, c8 = (f & 3) * 8;
        cpasync16(c.Bs_b + (uint32_t)(((s * 128 + n) * T_strB + c8) * 2),
                  c.Bg + (long)n * c.K + k0 + c8);
    }
    cpcommit();
}

// act: 0 none, 1 relu, 4 half row-major, 5 half batch-transpose, 6 half head-transpose
__device__ __forceinline__ void tg_body(
    TileCtx& c, const float* bias, float* C, int M, int N, int K,
    int row0, int col0, int act)
{
    int tid  = c.tid;
    int warp = tid >> 5, lane = tid & 31;
    int g = lane >> 2, tg = lane & 3;
    int mw = warp >> 2, nw = warp & 3;

    float acc[4][4][4];
    #pragma unroll
    for (int mi = 0; mi < 4; mi++)
        #pragma unroll
        for (int ni = 0; ni < 4; ni++)
            #pragma unroll
            for (int q = 0; q < 4; q++) acc[mi][ni][q] = 0.f;

    int nk = K / 32;
    tg_load_stage(c, 0, 0);

    for (int kt = 0; kt < nk; kt++) {
        cpwait0();
        __syncthreads();
        int s = kt & 1;
        if (kt + 1 < nk) tg_load_stage(c, kt + 1, s ^ 1);

        const float* Asb = c.As + s * T_AW;
        const __half* Bsb = c.Bs + s * T_BW;
        #pragma unroll
        for (int ks = 0; ks < 32; ks += 16) {
            uint32_t a[4][4], b[4][2];
            #pragma unroll
            for (int mi = 0; mi < 4; mi++) {
                int mr = mw * 64 + mi * 16;
                const float* r0p = &Asb[(mr + g)     * T_strA + ks + 2 * tg];
                const float* r1p = &Asb[(mr + g + 8) * T_strA + ks + 2 * tg];
                float2 v0 = *(const float2*)r0p;
                float2 v1 = *(const float2*)r1p;
                float2 v2 = *(const float2*)(r0p + 8);
                float2 v3 = *(const float2*)(r1p + 8);
                a[mi][0] = pkh2(v0.x, v0.y);
                a[mi][1] = pkh2(v1.x, v1.y);
                a[mi][2] = pkh2(v2.x, v2.y);
                a[mi][3] = pkh2(v3.x, v3.y);
            }
            #pragma unroll
            for (int ni = 0; ni < 4; ni++) {
                int nc = nw * 32 + ni * 8;
                const __half* bp = &Bsb[(nc + g) * T_strB + ks + 2 * tg];
                b[ni][0] = *(const uint32_t*)bp;
                b[ni][1] = *(const uint32_t*)(bp + 8);
            }
            #pragma unroll
            for (int mi = 0; mi < 4; mi++)
                #pragma unroll
                for (int ni = 0; ni < 4; ni++)
                    mma_f16(acc[mi][ni], a[mi], b[ni]);
        }
    }

    #pragma unroll
    for (int mi = 0; mi < 4; mi++) {
        #pragma unroll
        for (int ni = 0; ni < 4; ni++) {
            int r = row0 + mw * 64 + mi * 16 + g;
            int cc0 = col0 + nw * 32 + ni * 8 + tg * 2;
            float b0 = bias ? bias[cc0] : 0.f;
            float b1 = bias ? bias[cc0 + 1] : 0.f;
            #pragma unroll
            for (int rr = 0; rr < 2; rr++) {
                int r_ = r + rr * 8;
                float v0 = acc[mi][ni][rr * 2 + 0] + b0;
                float v1 = acc[mi][ni][rr * 2 + 1] + b1;
                if (act == 0) {
                    *(float2*)(C + (long)r_ * N + cc0) = make_float2(v0, v1);
                } else if (act == 1) {
                    *(float2*)(C + (long)r_ * N + cc0) =
                        make_float2(fmaxf(v0, 0.f), fmaxf(v1, 0.f));
                } else if (act == 4) {
                    __half2 h = __floats2half2_rn(v0, v1);
                    *(__half2*)((__half*)C + (long)r_ * N + cc0) = h;
                } else if (act == 5) {          // hT: [b][c][n]
                    __half* CT = (__half*)C;
                    int b_ = r_ >> 10, j = r_ & 1023;
                    CT[((long)(b_ * CHID + cc0))     * CN + j] = __float2half_rn(v0);
                    CT[((long)(b_ * CHID + cc0 + 1)) * CN + j] = __float2half_rn(v1);
                } else {                        // 6: VT: [bh][d][j]
                    __half* CT = (__half*)C;
                    int bh = r_ >> 8;
                    int j = ((r_ & 255) << 2) | (cc0 >> 6);
                    int d = cc0 & 63;
                    long base = ((long)bh << 16) + ((long)d << 10) + j;
                    CT[base] = __float2half_rn(v0);
                    CT[base + 1024] = __float2half_rn(v1);
                }
            }
        }
    }
}

template<int ACT>
__global__ void __launch_bounds__(256, 2) tgemm(
    const float* __restrict__ A, const __half* __restrict__ Bm,
    const float* __restrict__ bias, float* __restrict__ C,
    int M, int N, int K)
{
    extern __shared__ float smem[];
    TileCtx c;
    c.As = smem; c.Bs = (__half*)(smem + 2 * T_AW);
    c.As_b = (uint32_t)__cvta_generic_to_shared(c.As);
    c.Bs_b = (uint32_t)__cvta_generic_to_shared(c.Bs);
    c.K = K; c.N = N; c.tid = threadIdx.x;
    int row0 = blockIdx.y * 128, col0 = blockIdx.x * 128;
    c.Ag = A + (long)row0 * K;
    c.Bg = Bm + (long)col0 * K;
    tg_body(c, bias, C, M, N, K, row0, col0, ACT);
}

struct G2 { const float* A[2]; const __half* B[2]; const float* bias[2]; float* C[2]; int act[2]; };
__global__ void __launch_bounds__(256, 2) tgemm_pair(G2 args, int M, int N, int K)
{
    extern __shared__ float smem[];
    int z = blockIdx.z;
    TileCtx c;
    c.As = smem; c.Bs = (__half*)(smem + 2 * T_AW);
    c.As_b = (uint32_t)__cvta_generic_to_shared(c.As);
    c.Bs_b = (uint32_t)__cvta_generic_to_shared(c.Bs);
    c.K = K; c.N = N; c.tid = threadIdx.x;
    int row0 = blockIdx.y * 128, col0 = blockIdx.x * 128;
    c.Ag = args.A[z] + (long)row0 * K;
    c.Bg = args.B[z] + (long)col0 * K;
    tg_body(c, args.bias[z], args.C[z], M, N, K, row0, col0, args.act[z]);
}

// ---------------- fp16 flash attention, 64-row KV tiles, f16x2 exp ----------------
constexpr int F_ST = 72;   // half stride
constexpr int SM_FLASH = (128 * F_ST + 2 * 64 * F_ST + 2 * 64 * F_ST) * 2;  // 55296
__global__ void __launch_bounds__(256, 2) flash_kernel(
    const __half* __restrict__ Q, const __half* __restrict__ Kg_,
    const __half* __restrict__ Vt_, float* __restrict__ O)
{
    constexpr int KT = 64;
    extern __shared__ float smraw[];
    __half* Qs = (__half*)smraw;
    __half* Ks = Qs + 128 * F_ST;
    __half* Vs = Ks + 2 * KT * F_ST;
    uint32_t Qs_b = (uint32_t)__cvta_generic_to_shared(Qs);
    uint32_t Ks_b = (uint32_t)__cvta_generic_to_shared(Ks);
    uint32_t Vs_b = (uint32_t)__cvta_generic_to_shared(Vs);

    int bh = blockIdx.y;
    const __half* Qg = Q + (long)bh * CN * CDH + (long)blockIdx.x * 128 * CDH;
    const __half* Kg = Kg_ + (long)bh * CN * CDH;
    const __half* Vg = Vt_ + ((long)bh << 16);
    float* Og = O + (long)bh * CN * CDH + (long)blockIdx.x * 128 * CDH;

    int tid = threadIdx.x, warp = tid >> 5, lane = tid & 31;
    int g = lane >> 2, tg = lane & 3;
    int r0 = warp * 16;

    #pragma unroll
    for (int i = 0; i < 4; i++) {
        int f = tid + i * 256;
        int r = f >> 3, ch = f & 7;
        cpasync16(Qs_b + (uint32_t)((r * F_ST + ch * 8) * 2), Qg + r * CDH + ch * 8);
    }
    cpcommit();

    auto load_kv = [&](int t, int s) {
        const __half* Kt = Kg + t * KT * CDH;
        const __half* Vtb = Vg + t * KT;
        #pragma unroll
        for (int i = 0; i < 2; i++) {
            int f = tid + i * 256;
            int r = f >> 3, ch = f & 7;
            cpasync16(Ks_b + (uint32_t)(((s * KT + r) * F_ST + ch * 8) * 2),
                      Kt + r * CDH + ch * 8);
        }
        #pragma unroll
        for (int i = 0; i < 2; i++) {
            int f = tid + i * 256;
            int r = f >> 3, ch = f & 7;
            cpasync16(Vs_b + (uint32_t)(((s * KT + r) * F_ST + ch * 8) * 2),
                      Vtb + (long)r * CN + ch * 8);
        }
        cpcommit();
    };
    load_kv(0, 0);

    cpwait1();
    __syncthreads();

    uint32_t aq[4][4];
    #pragma unroll
    for (int kf = 0; kf < 4; kf++) {
        aq[kf][0] = *(uint32_t*)&Qs[(r0 + g)     * F_ST + kf * 16 + 2 * tg];
        aq[kf][1] = *(uint32_t*)&Qs[(r0 + g + 8) * F_ST + kf * 16 + 2 * tg];
        aq[kf][2] = *(uint32_t*)&Qs[(r0 + g)     * F_ST + kf * 16 + 2 * tg + 8];
        aq[kf][3] = *(uint32_t*)&Qs[(r0 + g + 8) * F_ST + kf * 16 + 2 * tg + 8];
    }

    const uint32_t bones[2] = {0x3C003C00u, 0x3C003C00u};
    float m0 = -3.4e38f, m1 = -3.4e38f;
    float lacc[4] = {0.f, 0.f, 0.f, 0.f};
    float o[8][4];
    #pragma unroll
    for (int nf = 0; nf < 8; nf++)
        #pragma unroll
        for (int q = 0; q < 4; q++) o[nf][q] = 0.f;

    for (int t = 0; t < 16; t++) {
        int s = t & 1;
        if (t < 15) load_kv(t + 1, s ^ 1);
        if (t < 15) cpwait1(); else cpwait0();
        __syncthreads();

        float sc[8][4];
        #pragma unroll
        for (int nf = 0; nf < 8; nf++)
            #pragma unroll
            for (int q = 0; q < 4; q++) sc[nf][q] = 0.f;
        #pragma unroll
        for (int kf = 0; kf < 4; kf++) {
            #pragma unroll
            for (int nf = 0; nf < 8; nf++) {
                uint32_t b[2];
                const __half* kr = &Ks[(s * KT + nf * 8 + g) * F_ST + kf * 16 + 2 * tg];
                b[0] = *(uint32_t*)kr;
                b[1] = *(uint32_t*)(kr + 8);
                mma_f16(sc[nf], aq[kf], b);
            }
        }

        float mx0 = -3.4e38f, mx1 = -3.4e38f;
        #pragma unroll
        for (int nf = 0; nf < 8; nf++) {
            mx0 = fmaxf(mx0, fmaxf(sc[nf][0], sc[nf][1]));
            mx1 = fmaxf(mx1, fmaxf(sc[nf][2], sc[nf][3]));
        }
        #pragma unroll
        for (int off = 1; off <= 2; off <<= 1) {
            mx0 = fmaxf(mx0, __shfl_xor_sync(0xffffffffu, mx0, off));
            mx1 = fmaxf(mx1, __shfl_xor_sync(0xffffffffu, mx1, off));
        }
        float mn0 = fmaxf(m0, mx0 * 0.125f);
        float mn1 = fmaxf(m1, mx1 * 0.125f);
        float cr0 = __expf(m0 - mn0);
        float cr1 = __expf(m1 - mn1);
        lacc[0] *= cr0; lacc[1] *= cr0; lacc[2] *= cr1; lacc[3] *= cr1;
        #pragma unroll
        for (int nf = 0; nf < 8; nf++) {
            o[nf][0] *= cr0; o[nf][1] *= cr0;
            o[nf][2] *= cr1; o[nf][3] *= cr1;
        }
        m0 = mn0; m1 = mn1;

        constexpr float CSC = 0.125f * L2EF;
        float mnl0 = mn0 * L2EF, mnl1 = mn1 * L2EF;
        uint32_t ph[8][2];
        #pragma unroll
        for (int nf = 0; nf < 8; nf++) {
            ph[nf][0] = ex2h2(fmaf(sc[nf][0], CSC, -mnl0), fmaf(sc[nf][1], CSC, -mnl0));
            ph[nf][1] = ex2h2(fmaf(sc[nf][2], CSC, -mnl1), fmaf(sc[nf][3], CSC, -mnl1));
        }

        #pragma unroll
        for (int kf = 0; kf < 4; kf++) {
            uint32_t a[4];
            a[0] = ph[2 * kf][0];
            a[1] = ph[2 * kf][1];
            a[2] = ph[2 * kf + 1][0];
            a[3] = ph[2 * kf + 1][1];
            mma_f16(lacc, a, bones);
            #pragma unroll
            for (int nf = 0; nf < 8; nf++) {
                uint32_t b[2];
                const __half* vr = &Vs[(s * KT + nf * 8 + g) * F_ST + kf * 16 + 2 * tg];
                b[0] = *(uint32_t*)vr;
                b[1] = *(uint32_t*)(vr + 8);
                mma_f16(o[nf], a, b);
            }
        }
        __syncthreads();
    }

    float inv0 = 1.f / lacc[0], inv1 = 1.f / lacc[2];
    #pragma unroll
    for (int nf = 0; nf < 8; nf++) {
        int c = nf * 8 + tg * 2;
        *(float2*)(Og + (long)(r0 + g)     * CDH + c) = make_float2(o[nf][0] * inv0, o[nf][1] * inv0);
        *(float2*)(Og + (long)(r0 + g + 8) * CDH + c) = make_float2(o[nf][2] * inv1, o[nf][3] * inv1);
    }
}

// ---------------- pack adj+smask ----------------
__global__ void pack_codes(const int* __restrict__ adj, const int* __restrict__ smask,
                           uint8_t* __restrict__ codes)
{
    long i = (long)blockIdx.x * 256 + threadIdx.x;
    int4 a = ((const int4*)adj)[i];
    int4 s = ((const int4*)smask)[i];
    uchar4 c;
    c.x = (uint8_t)(((a.x > 0) ? 2 : 0) | (s.x & 1));
    c.y = (uint8_t)(((a.y > 0) ? 2 : 0) | (s.y & 1));
    c.z = (uint8_t)(((a.z > 0) ? 2 : 0) | (s.z & 1));
    c.w = (uint8_t)(((a.w > 0) ? 2 : 0) | (s.w & 1));
    ((uchar4*)codes)[i] = c;
}

// ---------------- fused GAT attention (fp16 PV, f16x2 exp) ----------------
constexpr int G_CS = 80;
constexpr int SM_GATT = 2 * 64 * F_ST * 2 + CN * 4 + 2 * 128 * G_CS;  // 43008
__global__ void __launch_bounds__(256, 2) gatt_kernel(
    const float* __restrict__ e1, const float* __restrict__ e2,
    const float* __restrict__ rsc, const uint8_t* __restrict__ codes,
    const __half* __restrict__ hT, float* __restrict__ Agg)
{
    constexpr int JT = 64;
    extern __shared__ float smraw[];
    __half* Hs = (__half*)smraw;
    float* e2s = (float*)(Hs + 2 * JT * F_ST);
    uint8_t* Cs = (uint8_t*)(e2s + CN);
    uint32_t Hs_b = (uint32_t)__cvta_generic_to_shared(Hs);
    uint32_t Cs_b = (uint32_t)__cvta_generic_to_shared(Cs);

    int nq = blockIdx.x, ib = blockIdx.y, b = blockIdx.z;
    const __half*  hB  = hT + ((long)(b * CHID + nq * 64)) * CN;
    const uint8_t* cB  = codes + ((long)b * CN + ib * 128) * CN;
    const float*   e2B = e2 + (long)b * CN;
    float* AggB = Agg + ((long)b * CN + ib * 128) * CHID + nq * 64;

    int tid = threadIdx.x, warp = tid >> 5, lane = tid & 31;
    int g = lane >> 2, tg = lane & 3;
    int r0 = warp * 16;

    auto load_jt = [&](int t, int s) {
        #pragma unroll
        for (int i = 0; i < 2; i++) {
            int f = tid + i * 256;
            int r = f >> 3, ch = f & 7;
            cpasync16(Hs_b + (uint32_t)(((s * JT + r) * F_ST + ch * 8) * 2),
                      hB + (long)r * CN + t * JT + ch * 8);
        }
        #pragma unroll
        for (int i = 0; i < 2; i++) {
            int f = tid + i * 256;
            int r = f >> 2, c16 = (f & 3) * 16;
            cpasync16(Cs_b + (uint32_t)(s * 128 * G_CS + r * G_CS + c16),
                      cB + (long)r * CN + t * JT + c16);
        }
        cpcommit();
    };
    load_jt(0, 0);

    ((float4*)e2s)[tid] = ((const float4*)e2B)[tid];
    float e1v0 = e1[(long)b * CN + ib * 128 + r0 + g];
    float e1v1 = e1[(long)b * CN + ib * 128 + r0 + g + 8];
    float rA = rsc[0], rB2 = rsc[1];

    const uint32_t bones[2] = {0x3C003C00u, 0x3C003C00u};
    float m0 = -3.4e38f, m1 = -3.4e38f;
    float lacc[4] = {0.f, 0.f, 0.f, 0.f};
    float o[8][4];
    #pragma unroll
    for (int nf = 0; nf < 8; nf++)
        #pragma unroll
        for (int q = 0; q < 4; q++) o[nf][q] = 0.f;

    for (int t = 0; t < 16; t++) {
        int s = t & 1;
        if (t < 15) load_jt(t + 1, s ^ 1);
        if (t < 15) cpwait1(); else cpwait0();
        __syncthreads();

        float sc[8][4];
        #pragma unroll
        for (int nf = 0; nf < 8; nf++) {
            int lc = nf * 8 + tg * 2;
            float eA = e2s[t * JT + lc];
            float eB = e2s[t * JT + lc + 1];
            uint32_t c0 = *(const uint16_t*)&Cs[s * 128 * G_CS + (r0 + g) * G_CS + lc];
            uint32_t c1 = *(const uint16_t*)&Cs[s * 128 * G_CS + (r0 + g + 8) * G_CS + lc];
            float v;
            v = e1v0 + eA + ((c0 & 1u)   ? rB2 : rA); v = v >= 0.f ? v : ALPHAF * v; sc[nf][0] = (c0 & 2u)   ? v : NEGF;
            v = e1v0 + eB + ((c0 & 256u) ? rB2 : rA); v = v >= 0.f ? v : ALPHAF * v; sc[nf][1] = (c0 & 512u) ? v : NEGF;
            v = e1v1 + eA + ((c1 & 1u)   ? rB2 : rA); v = v >= 0.f ? v : ALPHAF * v; sc[nf][2] = (c1 & 2u)   ? v : NEGF;
            v = e1v1 + eB + ((c1 & 256u) ? rB2 : rA); v = v >= 0.f ? v : ALPHAF * v; sc[nf][3] = (c1 & 512u) ? v : NEGF;
        }

        float mx0 = -3.4e38f, mx1 = -3.4e38f;
        #pragma unroll
        for (int nf = 0; nf < 8; nf++) {
            mx0 = fmaxf(mx0, fmaxf(sc[nf][0], sc[nf][1]));
            mx1 = fmaxf(mx1, fmaxf(sc[nf][2], sc[nf][3]));
        }
        #pragma unroll
        for (int off = 1; off <= 2; off <<= 1) {
            mx0 = fmaxf(mx0, __shfl_xor_sync(0xffffffffu, mx0, off));
            mx1 = fmaxf(mx1, __shfl_xor_sync(0xffffffffu, mx1, off));
        }
        float mn0 = fmaxf(m0, mx0);
        float mn1 = fmaxf(m1, mx1);
        float cr0 = __expf(m0 - mn0);
        float cr1 = __expf(m1 - mn1);
        lacc[0] *= cr0; lacc[1] *= cr0; lacc[2] *= cr1; lacc[3] *= cr1;
        #pragma unroll
        for (int nf = 0; nf < 8; nf++) {
            o[nf][0] *= cr0; o[nf][1] *= cr0;
            o[nf][2] *= cr1; o[nf][3] *= cr1;
        }
        m0 = mn0; m1 = mn1;

        float mnl0 = mn0 * L2EF, mnl1 = mn1 * L2EF;
        uint32_t ph[8][2];
        #pragma unroll
        for (int nf = 0; nf < 8; nf++) {
            ph[nf][0] = ex2h2(fmaf(sc[nf][0], L2EF, -mnl0), fmaf(sc[nf][1], L2EF, -mnl0));
            ph[nf][1] = ex2h2(fmaf(sc[nf][2], L2EF, -mnl1), fmaf(sc[nf][3], L2EF, -mnl1));
        }

        #pragma unroll
        for (int kf = 0; kf < 4; kf++) {
            uint32_t a[4];
            a[0] = ph[2 * kf][0];
            a[1] = ph[2 * kf][1];
            a[2] = ph[2 * kf + 1][0];
            a[3] = ph[2 * kf + 1][1];
            mma_f16(lacc, a, bones);
            #pragma unroll
            for (int nf = 0; nf < 8; nf++) {
                uint32_t b2[2];
                const __half* hr = &Hs[(s * JT + nf * 8 + g) * F_ST + kf * 16 + 2 * tg];
                b2[0] = *(uint32_t*)hr;
                b2[1] = *(uint32_t*)(hr + 8);
                mma_f16(o[nf], a, b2);
            }
        }
        __syncthreads();
    }

    float inv0 = 1.f / lacc[0], inv1 = 1.f / lacc[2];
    #pragma unroll
    for (int nf = 0; nf < 8; nf++) {
        int c = nf * 8 + tg * 2;
        float v0 = o[nf][0] * inv0, v1 = o[nf][1] * inv0;
        float v2 = o[nf][2] * inv1, v3 = o[nf][3] * inv1;
        v0 = v0 > 0.f ? v0 : expm1f(v0);
        v1 = v1 > 0.f ? v1 : expm1f(v1);
        v2 = v2 > 0.f ? v2 : expm1f(v2);
        v3 = v3 > 0.f ? v3 : expm1f(v3);
        *(float2*)(AggB + (long)(r0 + g)     * CHID + c) = make_float2(v0, v1);
        *(float2*)(AggB + (long)(r0 + g + 8) * CHID + c) = make_float2(v2, v3);
    }
}

// ---------------- fp32 tiled SGEMM (fc2 only) ----------------
template<int ACT>
__global__ void sgemm(const float* __restrict__ A, const float* __restrict__ Bm,
                      const float* __restrict__ bias, float* __restrict__ C,
                      int M, int N, int K)
{
    __shared__ float As[16][68];
    __shared__ float Bs[16][68];
    int tx = threadIdx.x;
    int tr = tx >> 4, tc = tx & 15;
    int row0 = blockIdx.y * 64, col0 = blockIdx.x * 64;

    float acc[4][4] = {};
    for (int k0 = 0; k0 < K; k0 += 16) {
        #pragma unroll
        for (int i = 0; i < 4; i++) {
            int idx = tx * 4 + i;
            int m = idx >> 4, k = idx & 15;
            int gr = row0 + m;
            As[k][m] = (gr < M) ? A[(long)gr * K + k0 + k] : 0.f;
        }
        #pragma unroll
        for (int i = 0; i < 4; i++) {
            int idx = tx * 4 + i;
            int k = idx >> 6, n = idx & 63;
            int gn = col0 + n;
            Bs[k][n] = (gn < N) ? Bm[(long)(k0 + k) * N + gn] : 0.f;
        }
        __syncthreads();
        #pragma unroll
        for (int k = 0; k < 16; k++) {
            float a[4], b[4];
            #pragma unroll
            for (int i = 0; i < 4; i++) a[i] = As[k][tr * 4 + i];
            #pragma unroll
            for (int j = 0; j < 4; j++) b[j] = Bs[k][tc * 4 + j];
            #pragma unroll
            for (int i = 0; i < 4; i++)
                #pragma unroll
                for (int j = 0; j < 4; j++)
                    acc[i][j] = fmaf(a[i], b[j], acc[i][j]);
        }
        __syncthreads();
    }
    #pragma unroll
    for (int i = 0; i < 4; i++) {
        int gr = row0 + tr * 4 + i;
        if (gr >= M) continue;
        #pragma unroll
        for (int j = 0; j < 4; j++) {
            int gn = col0 + tc * 4 + j;
            if (gn >= N) continue;
            float v = acc[i][j];
            if (bias) v += bias[gn];
            if (ACT == 1) v = v > 0.f ? v : 0.f;
            C[(long)gr * N + gn] = v;
        }
    }
}

// ---------------- logits: warp per row ----------------
__global__ void logits_kernel(const float* __restrict__ H, const float* __restrict__ W,
                              const float* __restrict__ bb, float* __restrict__ out)
{
    int warp = threadIdx.x >> 5, lane = threadIdx.x & 31;
    int row = blockIdx.x * 8 + warp;
    float hv[8];
    #pragma unroll
    for (int j = 0; j < 8; j++) hv[j] = H[(long)row * CHID + j * 32 + lane];
    float acc[CNC];
    #pragma unroll
    for (int c = 0; c < CNC; c++) {
        float a = 0.f;
        #pragma unroll
        for (int j = 0; j < 8; j++) a = fmaf(hv[j], W[(j * 32 + lane) * CNC + c], a);
        acc[c] = a;
    }
    #pragma unroll
    for (int c = 0; c < CNC; c++)
        #pragma unroll
        for (int off = 16; off > 0; off >>= 1)
            acc[c] += __shfl_xor_sync(0xffffffffu, acc[c], off);
    if (lane < CNC) out[(long)row * CNC + lane] = acc[lane] + bb[lane];
}

// ---------------- PW = P @ wk ----------------
__global__ void pwk_kernel(const float* __restrict__ P, const float* __restrict__ wk,
                           float* __restrict__ PW)
{
    __shared__ float red[4][64];
    int r = blockIdx.x, dq = blockIdx.y;
    int dloc = threadIdx.x & 63, part = threadIdx.x >> 6;
    int d = dq * 64 + dloc;
    const float* Pr = P + (long)r * CHID;
    float a0 = 0.f, a1 = 0.f, a2 = 0.f, a3 = 0.f;
    int k0 = part * 64;
    #pragma unroll 4
    for (int k = 0; k < 64; k += 4) {
        a0 = fmaf(Pr[k0 + k],     wk[(k0 + k)     * CHID + d], a0);
        a1 = fmaf(Pr[k0 + k + 1], wk[(k0 + k + 1) * CHID + d], a1);
        a2 = fmaf(Pr[k0 + k + 2], wk[(k0 + k + 2) * CHID + d], a2);
        a3 = fmaf(Pr[k0 + k + 3], wk[(k0 + k + 3) * CHID + d], a3);
    }
    red[part][dloc] = (a0 + a1) + (a2 + a3);
    __syncthreads();
    if (part == 0)
        PW[(long)r * CHID + d] = red[0][dloc] + red[1][dloc] + red[2][dloc] + red[3][dloc];
}

// ---------------- Kh ----------------
__global__ void kcomb_kernel(const float* __restrict__ sadj, const float* __restrict__ PW,
                             const float* __restrict__ bk, __half* __restrict__ Kh)
{
    long idx = (long)blockIdx.x * 256 + threadIdx.x;
    int d = idx & (CHID - 1);
    int n = (idx >> 8) & (CN - 1);
    int b = (int)(idx >> 18);
    const float* sa = sadj + (long)b * CM * CN + n;
    const float* Pb = PW + (long)b * CM * CHID + d;
    float acc = bk[d];
    #pragma unroll
    for (int m = 0; m < CM; m++) acc = fmaf(sa[m * CN], Pb[m * CHID], acc);
    Kh[idx] = __float2half_rn(acc);
}

// ---------------- e1/e2 dots ----------------
__global__ void dots_kernel(const __half* __restrict__ hT, const float* __restrict__ a1,
                            const float* __restrict__ a2,
                            float* __restrict__ e1, float* __restrict__ e2)
{
    __shared__ float s1[4][64], s2[4][64];
    int bI = blockIdx.x;
    int b = bI >> 4, jb = bI & 15;
    int jloc = threadIdx.x & 63, part = threadIdx.x >> 6;
    int j = jb * 64 + jloc;
    const __half* base = hT + (long)b * CHID * CN + j;
    float t1 = 0.f, t2 = 0.f;
    #pragma unroll 8
    for (int c = part * 64; c < part * 64 + 64; c++) {
        float v = __half2float(base[(long)c * CN]);
        t1 = fmaf(v, a1[c], t1);
        t2 = fmaf(v, a2[c], t2);
    }
    s1[part][jloc] = t1; s2[part][jloc] = t2;
    __syncthreads();
    if (part == 0) {
        e1[b * CN + j] = s1[0][jloc] + s1[1][jloc] + s1[2][jloc] + s1[3][jloc];
        e2[b * CN + j] = s2[0][jloc] + s2[1][jloc] + s2[2][jloc] + s2[3][jloc];
    }
}

// ---------------- rel_sc ----------------
__global__ void relsc_kernel(const float* __restrict__ rel, const float* __restrict__ a3,
                             float* __restrict__ out)
{
    __shared__ float s[256];
    int r = blockIdx.x, t = threadIdx.x;
    s[t] = rel[r * CHID + t] * a3[t];
    __syncthreads();
    for (int o = 128; o > 0; o >>= 1) {
        if (t < o) s[t] += s[t + o];
        __syncthreads();
    }
    if (t == 0) out[r] = s[0];
}

// ---------------- LayerNorm ----------------
__global__ void ln_kernel(const float* __restrict__ T, const float* __restrict__ Hold,
                          const float* __restrict__ g, const float* __restrict__ bb,
                          float* __restrict__ out)
{
    int warp = threadIdx.x >> 5, lane = threadIdx.x & 31;
    int row = blockIdx.x * 8 + warp;
    long base = (long)row * CHID;
    float v[8];
    float s = 0.f;
    #pragma unroll
    for (int j = 0; j < 8; j++) {
        int c = j * 32 + lane;
        v[j] = T[base + c] + Hold[base + c];
        s += v[j];
    }
    #pragma unroll
    for (int off = 16; off > 0; off >>= 1) s += __shfl_xor_sync(0xffffffffu, s, off);
    float mu = s * (1.f / CHID);
    float q = 0.f;
    #pragma unroll
    for (int j = 0; j < 8; j++) { v[j] -= mu; q = fmaf(v[j], v[j], q); }
    #pragma unroll
    for (int off = 16; off > 0; off >>= 1) q += __shfl_xor_sync(0xffffffffu, q, off);
    float rstd = rsqrtf(q * (1.f / CHID) + 1e-5f);
    #pragma unroll
    for (int j = 0; j < 8; j++) {
        int c = j * 32 + lane;
        out[base + c] = v[j] * rstd * g[c] + bb[c];
    }
}

// ---------------- Pagg partials ----------------
__global__ void pagg_part_kernel(const float* __restrict__ sadj, const float* __restrict__ Hcur,
                                 float* __restrict__ PaggP)
{
    int bm = blockIdx.x, part = blockIdx.y;
    int b = bm >> 3;
    int c = threadIdx.x;
    const float* sa = sadj + (long)bm * CN + part * 256;
    const float* Hb = Hcur + ((long)b * CN + part * 256) * CHID + c;
    float a0 = 0.f, a1 = 0.f, a2 = 0.f, a3 = 0.f;
    #pragma unroll 4
    for (int n = 0; n < 256; n += 4) {
        a0 = fmaf(sa[n],     Hb[(long)(n)     * CHID], a0);
        a1 = fmaf(sa[n + 1], Hb[(long)(n + 1) * CHID], a1);
        a2 = fmaf(sa[n + 2], Hb[(long)(n + 2) * CHID], a2);
        a3 = fmaf(sa[n + 3], Hb[(long)(n + 3) * CHID], a3);
    }
    PaggP[((long)part * 64 + bm) * CHID + c] = (a0 + a1) + (a2 + a3);
}

// ---------------- GRU ----------------
__global__ void gru_kernel(const float* __restrict__ PaggP, float* __restrict__ P,
                           float* __restrict__ Pnew,
                           const float* __restrict__ wz, const float* __restrict__ uz,
                           const float* __restrict__ wr, const float* __restrict__ ur,
                           const float* __restrict__ w,  const float* __restrict__ u)
{
    __shared__ float sp[CHID], sq[CHID];
    __shared__ float red[6][4][64];
    int bm = blockIdx.x, dq = blockIdx.y;
    int dloc = threadIdx.x & 63, part = threadIdx.x >> 6;
    int d = dq * 64 + dloc;
    sp[threadIdx.x] = P[(long)bm * CHID + threadIdx.x];
    sq[threadIdx.x] = PaggP[(long)bm * CHID + threadIdx.x]
                    + PaggP[((long)64 + bm) * CHID + threadIdx.x]
                    + PaggP[((long)128 + bm) * CHID + threadIdx.x]
                    + PaggP[((long)192 + bm) * CHID + threadIdx.x];
    __syncthreads();
    float az = 0, bz = 0, ar = 0, br = 0, aw = 0, bw = 0;
    int k0 = part * 64;
    #pragma unroll 4
    for (int k = k0; k < k0 + 64; k++) {
        float pk = sp[k], qk = sq[k];
        az = fmaf(pk, wz[k * CHID + d], az); bz = fmaf(qk, uz[k * CHID + d], bz);
        ar = fmaf(pk, wr[k * CHID + d], ar); br = fmaf(qk, ur[k * CHID + d], br);
        aw = fmaf(pk, w [k * CHID + d], aw); bw = fmaf(qk, u [k * CHID + d], bw);
    }
    red[0][part][dloc] = az; red[1][part][dloc] = bz;
    red[2][part][dloc] = ar; red[3][part][dloc] = br;
    red[4][part][dloc] = aw; red[5][part][dloc] = bw;
    __syncthreads();
    if (part == 0) {
        float tz = red[0][0][dloc] + red[0][1][dloc] + red[0][2][dloc] + red[0][3][dloc]
                 + red[1][0][dloc] + red[1][1][dloc] + red[1][2][dloc] + red[1][3][dloc];
        float tr_ = red[2][0][dloc] + red[2][1][dloc] + red[2][2][dloc] + red[2][3][dloc]
                  + red[3][0][dloc] + red[3][1][dloc] + red[3][2][dloc] + red[3][3][dloc];
        float tw = red[4][0][dloc] + red[4][1][dloc] + red[4][2][dloc] + red[4][3][dloc];
        float tu = red[5][0][dloc] + red[5][1][dloc] + red[5][2][dloc] + red[5][3][dloc];
        float z  = 1.f / (1.f + expf(-tz));
        float rr = 1.f / (1.f + expf(-tr_));
        float hh = tanhf(tw + rr * tu);
        Pnew[(long)bm * CHID + d] = (1.f - z) * sp[d] + z * hh;
    }
}

// ---------------- p_sim ----------------
__global__ void psim_kernel(const float* __restrict__ P, float* __restrict__ outp, int tail)
{
    __shared__ float red[64];
    int t = threadIdx.x;
    int b = t >> 3, m = t & 7;
    const float* Pb = P + (long)b * CM * CHID;
    float s = 0.f;
    for (int k2 = 0; k2 < CM; k2++) {
        if (k2 == m) continue;
        float d = 0.f;
        for (int dd = 0; dd < CHID; dd++)
            d = fmaf(Pb[m * CHID + dd], Pb[k2 * CHID + dd], d);
        s += d;
    }
    red[t] = s; __syncthreads();
    if ((t & 7) < 4) red[t] += red[t + 4]; __syncthreads();
    if ((t & 7) < 2) red[t] += red[t + 2]; __syncthreads();
    if ((t & 7) < 1) red[t] += red[t + 1]; __syncthreads();
    if (tail >= CB) {
        if (t < CB) outp[t] = red[t * 8] / (float)(CM * CM);
    } else {
        if (t == 0) {
            float tot = 0.f;
            for (int b2 = 0; b2 < CB; b2++) tot += red[b2 * 8];
            outp[0] = tot / (float)(CB * CM * CM);
        }
    }
}

// ---------------- host orchestration ----------------
extern "C" void kernel_launch(void* const* d_in, const int* in_sizes, int n_in,
                              void* d_out, int out_size)
{
    const float* x     = (const float*)d_in[0];
    const int*   adj   = (const int*)  d_in[1];
    const int*   smask = (const int*)  d_in[2];
    const float* sf    = (const float*)d_in[3];
    const float* sadj  = (const float*)d_in[4];
    const float* fc1w  = (const float*)d_in[6];
    const float* fc1b  = (const float*)d_in[7];
    const float* fc2w  = (const float*)d_in[8];
    const float* fc2b  = (const float*)d_in[9];
    const float* gatW  = (const float*)d_in[10];
    const float* gata  = (const float*)d_in[11];
    const float* rel   = (const float*)d_in[12];
    const float* gwz   = (const float*)d_in[13];
    const float* guz   = (const float*)d_in[14];
    const float* gwr   = (const float*)d_in[15];
    const float* gur   = (const float*)d_in[16];
    const float* gw    = (const float*)d_in[17];
    const float* gu    = (const float*)d_in[18];
    const float* wv    = (const float*)d_in[19];
    const float* bv    = (const float*)d_in[20];
    const float* wk    = (const float*)d_in[21];
    const float* bk    = (const float*)d_in[22];
    const float* wq    = (const float*)d_in[23];
    const float* bq    = (const float*)d_in[24];
    const float* wo    = (const float*)d_in[25];
    const float* bo    = (const float*)d_in[26];
    const float* lng   = (const float*)d_in[27];
    const float* lnb   = (const float*)d_in[28];
    const float* outw  = (const float*)d_in[29];
    const float* outb  = (const float*)d_in[30];
    float* out = (float*)d_out;

    float *H, *Hn, *P, *PW, *PaggP, *Agg, *ctx, *Tb, *e1, *e2, *rsc;
    __half *Qh, *Kh, *VT, *hT, *WT8, *WTfc1;
    uint8_t* codes;
    cudaGetSymbolAddress((void**)&H,    g_H);
    cudaGetSymbolAddress((void**)&Hn,   g_Hn);
    cudaGetSymbolAddress((void**)&P,    g_P);
    cudaGetSymbolAddress((void**)&PW,   g_PW);
    cudaGetSymbolAddress((void**)&PaggP, g_PaggP);
    cudaGetSymbolAddress((void**)&Agg,  g_Agg);
    cudaGetSymbolAddress((void**)&ctx,  g_ctx);
    cudaGetSymbolAddress((void**)&Tb,   g_T);
    cudaGetSymbolAddress((void**)&Qh,   g_Qh);
    cudaGetSymbolAddress((void**)&Kh,   g_Kh);
    cudaGetSymbolAddress((void**)&VT,   g_VT);
    cudaGetSymbolAddress((void**)&hT,   g_hT);
    cudaGetSymbolAddress((void**)&WT8,  g_WT8);
    cudaGetSymbolAddress((void**)&WTfc1, g_WTfc1);
    cudaGetSymbolAddress((void**)&codes, g_codes);
    cudaGetSymbolAddress((void**)&e1,   g_e1);
    cudaGetSymbolAddress((void**)&e2,   g_e2);
    cudaGetSymbolAddress((void**)&rsc,  g_rsc);

    cudaFuncSetAttribute(tgemm<0>, cudaFuncAttributeMaxDynamicSharedMemorySize, SM_TG);
    cudaFuncSetAttribute(tgemm<1>, cudaFuncAttributeMaxDynamicSharedMemorySize, SM_TG);
    cudaFuncSetAttribute(tgemm<4>, cudaFuncAttributeMaxDynamicSharedMemorySize, SM_TG);
    cudaFuncSetAttribute(tgemm_pair, cudaFuncAttributeMaxDynamicSharedMemorySize, SM_TG);
    cudaFuncSetAttribute(flash_kernel, cudaFuncAttributeMaxDynamicSharedMemorySize, SM_FLASH);
    cudaFuncSetAttribute(gatt_kernel, cudaFuncAttributeMaxDynamicSharedMemorySize, SM_GATT);

    dim3 blk(256);
    const int BN = CB * CN;
    const long HH = (long)CHID * CHID;
    const long WQ = (long)CHID * CHID;

    // ---- pack weights to fp16 [N][K] (idx = l*4 + {gatW, wv, wq, wo}) ----
    {
        W8 w;
        for (int l = 0; l < 2; l++) {
            w.src[l * 4 + 0] = gatW + l * HH;
            w.src[l * 4 + 1] = wv + l * HH;
            w.src[l * 4 + 2] = wq + l * HH;
            w.src[l * 4 + 3] = wo + l * HH;
        }
        wpack8_kernel<<<dim3(8, 8, 8), blk>>>(w, WT8);
        wpack_fc1_kernel<<<dim3(32, 8), blk>>>(fc1w, WTfc1);
    }

    pack_codes<<<(int)((long)CB * CN * CN / 4 / 256), blk>>>(adj, smask, codes);
    // H = relu(x @ fc1_w + b)  (fp16 B)
    tgemm<1><<<dim3(2, 64), blk, SM_TG>>>(x, WTfc1, fc1b, H, BN, CHID, CDIN);
    sgemm<1><<<dim3(4, 1, 1), blk>>>(sf, fc2w, fc2b, P, CB * CM, CHID, CDIN);

    for (int l = 0; l < CL; l++) {
        float* cur = l ? Hn : H;
        float* nxt = l ? H : Hn;

        pwk_kernel<<<dim3(CB * CM, 4), blk>>>(P, wk + l * HH, PW);
        kcomb_kernel<<<BN * CHID / 256, blk>>>(sadj, PW, bk + l * CHID, Kh);

        // paired: hT = (cur @ gatW)^T fp16 ; VT = (cur @ wv + bv) head-T fp16
        {
            G2 a;
            a.A[0] = cur;                  a.A[1] = cur;
            a.B[0] = WT8 + (l * 4 + 0) * WQ; a.B[1] = WT8 + (l * 4 + 1) * WQ;
            a.bias[0] = nullptr;           a.bias[1] = bv + l * CHID;
            a.C[0] = (float*)hT;           a.C[1] = (float*)VT;
            a.act[0] = 5;                  a.act[1] = 6;
            tgemm_pair<<<dim3(2, 64, 2), blk, SM_TG>>>(a, BN, CHID, CHID);
        }
        dots_kernel<<<CB * 16, blk>>>(hT, gata + l * 3 * CHID, gata + l * 3 * CHID + CHID, e1, e2);
        relsc_kernel<<<2, blk>>>(rel + l * 2 * CHID, gata + l * 3 * CHID + 2 * CHID, rsc);
        gatt_kernel<<<dim3(4, 8, CB), blk, SM_GATT>>>(e1, e2, rsc, codes, hT, Agg);
        // Qh = Agg @ wq + bq (fp16 row-major out)
        tgemm<4><<<dim3(2, 64), blk, SM_TG>>>(Agg, WT8 + (l * 4 + 2) * WQ, bq + l * CHID,
                                              (float*)Qh, BN, CHID, CHID);
        flash_kernel<<<dim3(8, 32), blk, SM_FLASH>>>(Qh, Kh, VT, ctx);
        tgemm<0><<<dim3(2, 64), blk, SM_TG>>>(ctx, WT8 + (l * 4 + 3) * WQ, bo + l * CHID,
                                              Tb, BN, CHID, CHID);
        ln_kernel<<<BN / 8, blk>>>(Tb, cur, lng + l * CHID, lnb + l * CHID, nxt);

        pagg_part_kernel<<<dim3(CB * CM, 4), blk>>>(sadj, cur, PaggP);
        gru_kernel<<<dim3(CB * CM, 4), blk>>>(PaggP, P, P,
                                              gwz + l * HH, guz + l * HH,
                                              gwr + l * HH, gur + l * HH,
                                              gw + l * HH,  gu + l * HH);
    }

    logits_kernel<<<BN / 8, blk>>>(H, outw, outb, out);
    psim_kernel<<<1, 64>>>(P, out + (long)BN * CNC, out_size - BN * CNC);
}